// round 4
// baseline (speedup 1.0000x reference)
#include <cuda_runtime.h>
#include <math.h>

// ---------------- problem constants ----------------
// B=2 S=1024 H=2048 NH=16 NOPE=128 ROPE=64 VD=128 QKD=192 QLR=1536 KVLR=512
// TOK = B*S = 2048
#define TOK   2048
#define HID   2048
#define QLR   1536
#define KVLR  512
#define ROPE  64
#define NH    16
#define QKD   192
#define NOPE  128
#define VD    128
#define SQ    1024
#define EFFD  576   // KVLR + ROPE
#define QSTR  9216  // NH*EFFD
#define CTXLD 8192  // NH*KVLR

// ---------------- scratch (device globals, no allocation) ----------------
__device__ float g_qa_raw[TOK * QLR];            // 12.6 MB
__device__ float g_kva_raw[TOK * EFFD];          //  4.7 MB
__device__ float g_qa_ln[TOK * QLR];             // 12.6 MB
__device__ float g_kk[TOK * EFFD];               //  4.7 MB  [kv_c | k_pe]
__device__ float g_q[TOK * NH * QKD];            // 25.2 MB
__device__ float g_qq[TOK * QSTR];               // 75.5 MB  [q_lat | roped q_pe]
__device__ float g_sc[33554432];                 // 128 MB   (2*16, 1024, 1024)
__device__ float g_ctx[TOK * CTXLD];             // 67.1 MB
__device__ float g_attn[TOK * HID];              // 16.8 MB

// ---------------- generic strided SGEMM ----------------
// C[m,n] = alpha * sum_k A[m,k] * B(k,n)
// A row-major with lda. B element (k,n) at B[k*sBk + n*sBn]  (sBk==1 -> B^T
// weight layout, contiguous along k; sBn==1 -> normal row-major B).
// z = blockIdx.z; zb = z/zdiv, zh = z%zdiv; per-z offsets via (sAb,sAh) etc.
// mode 0: plain; mode 1: causal skip (return if n0 > m0+BM-1);
// mode 2: causal K-limit (Kend = min(K, m0+BM)).
#define BM 128
#define BN 64
#define BK 16

__global__ __launch_bounds__(256) void gemm_k(
    const float* __restrict__ A, int lda, long sAb, long sAh,
    const float* __restrict__ B, int sBk, int sBn, long sBb, long sBh,
    float* __restrict__ C, int ldc, long sCb, long sCh,
    int K, float alpha, int mode, int zdiv)
{
    int z  = blockIdx.z;
    int zb = z / zdiv;
    int zh = z - zb * zdiv;
    A += (long)zb * sAb + (long)zh * sAh;
    B += (long)zb * sBb + (long)zh * sBh;
    C += (long)zb * sCb + (long)zh * sCh;

    int m0 = blockIdx.y * BM;
    int n0 = blockIdx.x * BN;
    if (mode == 1 && n0 > m0 + (BM - 1)) return;
    int Kend = (mode == 2) ? min(K, m0 + BM) : K;

    __shared__ float As[BK][BM];
    __shared__ float Bs[BK][BN];

    int tid = threadIdx.x;
    int tx  = tid & 15;          // n: 4 cols each
    int ty  = tid >> 4;          // m: 8 rows each
    int lr  = tid >> 2;          // 0..63
    int lk4 = (tid & 3) << 2;    // 0,4,8,12
    int lk  = tid >> 4;          // 0..15
    int ln4 = (tid & 15) << 2;   // 0..60

    float acc[8][4];
#pragma unroll
    for (int i = 0; i < 8; i++)
#pragma unroll
        for (int j = 0; j < 4; j++) acc[i][j] = 0.f;

    const bool btrans = (sBk == 1);

    for (int k0 = 0; k0 < Kend; k0 += BK) {
        float4 a0 = *reinterpret_cast<const float4*>(&A[(long)(m0 + lr) * lda + k0 + lk4]);
        float4 a1 = *reinterpret_cast<const float4*>(&A[(long)(m0 + lr + 64) * lda + k0 + lk4]);
        As[lk4 + 0][lr] = a0.x; As[lk4 + 1][lr] = a0.y;
        As[lk4 + 2][lr] = a0.z; As[lk4 + 3][lr] = a0.w;
        As[lk4 + 0][lr + 64] = a1.x; As[lk4 + 1][lr + 64] = a1.y;
        As[lk4 + 2][lr + 64] = a1.z; As[lk4 + 3][lr + 64] = a1.w;

        if (btrans) {
            float4 bv = *reinterpret_cast<const float4*>(&B[(long)(n0 + lr) * sBn + k0 + lk4]);
            Bs[lk4 + 0][lr] = bv.x; Bs[lk4 + 1][lr] = bv.y;
            Bs[lk4 + 2][lr] = bv.z; Bs[lk4 + 3][lr] = bv.w;
        } else {
            float4 bv = *reinterpret_cast<const float4*>(&B[(long)(k0 + lk) * sBk + n0 + ln4]);
            *reinterpret_cast<float4*>(&Bs[lk][ln4]) = bv;
        }
        __syncthreads();

#pragma unroll
        for (int kk = 0; kk < BK; kk++) {
            float4 bf  = *reinterpret_cast<float4*>(&Bs[kk][tx << 2]);
            float4 af0 = *reinterpret_cast<float4*>(&As[kk][ty << 3]);
            float4 af1 = *reinterpret_cast<float4*>(&As[kk][(ty << 3) + 4]);
            float am[8] = {af0.x, af0.y, af0.z, af0.w, af1.x, af1.y, af1.z, af1.w};
            float bn_[4] = {bf.x, bf.y, bf.z, bf.w};
#pragma unroll
            for (int i = 0; i < 8; i++)
#pragma unroll
                for (int j = 0; j < 4; j++)
                    acc[i][j] += am[i] * bn_[j];
        }
        __syncthreads();
    }

#pragma unroll
    for (int i = 0; i < 8; i++) {
        long r = m0 + (ty << 3) + i;
        float4 o = make_float4(acc[i][0] * alpha, acc[i][1] * alpha,
                               acc[i][2] * alpha, acc[i][3] * alpha);
        *reinterpret_cast<float4*>(&C[r * ldc + n0 + (tx << 2)]) = o;
    }
}

// ---------------- dual layernorm + k_pe rope ----------------
__global__ __launch_bounds__(256) void ln_rope_kernel(
    const float* __restrict__ qa_raw, const float* __restrict__ kva_raw,
    const float* __restrict__ qw, const float* __restrict__ kw,
    const float* __restrict__ cosb, const float* __restrict__ sinb,
    float* __restrict__ qa_ln, float* __restrict__ kk)
{
    int t = blockIdx.x;
    int tid = threadIdx.x;
    __shared__ float r1[256], r2[256];

    // q_a layernorm over QLR=1536
    const float* row = qa_raw + (long)t * QLR;
    float s = 0.f, s2 = 0.f;
    for (int i = tid; i < QLR; i += 256) { float v = row[i]; s += v; s2 += v * v; }
    r1[tid] = s; r2[tid] = s2; __syncthreads();
    for (int o = 128; o > 0; o >>= 1) {
        if (tid < o) { r1[tid] += r1[tid + o]; r2[tid] += r2[tid + o]; }
        __syncthreads();
    }
    float mean = r1[0] * (1.f / QLR);
    float var  = r2[0] * (1.f / QLR) - mean * mean;
    float rs   = rsqrtf(var + 1e-5f);
    for (int i = tid; i < QLR; i += 256)
        qa_ln[(long)t * QLR + i] = (row[i] - mean) * rs * qw[i];
    __syncthreads();

    // kv_a layernorm over KVLR=512
    const float* krow = kva_raw + (long)t * EFFD;
    s = 0.f; s2 = 0.f;
    for (int i = tid; i < KVLR; i += 256) { float v = krow[i]; s += v; s2 += v * v; }
    r1[tid] = s; r2[tid] = s2; __syncthreads();
    for (int o = 128; o > 0; o >>= 1) {
        if (tid < o) { r1[tid] += r1[tid + o]; r2[tid] += r2[tid + o]; }
        __syncthreads();
    }
    mean = r1[0] * (1.f / KVLR);
    var  = r2[0] * (1.f / KVLR) - mean * mean;
    rs   = rsqrtf(var + 1e-5f);
    for (int i = tid; i < KVLR; i += 256)
        kk[(long)t * EFFD + i] = (krow[i] - mean) * rs * kw[i];

    // k_pe rope (64)
    if (tid < ROPE) {
        int i = tid;
        float x   = krow[KVLR + i];
        float rot = (i < 32) ? -krow[KVLR + i + 32] : krow[KVLR + i - 32];
        kk[(long)t * EFFD + KVLR + i] =
            x * cosb[(long)t * ROPE + i] + rot * sinb[(long)t * ROPE + i];
    }
}

// ---------------- q_pe rope -> qq[...,512:576] ----------------
__global__ __launch_bounds__(256) void qrope_kernel(
    const float* __restrict__ q, const float* __restrict__ cosb,
    const float* __restrict__ sinb, float* __restrict__ qq)
{
    int t = blockIdx.x;
    int tid = threadIdx.x;
    for (int idx = tid; idx < NH * ROPE; idx += 256) {
        int h = idx >> 6, i = idx & 63;
        const float* qp = q + (long)t * (NH * QKD) + h * QKD + NOPE;
        float x   = qp[i];
        float rot = (i < 32) ? -qp[i + 32] : qp[i - 32];
        qq[(long)t * QSTR + h * EFFD + KVLR + i] =
            x * cosb[(long)t * ROPE + i] + rot * sinb[(long)t * ROPE + i];
    }
}

// ---------------- causal softmax (rows register-resident) ----------------
__global__ __launch_bounds__(128) void softmax_kernel(float* __restrict__ sc)
{
    int q  = blockIdx.x;
    int bh = blockIdx.y;
    float* row = sc + ((long)bh * SQ + q) * SQ;
    int n = q + 1;
    int tid = threadIdx.x;

    float v[8];
    int cnt = 0;
    float mx = -3.4e38f;
    for (int k = tid; k < n; k += 128) { float x = row[k]; v[cnt++] = x; mx = fmaxf(mx, x); }

    __shared__ float red[128];
    red[tid] = mx; __syncthreads();
    for (int o = 64; o > 0; o >>= 1) {
        if (tid < o) red[tid] = fmaxf(red[tid], red[tid + o]);
        __syncthreads();
    }
    mx = red[0]; __syncthreads();

    float sum = 0.f;
    for (int c = 0; c < cnt; c++) { float e = __expf(v[c] - mx); v[c] = e; sum += e; }
    red[tid] = sum; __syncthreads();
    for (int o = 64; o > 0; o >>= 1) {
        if (tid < o) red[tid] += red[tid + o];
        __syncthreads();
    }
    float inv = 1.f / red[0];

    cnt = 0;
    for (int k = tid; k < n; k += 128) row[k] = v[cnt++] * inv;
    // zero-fill up to the causal K-limit tile boundary so the ctx GEMM can
    // run dense up to m0+BM without masking
    int zend = ((q >> 7) + 1) << 7;
    for (int k = n + tid; k < zend; k += 128) row[k] = 0.f;
}

// ---------------- launch ----------------
extern "C" void kernel_launch(void* const* d_in, const int* in_sizes, int n_in,
                              void* d_out, int out_size)
{
    const float* hidden = (const float*)d_in[0];
    const float* cosb   = (const float*)d_in[1];
    const float* sinb   = (const float*)d_in[2];
    const float* w_qa   = (const float*)d_in[3];
    const float* qln    = (const float*)d_in[4];
    const float* w_qb   = (const float*)d_in[5];
    const float* w_kva  = (const float*)d_in[6];
    const float* kln    = (const float*)d_in[7];
    const float* w_uk   = (const float*)d_in[8];
    const float* w_uv   = (const float*)d_in[9];
    const float* w_o    = (const float*)d_in[10];
    float* out = (float*)d_out;

    float *qa_raw, *kva_raw, *qa_ln, *kkb, *qbuf, *qqb, *sc, *ctx, *attn;
    cudaGetSymbolAddress((void**)&qa_raw,  g_qa_raw);
    cudaGetSymbolAddress((void**)&kva_raw, g_kva_raw);
    cudaGetSymbolAddress((void**)&qa_ln,   g_qa_ln);
    cudaGetSymbolAddress((void**)&kkb,     g_kk);
    cudaGetSymbolAddress((void**)&qbuf,    g_q);
    cudaGetSymbolAddress((void**)&qqb,     g_qq);
    cudaGetSymbolAddress((void**)&sc,      g_sc);
    cudaGetSymbolAddress((void**)&ctx,     g_ctx);
    cudaGetSymbolAddress((void**)&attn,    g_attn);

    dim3 blk(256);
    const float scale = 1.0f / sqrtf((float)QKD);

    // 1) qa_raw = hidden @ w_qa^T           (2048 x 1536 x 2048)
    gemm_k<<<dim3(QLR / BN, TOK / BM, 1), blk>>>(
        hidden, HID, 0, 0,  w_qa, 1, HID, 0, 0,
        qa_raw, QLR, 0, 0,  HID, 1.f, 0, 1);

    // 2) kva_raw = hidden @ w_kva^T         (2048 x 576 x 2048)
    gemm_k<<<dim3(EFFD / BN, TOK / BM, 1), blk>>>(
        hidden, HID, 0, 0,  w_kva, 1, HID, 0, 0,
        kva_raw, EFFD, 0, 0,  HID, 1.f, 0, 1);

    // 3) layernorms + k_pe rope
    ln_rope_kernel<<<TOK, 256>>>(qa_raw, kva_raw, qln, kln, cosb, sinb, qa_ln, kkb);

    // 4) q = qa_ln @ w_qb^T                 (2048 x 3072 x 1536)
    gemm_k<<<dim3(NH * QKD / BN, TOK / BM, 1), blk>>>(
        qa_ln, QLR, 0, 0,  w_qb, 1, QLR, 0, 0,
        qbuf, NH * QKD, 0, 0,  QLR, 1.f, 0, 1);

    // 5) q_pe rope -> qq[...,512:576]
    qrope_kernel<<<TOK, 256>>>(qbuf, cosb, sinb, qqb);

    // 6) q_lat[h] = q_nope[h] @ W_UK_T[h]   (16 x (2048 x 512 x 128))
    gemm_k<<<dim3(KVLR / BN, TOK / BM, NH), blk>>>(
        qbuf, NH * QKD, 0, QKD,  w_uk, KVLR, 1, 0, (long)NOPE * KVLR,
        qqb, QSTR, 0, EFFD,  NOPE, 1.f, 0, NH);

    // 7) scores = qq @ kk^T * scale, causal tile-skip   (32 x (1024x1024x576))
    gemm_k<<<dim3(SQ / BN, SQ / BM, 2 * NH), blk>>>(
        qqb, QSTR, (long)SQ * QSTR, EFFD,
        kkb, 1, EFFD, (long)SQ * EFFD, 0,
        sc, SQ, (long)NH * SQ * SQ, (long)SQ * SQ,
        EFFD, scale, 1, NH);

    // 8) causal softmax (in place)
    softmax_kernel<<<dim3(SQ, 2 * NH), 128>>>(sc);

    // 9) ctx = p @ kv_c, causal K-limit     (32 x (1024x512x1024))
    gemm_k<<<dim3(KVLR / BN, SQ / BM, 2 * NH), blk>>>(
        sc, SQ, (long)NH * SQ * SQ, (long)SQ * SQ,
        kkb, EFFD, 1, (long)SQ * EFFD, 0,
        ctx, CTXLD, (long)SQ * CTXLD, KVLR,
        SQ, 1.f, 2, NH);

    // 10) attn[h] = ctx[h] @ W_UV[h]        (16 x (2048 x 128 x 512))
    gemm_k<<<dim3(VD / BN, TOK / BM, NH), blk>>>(
        ctx, CTXLD, 0, KVLR,  w_uv, VD, 1, 0, (long)KVLR * VD,
        attn, HID, 0, VD,  KVLR, 1.f, 0, NH);

    // 11) out = attn @ w_o^T                (2048 x 2048 x 2048)
    gemm_k<<<dim3(HID / BN, TOK / BM, 1), blk>>>(
        attn, HID, 0, 0,  w_o, 1, HID, 0, 0,
        out, HID, 0, 0,  HID, 1.f, 0, 1);
}

// round 5
// speedup vs baseline: 1.0542x; 1.0542x over previous
#include <cuda_runtime.h>
#include <math.h>

// ---------------- problem constants ----------------
// B=2 S=1024 H=2048 NH=16 NOPE=128 ROPE=64 VD=128 QKD=192 QLR=1536 KVLR=512
// TOK = B*S = 2048
#define TOK   2048
#define HID   2048
#define QLR   1536
#define KVLR  512
#define ROPE  64
#define NH    16
#define QKD   192
#define NOPE  128
#define VD    128
#define SQ    1024
#define EFFD  576   // KVLR + ROPE
#define QSTR  9216  // NH*EFFD
#define CTXLD 8192  // NH*KVLR

// ---------------- scratch (device globals, no allocation) ----------------
__device__ float g_qa_raw[TOK * QLR];            // 12.6 MB
__device__ float g_kva_raw[TOK * EFFD];          //  4.7 MB
__device__ float g_qa_ln[TOK * QLR];             // 12.6 MB
__device__ float g_kk[TOK * EFFD];               //  4.7 MB  [kv_c | k_pe]
__device__ float g_q[TOK * NH * QKD];            // 25.2 MB
__device__ float g_qq[TOK * QSTR];               // 75.5 MB  [q_lat | roped q_pe]
__device__ float g_sc[33554432];                 // 128 MB   (2*16, 1024, 1024)
__device__ float g_ctx[TOK * CTXLD];             // 67.1 MB
__device__ float g_attn[TOK * HID];              // 16.8 MB

// ---------------- generic strided SGEMM ----------------
// C[m,n] = alpha * sum_k A[m,k] * B(k,n)
// A row-major with lda. B element (k,n) at B[k*sBk + n*sBn]  (sBk==1 -> B^T
// weight layout, contiguous along k; sBn==1 -> normal row-major B).
// z = blockIdx.z; zb = z/zdiv, zh = z%zdiv; per-z offsets via (sAb,sAh) etc.
// mode 0: plain; mode 1: causal skip (return if n0 > m0+BM-1);
// mode 2: causal K-limit (Kend = min(K, m0+BM)).
#define BM 128
#define BN 64
#define BK 16

__global__ __launch_bounds__(256) void gemm_k(
    const float* __restrict__ A, int lda, long sAb, long sAh,
    const float* __restrict__ B, int sBk, int sBn, long sBb, long sBh,
    float* __restrict__ C, int ldc, long sCb, long sCh,
    int K, float alpha, int mode, int zdiv)
{
    int z  = blockIdx.z;
    int zb = z / zdiv;
    int zh = z - zb * zdiv;
    A += (long)zb * sAb + (long)zh * sAh;
    B += (long)zb * sBb + (long)zh * sBh;
    C += (long)zb * sCb + (long)zh * sCh;

    int m0 = blockIdx.y * BM;
    int n0 = blockIdx.x * BN;
    if (mode == 1 && n0 > m0 + (BM - 1)) return;
    int Kend = (mode == 2) ? min(K, m0 + BM) : K;

    __shared__ float As[BK][BM];
    __shared__ float Bs[BK][BN];

    int tid = threadIdx.x;
    int tx  = tid & 15;          // n: 4 cols each
    int ty  = tid >> 4;          // m: 8 rows each
    int lr  = tid >> 2;          // 0..63
    int lk4 = (tid & 3) << 2;    // 0,4,8,12
    int lk  = tid >> 4;          // 0..15
    int ln4 = (tid & 15) << 2;   // 0..60

    float acc[8][4];
#pragma unroll
    for (int i = 0; i < 8; i++)
#pragma unroll
        for (int j = 0; j < 4; j++) acc[i][j] = 0.f;

    const bool btrans = (sBk == 1);

    for (int k0 = 0; k0 < Kend; k0 += BK) {
        float4 a0 = *reinterpret_cast<const float4*>(&A[(long)(m0 + lr) * lda + k0 + lk4]);
        float4 a1 = *reinterpret_cast<const float4*>(&A[(long)(m0 + lr + 64) * lda + k0 + lk4]);
        As[lk4 + 0][lr] = a0.x; As[lk4 + 1][lr] = a0.y;
        As[lk4 + 2][lr] = a0.z; As[lk4 + 3][lr] = a0.w;
        As[lk4 + 0][lr + 64] = a1.x; As[lk4 + 1][lr + 64] = a1.y;
        As[lk4 + 2][lr + 64] = a1.z; As[lk4 + 3][lr + 64] = a1.w;

        if (btrans) {
            float4 bv = *reinterpret_cast<const float4*>(&B[(long)(n0 + lr) * sBn + k0 + lk4]);
            Bs[lk4 + 0][lr] = bv.x; Bs[lk4 + 1][lr] = bv.y;
            Bs[lk4 + 2][lr] = bv.z; Bs[lk4 + 3][lr] = bv.w;
        } else {
            float4 bv = *reinterpret_cast<const float4*>(&B[(long)(k0 + lk) * sBk + n0 + ln4]);
            *reinterpret_cast<float4*>(&Bs[lk][ln4]) = bv;
        }
        __syncthreads();

#pragma unroll
        for (int kk = 0; kk < BK; kk++) {
            float4 bf  = *reinterpret_cast<float4*>(&Bs[kk][tx << 2]);
            float4 af0 = *reinterpret_cast<float4*>(&As[kk][ty << 3]);
            float4 af1 = *reinterpret_cast<float4*>(&As[kk][(ty << 3) + 4]);
            float am[8] = {af0.x, af0.y, af0.z, af0.w, af1.x, af1.y, af1.z, af1.w};
            float bn_[4] = {bf.x, bf.y, bf.z, bf.w};
#pragma unroll
            for (int i = 0; i < 8; i++)
#pragma unroll
                for (int j = 0; j < 4; j++)
                    acc[i][j] += am[i] * bn_[j];
        }
        __syncthreads();
    }

#pragma unroll
    for (int i = 0; i < 8; i++) {
        long r = m0 + (ty << 3) + i;
        float4 o = make_float4(acc[i][0] * alpha, acc[i][1] * alpha,
                               acc[i][2] * alpha, acc[i][3] * alpha);
        *reinterpret_cast<float4*>(&C[r * ldc + n0 + (tx << 2)]) = o;
    }
}

// ---------------- dual layernorm + k_pe rope ----------------
__global__ __launch_bounds__(256) void ln_rope_kernel(
    const float* __restrict__ qa_raw, const float* __restrict__ kva_raw,
    const float* __restrict__ qw, const float* __restrict__ kw,
    const float* __restrict__ cosb, const float* __restrict__ sinb,
    float* __restrict__ qa_ln, float* __restrict__ kk)
{
    int t = blockIdx.x;
    int tid = threadIdx.x;
    __shared__ float r1[256], r2[256];

    // q_a layernorm over QLR=1536
    const float* row = qa_raw + (long)t * QLR;
    float s = 0.f, s2 = 0.f;
    for (int i = tid; i < QLR; i += 256) { float v = row[i]; s += v; s2 += v * v; }
    r1[tid] = s; r2[tid] = s2; __syncthreads();
    for (int o = 128; o > 0; o >>= 1) {
        if (tid < o) { r1[tid] += r1[tid + o]; r2[tid] += r2[tid + o]; }
        __syncthreads();
    }
    float mean = r1[0] * (1.f / QLR);
    float var  = r2[0] * (1.f / QLR) - mean * mean;
    float rs   = rsqrtf(var + 1e-5f);
    for (int i = tid; i < QLR; i += 256)
        qa_ln[(long)t * QLR + i] = (row[i] - mean) * rs * qw[i];
    __syncthreads();

    // kv_a layernorm over KVLR=512
    const float* krow = kva_raw + (long)t * EFFD;
    s = 0.f; s2 = 0.f;
    for (int i = tid; i < KVLR; i += 256) { float v = krow[i]; s += v; s2 += v * v; }
    r1[tid] = s; r2[tid] = s2; __syncthreads();
    for (int o = 128; o > 0; o >>= 1) {
        if (tid < o) { r1[tid] += r1[tid + o]; r2[tid] += r2[tid + o]; }
        __syncthreads();
    }
    mean = r1[0] * (1.f / KVLR);
    var  = r2[0] * (1.f / KVLR) - mean * mean;
    rs   = rsqrtf(var + 1e-5f);
    for (int i = tid; i < KVLR; i += 256)
        kk[(long)t * EFFD + i] = (krow[i] - mean) * rs * kw[i];

    // k_pe rope (64)
    if (tid < ROPE) {
        int i = tid;
        float x   = krow[KVLR + i];
        float rot = (i < 32) ? -krow[KVLR + i + 32] : krow[KVLR + i - 32];
        kk[(long)t * EFFD + KVLR + i] =
            x * cosb[(long)t * ROPE + i] + rot * sinb[(long)t * ROPE + i];
    }
}

// ---------------- q_pe rope -> qq[...,512:576] ----------------
__global__ __launch_bounds__(256) void qrope_kernel(
    const float* __restrict__ q, const float* __restrict__ cosb,
    const float* __restrict__ sinb, float* __restrict__ qq)
{
    int t = blockIdx.x;
    int tid = threadIdx.x;
    for (int idx = tid; idx < NH * ROPE; idx += 256) {
        int h = idx >> 6, i = idx & 63;
        const float* qp = q + (long)t * (NH * QKD) + h * QKD + NOPE;
        float x   = qp[i];
        float rot = (i < 32) ? -qp[i + 32] : qp[i - 32];
        qq[(long)t * QSTR + h * EFFD + KVLR + i] =
            x * cosb[(long)t * ROPE + i] + rot * sinb[(long)t * ROPE + i];
    }
}

// ---------------- causal softmax (rows register-resident) ----------------
__global__ __launch_bounds__(128) void softmax_kernel(float* __restrict__ sc)
{
    int q  = blockIdx.x;
    int bh = blockIdx.y;
    float* row = sc + ((long)bh * SQ + q) * SQ;
    int n = q + 1;
    int tid = threadIdx.x;

    float v[8];
    int cnt = 0;
    float mx = -3.4e38f;
    for (int k = tid; k < n; k += 128) { float x = row[k]; v[cnt++] = x; mx = fmaxf(mx, x); }

    __shared__ float red[128];
    red[tid] = mx; __syncthreads();
    for (int o = 64; o > 0; o >>= 1) {
        if (tid < o) red[tid] = fmaxf(red[tid], red[tid + o]);
        __syncthreads();
    }
    mx = red[0]; __syncthreads();

    float sum = 0.f;
    for (int c = 0; c < cnt; c++) { float e = __expf(v[c] - mx); v[c] = e; sum += e; }
    red[tid] = sum; __syncthreads();
    for (int o = 64; o > 0; o >>= 1) {
        if (tid < o) red[tid] += red[tid + o];
        __syncthreads();
    }
    float inv = 1.f / red[0];

    cnt = 0;
    for (int k = tid; k < n; k += 128) row[k] = v[cnt++] * inv;
    // zero-fill up to the causal K-limit tile boundary so the ctx GEMM can
    // run dense up to m0+BM without masking
    int zend = ((q >> 7) + 1) << 7;
    for (int k = n + tid; k < zend; k += 128) row[k] = 0.f;
}

// ---------------- launch ----------------
extern "C" void kernel_launch(void* const* d_in, const int* in_sizes, int n_in,
                              void* d_out, int out_size)
{
    const float* hidden = (const float*)d_in[0];
    const float* cosb   = (const float*)d_in[1];
    const float* sinb   = (const float*)d_in[2];
    const float* w_qa   = (const float*)d_in[3];
    const float* qln    = (const float*)d_in[4];
    const float* w_qb   = (const float*)d_in[5];
    const float* w_kva  = (const float*)d_in[6];
    const float* kln    = (const float*)d_in[7];
    const float* w_uk   = (const float*)d_in[8];
    const float* w_uv   = (const float*)d_in[9];
    const float* w_o    = (const float*)d_in[10];
    float* out = (float*)d_out;

    float *qa_raw, *kva_raw, *qa_ln, *kkb, *qbuf, *qqb, *sc, *ctx, *attn;
    cudaGetSymbolAddress((void**)&qa_raw,  g_qa_raw);
    cudaGetSymbolAddress((void**)&kva_raw, g_kva_raw);
    cudaGetSymbolAddress((void**)&qa_ln,   g_qa_ln);
    cudaGetSymbolAddress((void**)&kkb,     g_kk);
    cudaGetSymbolAddress((void**)&qbuf,    g_q);
    cudaGetSymbolAddress((void**)&qqb,     g_qq);
    cudaGetSymbolAddress((void**)&sc,      g_sc);
    cudaGetSymbolAddress((void**)&ctx,     g_ctx);
    cudaGetSymbolAddress((void**)&attn,    g_attn);

    dim3 blk(256);
    const float scale = 1.0f / sqrtf((float)QKD);

    // 1) qa_raw = hidden @ w_qa^T           (2048 x 1536 x 2048)
    gemm_k<<<dim3(QLR / BN, TOK / BM, 1), blk>>>(
        hidden, HID, 0, 0,  w_qa, 1, HID, 0, 0,
        qa_raw, QLR, 0, 0,  HID, 1.f, 0, 1);

    // 2) kva_raw = hidden @ w_kva^T         (2048 x 576 x 2048)
    gemm_k<<<dim3(EFFD / BN, TOK / BM, 1), blk>>>(
        hidden, HID, 0, 0,  w_kva, 1, HID, 0, 0,
        kva_raw, EFFD, 0, 0,  HID, 1.f, 0, 1);

    // 3) layernorms + k_pe rope
    ln_rope_kernel<<<TOK, 256>>>(qa_raw, kva_raw, qln, kln, cosb, sinb, qa_ln, kkb);

    // 4) q = qa_ln @ w_qb^T                 (2048 x 3072 x 1536)
    gemm_k<<<dim3(NH * QKD / BN, TOK / BM, 1), blk>>>(
        qa_ln, QLR, 0, 0,  w_qb, 1, QLR, 0, 0,
        qbuf, NH * QKD, 0, 0,  QLR, 1.f, 0, 1);

    // 5) q_pe rope -> qq[...,512:576]
    qrope_kernel<<<TOK, 256>>>(qbuf, cosb, sinb, qqb);

    // 6) q_lat[h] = q_nope[h] @ W_UK_T[h]   (16 x (2048 x 512 x 128))
    gemm_k<<<dim3(KVLR / BN, TOK / BM, NH), blk>>>(
        qbuf, NH * QKD, 0, QKD,  w_uk, KVLR, 1, 0, (long)NOPE * KVLR,
        qqb, QSTR, 0, EFFD,  NOPE, 1.f, 0, NH);

    // 7) scores = qq @ kk^T * scale, causal tile-skip   (32 x (1024x1024x576))
    gemm_k<<<dim3(SQ / BN, SQ / BM, 2 * NH), blk>>>(
        qqb, QSTR, (long)SQ * QSTR, EFFD,
        kkb, 1, EFFD, (long)SQ * EFFD, 0,
        sc, SQ, (long)NH * SQ * SQ, (long)SQ * SQ,
        EFFD, scale, 1, NH);

    // 8) causal softmax (in place)
    softmax_kernel<<<dim3(SQ, 2 * NH), 128>>>(sc);

    // 9) ctx = p @ kv_c, causal K-limit     (32 x (1024x512x1024))
    gemm_k<<<dim3(KVLR / BN, SQ / BM, 2 * NH), blk>>>(
        sc, SQ, (long)NH * SQ * SQ, (long)SQ * SQ,
        kkb, EFFD, 1, (long)SQ * EFFD, 0,
        ctx, CTXLD, (long)SQ * CTXLD, KVLR,
        SQ, 1.f, 2, NH);

    // 10) attn[h] = ctx[h] @ W_UV[h]        (16 x (2048 x 128 x 512))
    gemm_k<<<dim3(VD / BN, TOK / BM, NH), blk>>>(
        ctx, CTXLD, 0, KVLR,  w_uv, VD, 1, 0, (long)KVLR * VD,
        attn, HID, 0, VD,  KVLR, 1.f, 0, NH);

    // 11) out = attn @ w_o^T                (2048 x 2048 x 2048)
    gemm_k<<<dim3(HID / BN, TOK / BM, 1), blk>>>(
        attn, HID, 0, 0,  w_o, 1, HID, 0, 0,
        out, HID, 0, 0,  HID, 1.f, 0, 1);
}

// round 7
// speedup vs baseline: 2.5564x; 2.4251x over previous
#include <cuda_runtime.h>
#include <cuda_bf16.h>
#include <math.h>
#include <stdint.h>

#define TOK   2048
#define HID   2048
#define QLR   1536
#define KVLR  512
#define ROPE  64
#define NH    16
#define QKD   192
#define NOPE  128
#define VD    128
#define SQ    1024
#define EFFD  576
#define QSTR  9216
#define CTXLD 8192

typedef __nv_bfloat16 bf;
typedef long long ll;

// ---------------- scratch ----------------
__device__ __align__(16) bf g_hid_h[TOK*HID],       g_hid_l[TOK*HID];
__device__ __align__(16) bf g_wqa_h[QLR*HID],       g_wqa_l[QLR*HID];
__device__ __align__(16) bf g_wkva_h[EFFD*HID],     g_wkva_l[EFFD*HID];
__device__ __align__(16) bf g_wqb_h[NH*QKD*QLR],    g_wqb_l[NH*QKD*QLR];
__device__ __align__(16) bf g_wo_h[HID*HID],        g_wo_l[HID*HID];
__device__ __align__(16) bf g_wukT_h[NH*KVLR*NOPE], g_wukT_l[NH*KVLR*NOPE];
__device__ __align__(16) bf g_wuvT_h[NH*VD*KVLR],   g_wuvT_l[NH*VD*KVLR];
__device__ __align__(16) float g_qa_raw[TOK*QLR];
__device__ __align__(16) float g_kva_raw[TOK*EFFD];
__device__ __align__(16) bf g_qaln_h[TOK*QLR],      g_qaln_l[TOK*QLR];
__device__ __align__(16) bf g_kk_h[TOK*EFFD],       g_kk_l[TOK*EFFD];
__device__ __align__(16) float g_kvc[TOK*KVLR];
__device__ __align__(16) bf g_kkT_h[2*KVLR*SQ],     g_kkT_l[2*KVLR*SQ];
__device__ __align__(16) float g_q[TOK*NH*QKD];
__device__ __align__(16) bf g_q_h[TOK*NH*QKD],      g_q_l[TOK*NH*QKD];
__device__ __align__(16) bf g_qq_h[TOK*QSTR],       g_qq_l[TOK*QSTR];
__device__ __align__(16) float g_sc[33554432];
__device__ __align__(16) bf g_p_h[33554432],        g_p_l[33554432];
__device__ __align__(16) bf g_ctx_h[TOK*CTXLD],     g_ctx_l[TOK*CTXLD];
__device__ __align__(16) bf g_attn_h[TOK*HID],      g_attn_l[TOK*HID];

__device__ __forceinline__ uint32_t smem_u32(const void* p) {
    uint32_t a;
    asm("{ .reg .u64 t; cvta.to.shared.u64 t, %1; cvt.u32.u64 %0, t; }" : "=r"(a) : "l"(p));
    return a;
}
__device__ __forceinline__ void split_hl(float v, unsigned short& h, unsigned short& l) {
    bf hh = __float2bfloat16(v);
    bf ll2 = __float2bfloat16(v - __bfloat162float(hh));
    h = __bfloat16_as_ushort(hh); l = __bfloat16_as_ushort(ll2);
}

#define LDMX4(r, a) \
    asm volatile("ldmatrix.sync.aligned.m8n8.x4.shared.b16 {%0,%1,%2,%3}, [%4];" \
        : "=r"((r)[0]), "=r"((r)[1]), "=r"((r)[2]), "=r"((r)[3]) : "r"(a))

__device__ __forceinline__ void mma_bf16(float* d, const uint32_t* a, const uint32_t* b) {
    asm volatile("mma.sync.aligned.m16n8k16.row.col.f32.bf16.bf16.f32 "
        "{%0,%1,%2,%3}, {%4,%5,%6,%7}, {%8,%9}, {%0,%1,%2,%3};"
        : "+f"(d[0]), "+f"(d[1]), "+f"(d[2]), "+f"(d[3])
        : "r"(a[0]), "r"(a[1]), "r"(a[2]), "r"(a[3]), "r"(b[0]), "r"(b[1]));
}

// ---- HMMA split-bf16 GEMM: C[m,n] = alpha * sum_k A[m,k]*B[n,k] ----
// A, B k-contiguous (lda/ldb in elements). mode 0 plain, 1 causal tile-skip,
// 2 causal K-limit. outmode 0: f32 C; 1: hi/lo bf16 (Ch, Cl).
#define BM 128
#define BN 64
#define BK 32
#define SKP 40
#define STAGE_B 30720
#define OFF_AH 0
#define OFF_AL 10240
#define OFF_BH 20480
#define OFF_BL 25600
#define SMEM_T (2*STAGE_B)

__global__ __launch_bounds__(256) void gemm_tc(
    const bf* __restrict__ Ah, const bf* __restrict__ Al, int lda, ll sAb, ll sAh,
    const bf* __restrict__ Bh, const bf* __restrict__ Bl, int ldb, ll sBb, ll sBh,
    float* __restrict__ C, bf* __restrict__ Ch, bf* __restrict__ Cl,
    int ldc, ll sCb, ll sCh, int K, float alpha, int mode, int zdiv, int outmode)
{
    extern __shared__ char sm[];
    int z = blockIdx.z, zb = z / zdiv, zh = z - zb * zdiv;
    int m0 = blockIdx.y * BM, n0 = blockIdx.x * BN;
    if (mode == 1 && n0 > m0 + (BM - 1)) return;
    int Kend = (mode == 2) ? min(K, m0 + BM) : K;
    int NIT = Kend / BK;

    Ah += zb * sAb + zh * sAh;  Al += zb * sAb + zh * sAh;
    Bh += zb * sBb + zh * sBh;  Bl += zb * sBb + zh * sBh;

    int tid = threadIdx.x, lane = tid & 31, wid = tid >> 5;
    int wm = wid & 3, wn = wid >> 2;           // 4 x 2 warp grid
    uint32_t sb = smem_u32(sm);

    auto load_stage = [&](int it, int s) {
        int k0 = it * BK;
        uint32_t st = sb + s * STAGE_B;
#pragma unroll
        for (int q = 0; q < 6; q++) {
            int g = q * 256 + tid;
            const bf* gp; uint32_t sa;
            if (g < 1024) {                       // A: 512 hi + 512 lo chunks
                int half = g >> 9, idx = g & 511;
                int row = idx >> 2, kc = idx & 3;
                gp = (half ? Al : Ah) + (ll)(m0 + row) * lda + k0 + kc * 8;
                sa = st + (half ? OFF_AL : OFF_AH) + (row * SKP + kc * 8) * 2;
            } else {                              // B: 256 hi + 256 lo chunks
                int h2 = g - 1024;
                int half = h2 >> 8, idx = h2 & 255;
                int row = idx >> 2, kc = idx & 3;
                gp = (half ? Bl : Bh) + (ll)(n0 + row) * ldb + k0 + kc * 8;
                sa = st + (half ? OFF_BL : OFF_BH) + (row * SKP + kc * 8) * 2;
            }
            asm volatile("cp.async.cg.shared.global [%0], [%1], 16;" :: "r"(sa), "l"(gp));
        }
        asm volatile("cp.async.commit_group;" ::: "memory");
    };

    float acc[2][4][4];
#pragma unroll
    for (int i = 0; i < 2; i++)
#pragma unroll
        for (int j = 0; j < 4; j++)
#pragma unroll
            for (int k = 0; k < 4; k++) acc[i][j][k] = 0.f;

    load_stage(0, 0);
    for (int it = 0; it < NIT; it++) {
        if (it + 1 < NIT) {
            load_stage(it + 1, (it + 1) & 1);
            asm volatile("cp.async.wait_group 1;" ::: "memory");
        } else {
            asm volatile("cp.async.wait_group 0;" ::: "memory");
        }
        __syncthreads();

        uint32_t st = sb + (it & 1) * STAGE_B;
#pragma unroll
        for (int ks = 0; ks < 2; ks++) {
            uint32_t Ah4[2][4], Al4[2][4];
#pragma unroll
            for (int mt = 0; mt < 2; mt++) {
                int row = wm * 32 + mt * 16 + (lane & 15);
                uint32_t col = ks * 16 + (lane >> 4) * 8;
                uint32_t a = st + OFF_AH + (row * SKP + col) * 2;
                LDMX4(Ah4[mt], a);
                LDMX4(Al4[mt], a + (OFF_AL - OFF_AH));
            }
            uint32_t Bh2[4][2], Bl2[4][2];
#pragma unroll
            for (int g2 = 0; g2 < 2; g2++) {
                int grp = lane >> 3;
                int nrow = wn * 32 + g2 * 16 + (grp >> 1) * 8 + (lane & 7);
                uint32_t col = ks * 16 + (grp & 1) * 8;
                uint32_t a = st + OFF_BH + (nrow * SKP + col) * 2;
                LDMX4(&Bh2[g2 * 2][0], a);
                LDMX4(&Bl2[g2 * 2][0], a + (OFF_BL - OFF_BH));
            }
#pragma unroll
            for (int mt = 0; mt < 2; mt++)
#pragma unroll
                for (int nt = 0; nt < 4; nt++) {
                    mma_bf16(acc[mt][nt], Ah4[mt], Bh2[nt]);
                    mma_bf16(acc[mt][nt], Ah4[mt], Bl2[nt]);
                    mma_bf16(acc[mt][nt], Al4[mt], Bh2[nt]);
                }
        }
        __syncthreads();
    }

    // epilogue
    int rbase = m0 + wm * 32 + (lane >> 2);
    int cbase = n0 + wn * 32 + (lane & 3) * 2;
    if (outmode == 0) {
        float* Cz = C + zb * sCb + zh * sCh;
#pragma unroll
        for (int mt = 0; mt < 2; mt++)
#pragma unroll
            for (int nt = 0; nt < 4; nt++) {
                int r = rbase + mt * 16, c = cbase + nt * 8;
                float2 v0 = make_float2(acc[mt][nt][0] * alpha, acc[mt][nt][1] * alpha);
                float2 v1 = make_float2(acc[mt][nt][2] * alpha, acc[mt][nt][3] * alpha);
                *reinterpret_cast<float2*>(&Cz[(ll)r * ldc + c]) = v0;
                *reinterpret_cast<float2*>(&Cz[(ll)(r + 8) * ldc + c]) = v1;
            }
    } else {
        bf* Chz = Ch + zb * sCb + zh * sCh;
        bf* Clz = Cl + zb * sCb + zh * sCh;
#pragma unroll
        for (int mt = 0; mt < 2; mt++)
#pragma unroll
            for (int nt = 0; nt < 4; nt++) {
                int r = rbase + mt * 16, c = cbase + nt * 8;
#pragma unroll
                for (int half = 0; half < 2; half++) {
                    int rr = r + half * 8;
                    unsigned short h0, l0, h1, l1;
                    split_hl(acc[mt][nt][half * 2 + 0] * alpha, h0, l0);
                    split_hl(acc[mt][nt][half * 2 + 1] * alpha, h1, l1);
                    uint32_t hv = h0 | ((uint32_t)h1 << 16);
                    uint32_t lv = l0 | ((uint32_t)l1 << 16);
                    *reinterpret_cast<uint32_t*>(&Chz[(ll)rr * ldc + c]) = hv;
                    *reinterpret_cast<uint32_t*>(&Clz[(ll)rr * ldc + c]) = lv;
                }
            }
    }
}

// ---- f32 -> hi/lo bf16 ----
__global__ __launch_bounds__(256) void cvt_hilo(const float* __restrict__ s,
                                                bf* __restrict__ h, bf* __restrict__ l) {
    ll i = ((ll)blockIdx.x * 256 + threadIdx.x) * 8;
    float4 a = *reinterpret_cast<const float4*>(s + i);
    float4 b = *reinterpret_cast<const float4*>(s + i + 4);
    float v[8] = {a.x, a.y, a.z, a.w, b.x, b.y, b.z, b.w};
    unsigned short hs[8], ls[8];
#pragma unroll
    for (int j = 0; j < 8; j++) split_hl(v[j], hs[j], ls[j]);
    uint4 hv, lv;
    hv.x = hs[0] | ((uint32_t)hs[1] << 16); hv.y = hs[2] | ((uint32_t)hs[3] << 16);
    hv.z = hs[4] | ((uint32_t)hs[5] << 16); hv.w = hs[6] | ((uint32_t)hs[7] << 16);
    lv.x = ls[0] | ((uint32_t)ls[1] << 16); lv.y = ls[2] | ((uint32_t)ls[3] << 16);
    lv.z = ls[4] | ((uint32_t)ls[5] << 16); lv.w = ls[6] | ((uint32_t)ls[7] << 16);
    *reinterpret_cast<uint4*>(h + i) = hv;
    *reinterpret_cast<uint4*>(l + i) = lv;
}

// ---- transpose + convert: src (RxC) -> dst (CxR) hi/lo ----
__global__ __launch_bounds__(256) void tcvt(const float* __restrict__ s, int lds, ll sz,
                                            bf* __restrict__ dh, bf* __restrict__ dl,
                                            int ldd, ll dz) {
    __shared__ float t[32][33];
    s += (ll)blockIdx.z * sz;  dh += (ll)blockIdx.z * dz;  dl += (ll)blockIdx.z * dz;
    int r0 = blockIdx.y * 32, c0 = blockIdx.x * 32;
    int tx = threadIdx.x & 31, ty = threadIdx.x >> 5;
#pragma unroll
    for (int i = 0; i < 32; i += 8)
        t[ty + i][tx] = s[(ll)(r0 + ty + i) * lds + c0 + tx];
    __syncthreads();
#pragma unroll
    for (int i = 0; i < 32; i += 8) {
        unsigned short hh, ll2;
        split_hl(t[tx][ty + i], hh, ll2);
        ll o = (ll)(c0 + ty + i) * ldd + r0 + tx;
        dh[o] = __ushort_as_bfloat16(hh);
        dl[o] = __ushort_as_bfloat16(ll2);
    }
}

// ---- dual LN + k_pe rope ----
__global__ __launch_bounds__(256) void ln_rope_k(
    const float* __restrict__ qa_raw, const float* __restrict__ kva_raw,
    const float* __restrict__ qw, const float* __restrict__ kw,
    const float* __restrict__ cosb, const float* __restrict__ sinb,
    bf* __restrict__ qh, bf* __restrict__ ql,
    bf* __restrict__ kh, bf* __restrict__ kl, float* __restrict__ kvc)
{
    int t = blockIdx.x, tid = threadIdx.x;
    __shared__ float r1[256], r2[256];
    const float* row = qa_raw + (ll)t * QLR;
    float s = 0.f, s2 = 0.f;
    for (int i = tid; i < QLR; i += 256) { float v = row[i]; s += v; s2 += v * v; }
    r1[tid] = s; r2[tid] = s2; __syncthreads();
    for (int o = 128; o > 0; o >>= 1) { if (tid < o) { r1[tid] += r1[tid+o]; r2[tid] += r2[tid+o]; } __syncthreads(); }
    float mean = r1[0] * (1.f / QLR);
    float rs = rsqrtf(r2[0] * (1.f / QLR) - mean * mean + 1e-5f);
    for (int i = tid; i < QLR; i += 256) {
        unsigned short hh, ll2; split_hl((row[i] - mean) * rs * qw[i], hh, ll2);
        qh[(ll)t * QLR + i] = __ushort_as_bfloat16(hh);
        ql[(ll)t * QLR + i] = __ushort_as_bfloat16(ll2);
    }
    __syncthreads();
    const float* krow = kva_raw + (ll)t * EFFD;
    s = 0.f; s2 = 0.f;
    for (int i = tid; i < KVLR; i += 256) { float v = krow[i]; s += v; s2 += v * v; }
    r1[tid] = s; r2[tid] = s2; __syncthreads();
    for (int o = 128; o > 0; o >>= 1) { if (tid < o) { r1[tid] += r1[tid+o]; r2[tid] += r2[tid+o]; } __syncthreads(); }
    mean = r1[0] * (1.f / KVLR);
    rs = rsqrtf(r2[0] * (1.f / KVLR) - mean * mean + 1e-5f);
    for (int i = tid; i < KVLR; i += 256) {
        float v = (krow[i] - mean) * rs * kw[i];
        unsigned short hh, ll2; split_hl(v, hh, ll2);
        kh[(ll)t * EFFD + i] = __ushort_as_bfloat16(hh);
        kl[(ll)t * EFFD + i] = __ushort_as_bfloat16(ll2);
        kvc[(ll)t * KVLR + i] = v;
    }
    if (tid < ROPE) {
        int i = tid;
        float x = krow[KVLR + i];
        float rot = (i < 32) ? -krow[KVLR + i + 32] : krow[KVLR + i - 32];
        float v = x * cosb[(ll)t * ROPE + i] + rot * sinb[(ll)t * ROPE + i];
        unsigned short hh, ll2; split_hl(v, hh, ll2);
        kh[(ll)t * EFFD + KVLR + i] = __ushort_as_bfloat16(hh);
        kl[(ll)t * EFFD + KVLR + i] = __ushort_as_bfloat16(ll2);
    }
}

// ---- q_pe rope -> qq[...,512:576] hi/lo ----
__global__ __launch_bounds__(256) void qrope_k(
    const float* __restrict__ q, const float* __restrict__ cosb,
    const float* __restrict__ sinb, bf* __restrict__ qqh, bf* __restrict__ qql)
{
    int t = blockIdx.x, tid = threadIdx.x;
    for (int idx = tid; idx < NH * ROPE; idx += 256) {
        int h = idx >> 6, i = idx & 63;
        const float* qp = q + (ll)t * (NH * QKD) + h * QKD + NOPE;
        float x = qp[i];
        float rot = (i < 32) ? -qp[i + 32] : qp[i - 32];
        float v = x * cosb[(ll)t * ROPE + i] + rot * sinb[(ll)t * ROPE + i];
        unsigned short hh, ll2; split_hl(v, hh, ll2);
        ll o = (ll)t * QSTR + h * EFFD + KVLR + i;
        qqh[o] = __ushort_as_bfloat16(hh);
        qql[o] = __ushort_as_bfloat16(ll2);
    }
}

// ---- causal softmax -> hi/lo bf16 p, zero-filled to 128-tile boundary ----
__global__ __launch_bounds__(128) void softmax_k(
    const float* __restrict__ sc, bf* __restrict__ ph, bf* __restrict__ pl)
{
    int q = blockIdx.x, bh = blockIdx.y;
    ll ob = ((ll)bh * SQ + q) * SQ;
    const float* row = sc + ob;
    int n = q + 1, tid = threadIdx.x;
    float v[8]; int cnt = 0; float mx = -3.4e38f;
    for (int k = tid; k < n; k += 128) { float x = row[k]; v[cnt++] = x; mx = fmaxf(mx, x); }
    __shared__ float red[128];
    red[tid] = mx; __syncthreads();
    for (int o = 64; o > 0; o >>= 1) { if (tid < o) red[tid] = fmaxf(red[tid], red[tid+o]); __syncthreads(); }
    mx = red[0]; __syncthreads();
    float sum = 0.f;
    for (int c = 0; c < cnt; c++) { float e = __expf(v[c] - mx); v[c] = e; sum += e; }
    red[tid] = sum; __syncthreads();
    for (int o = 64; o > 0; o >>= 1) { if (tid < o) red[tid] += red[tid+o]; __syncthreads(); }
    float inv = 1.f / red[0];
    cnt = 0;
    for (int k = tid; k < n; k += 128) {
        unsigned short hh, ll2; split_hl(v[cnt++] * inv, hh, ll2);
        ph[ob + k] = __ushort_as_bfloat16(hh);
        pl[ob + k] = __ushort_as_bfloat16(ll2);
    }
    int zend = ((q >> 7) + 1) << 7;
    bf z0 = __float2bfloat16(0.f);
    for (int k = n + tid; k < zend; k += 128) { ph[ob + k] = z0; pl[ob + k] = z0; }
}

extern "C" void kernel_launch(void* const* d_in, const int* in_sizes, int n_in,
                              void* d_out, int out_size)
{
    const float* hidden = (const float*)d_in[0];
    const float* cosb   = (const float*)d_in[1];
    const float* sinb   = (const float*)d_in[2];
    const float* w_qa   = (const float*)d_in[3];
    const float* qln    = (const float*)d_in[4];
    const float* w_qb   = (const float*)d_in[5];
    const float* w_kva  = (const float*)d_in[6];
    const float* kln    = (const float*)d_in[7];
    const float* w_uk   = (const float*)d_in[8];
    const float* w_uv   = (const float*)d_in[9];
    const float* w_o    = (const float*)d_in[10];
    float* out = (float*)d_out;

    bf *hid_h,*hid_l,*wqa_h,*wqa_l,*wkva_h,*wkva_l,*wqb_h,*wqb_l,*wo_h,*wo_l;
    bf *wukT_h,*wukT_l,*wuvT_h,*wuvT_l,*qaln_h,*qaln_l,*kk_h,*kk_l,*kkT_h,*kkT_l;
    bf *q_h,*q_l,*qq_h,*qq_l,*p_h,*p_l,*ctx_h,*ctx_l,*attn_h,*attn_l;
    float *qa_raw,*kva_raw,*kvc,*qf,*sc;
    cudaGetSymbolAddress((void**)&hid_h,g_hid_h);   cudaGetSymbolAddress((void**)&hid_l,g_hid_l);
    cudaGetSymbolAddress((void**)&wqa_h,g_wqa_h);   cudaGetSymbolAddress((void**)&wqa_l,g_wqa_l);
    cudaGetSymbolAddress((void**)&wkva_h,g_wkva_h); cudaGetSymbolAddress((void**)&wkva_l,g_wkva_l);
    cudaGetSymbolAddress((void**)&wqb_h,g_wqb_h);   cudaGetSymbolAddress((void**)&wqb_l,g_wqb_l);
    cudaGetSymbolAddress((void**)&wo_h,g_wo_h);     cudaGetSymbolAddress((void**)&wo_l,g_wo_l);
    cudaGetSymbolAddress((void**)&wukT_h,g_wukT_h); cudaGetSymbolAddress((void**)&wukT_l,g_wukT_l);
    cudaGetSymbolAddress((void**)&wuvT_h,g_wuvT_h); cudaGetSymbolAddress((void**)&wuvT_l,g_wuvT_l);
    cudaGetSymbolAddress((void**)&qa_raw,g_qa_raw); cudaGetSymbolAddress((void**)&kva_raw,g_kva_raw);
    cudaGetSymbolAddress((void**)&qaln_h,g_qaln_h); cudaGetSymbolAddress((void**)&qaln_l,g_qaln_l);
    cudaGetSymbolAddress((void**)&kk_h,g_kk_h);     cudaGetSymbolAddress((void**)&kk_l,g_kk_l);
    cudaGetSymbolAddress((void**)&kvc,g_kvc);
    cudaGetSymbolAddress((void**)&kkT_h,g_kkT_h);   cudaGetSymbolAddress((void**)&kkT_l,g_kkT_l);
    cudaGetSymbolAddress((void**)&qf,g_q);
    cudaGetSymbolAddress((void**)&q_h,g_q_h);       cudaGetSymbolAddress((void**)&q_l,g_q_l);
    cudaGetSymbolAddress((void**)&qq_h,g_qq_h);     cudaGetSymbolAddress((void**)&qq_l,g_qq_l);
    cudaGetSymbolAddress((void**)&sc,g_sc);
    cudaGetSymbolAddress((void**)&p_h,g_p_h);       cudaGetSymbolAddress((void**)&p_l,g_p_l);
    cudaGetSymbolAddress((void**)&ctx_h,g_ctx_h);   cudaGetSymbolAddress((void**)&ctx_l,g_ctx_l);
    cudaGetSymbolAddress((void**)&attn_h,g_attn_h); cudaGetSymbolAddress((void**)&attn_l,g_attn_l);

    cudaFuncSetAttribute(gemm_tc, cudaFuncAttributeMaxDynamicSharedMemorySize, SMEM_T);
    const float scale = 1.0f / sqrtf((float)QKD);

    // conversions
    cvt_hilo<<<TOK*HID/2048, 256>>>(hidden, hid_h, hid_l);
    cvt_hilo<<<QLR*HID/2048, 256>>>(w_qa, wqa_h, wqa_l);
    cvt_hilo<<<EFFD*HID/2048, 256>>>(w_kva, wkva_h, wkva_l);
    cvt_hilo<<<NH*QKD*QLR/2048, 256>>>(w_qb, wqb_h, wqb_l);
    cvt_hilo<<<HID*HID/2048, 256>>>(w_o, wo_h, wo_l);
    tcvt<<<dim3(KVLR/32, NOPE/32, NH), 256>>>(w_uk, KVLR, (ll)NOPE*KVLR, wukT_h, wukT_l, NOPE, (ll)KVLR*NOPE);
    tcvt<<<dim3(VD/32, KVLR/32, NH), 256>>>(w_uv, VD, (ll)KVLR*VD, wuvT_h, wuvT_l, KVLR, (ll)VD*KVLR);

    // 1) qa_raw = hidden @ w_qa^T  (f32 out)
    gemm_tc<<<dim3(QLR/BN, TOK/BM, 1), 256, SMEM_T>>>(
        hid_h, hid_l, HID, 0, 0,  wqa_h, wqa_l, HID, 0, 0,
        qa_raw, 0, 0, QLR, 0, 0,  HID, 1.f, 0, 1, 0);
    // 2) kva_raw = hidden @ w_kva^T  (f32 out)
    gemm_tc<<<dim3(EFFD/BN, TOK/BM, 1), 256, SMEM_T>>>(
        hid_h, hid_l, HID, 0, 0,  wkva_h, wkva_l, HID, 0, 0,
        kva_raw, 0, 0, EFFD, 0, 0,  HID, 1.f, 0, 1, 0);
    // 3) LN + k_pe rope
    ln_rope_k<<<TOK, 256>>>(qa_raw, kva_raw, qln, kln, cosb, sinb,
                            qaln_h, qaln_l, kk_h, kk_l, kvc);
    // kv_c^T per batch for ctx GEMM
    tcvt<<<dim3(KVLR/32, SQ/32, 2), 256>>>(kvc, KVLR, (ll)SQ*KVLR, kkT_h, kkT_l, SQ, (ll)KVLR*SQ);
    // 4) q = qa_ln @ w_qb^T  (f32)
    gemm_tc<<<dim3(NH*QKD/BN, TOK/BM, 1), 256, SMEM_T>>>(
        qaln_h, qaln_l, QLR, 0, 0,  wqb_h, wqb_l, QLR, 0, 0,
        qf, 0, 0, NH*QKD, 0, 0,  QLR, 1.f, 0, 1, 0);
    cvt_hilo<<<TOK*NH*QKD/2048, 256>>>(qf, q_h, q_l);
    qrope_k<<<TOK, 256>>>(qf, cosb, sinb, qq_h, qq_l);
    // 6) q_lat[h] = q_nope[h] @ wukT[h]^T -> qq[...,0:512] hi/lo
    gemm_tc<<<dim3(KVLR/BN, TOK/BM, NH), 256, SMEM_T>>>(
        q_h, q_l, NH*QKD, 0, QKD,  wukT_h, wukT_l, NOPE, 0, (ll)KVLR*NOPE,
        0, qq_h, qq_l, QSTR, 0, EFFD,  NOPE, 1.f, 0, NH, 1);
    // 7) scores = qq @ kk^T * scale, causal skip  (f32)
    gemm_tc<<<dim3(SQ/BN, SQ/BM, 2*NH), 256, SMEM_T>>>(
        qq_h, qq_l, QSTR, (ll)SQ*QSTR, EFFD,
        kk_h, kk_l, EFFD, (ll)SQ*EFFD, 0,
        sc, 0, 0, SQ, (ll)NH*SQ*SQ, (ll)SQ*SQ,  EFFD, scale, 1, NH, 0);
    // 8) softmax -> p hi/lo
    softmax_k<<<dim3(SQ, 2*NH), 128>>>(sc, p_h, p_l);
    // 9) ctx = p @ kv_c  (causal K-limit), hi/lo out
    gemm_tc<<<dim3(KVLR/BN, SQ/BM, 2*NH), 256, SMEM_T>>>(
        p_h, p_l, SQ, (ll)NH*SQ*SQ, (ll)SQ*SQ,
        kkT_h, kkT_l, SQ, (ll)KVLR*SQ, 0,
        0, ctx_h, ctx_l, CTXLD, (ll)SQ*CTXLD, KVLR,  SQ, 1.f, 2, NH, 1);
    // 10) attn[h] = ctx[h] @ wuvT[h]^T, hi/lo out
    gemm_tc<<<dim3(VD/BN, TOK/BM, NH), 256, SMEM_T>>>(
        ctx_h, ctx_l, CTXLD, 0, KVLR,  wuvT_h, wuvT_l, KVLR, 0, (ll)VD*KVLR,
        0, attn_h, attn_l, HID, 0, VD,  KVLR, 1.f, 0, NH, 1);
    // 11) out = attn @ w_o^T  (f32)
    gemm_tc<<<dim3(HID/BN, TOK/BM, 1), 256, SMEM_T>>>(
        attn_h, attn_l, HID, 0, 0,  wo_h, wo_l, HID, 0, 0,
        out, 0, 0, HID, 0, 0,  HID, 1.f, 0, 1, 0);
}

// round 8
// speedup vs baseline: 3.5356x; 1.3830x over previous
#include <cuda_runtime.h>
#include <cuda_fp16.h>
#include <math.h>
#include <stdint.h>

#define TOK   2048
#define HID   2048
#define QLR   1536
#define KVLR  512
#define ROPE  64
#define NH    16
#define QKD   192
#define NOPE  128
#define VD    128
#define SQ    1024
#define EFFD  576
#define QSTR  9216
#define CTXLD 8192

#define LSCALE 1024.0f
#define LINV   0.0009765625f

typedef __half hf;
typedef long long ll;

// ---------------- scratch ----------------
// A-side tensors: hi only. B-side tensors: hi + scaled-lo.
__device__ __align__(16) hf g_hid_h[TOK*HID];
__device__ __align__(16) hf g_wqa_h[QLR*HID],       g_wqa_l[QLR*HID];
__device__ __align__(16) hf g_wkva_h[EFFD*HID],     g_wkva_l[EFFD*HID];
__device__ __align__(16) hf g_wqb_h[NH*QKD*QLR],    g_wqb_l[NH*QKD*QLR];
__device__ __align__(16) hf g_wo_h[HID*HID],        g_wo_l[HID*HID];
__device__ __align__(16) hf g_wukT_h[NH*KVLR*NOPE], g_wukT_l[NH*KVLR*NOPE];
__device__ __align__(16) hf g_wuvT_h[NH*VD*KVLR],   g_wuvT_l[NH*VD*KVLR];
__device__ __align__(16) float g_qa_raw[TOK*QLR];
__device__ __align__(16) float g_kva_raw[TOK*EFFD];
__device__ __align__(16) hf g_qaln_h[TOK*QLR];
__device__ __align__(16) hf g_kk_h[TOK*EFFD],       g_kk_l[TOK*EFFD];
__device__ __align__(16) float g_kvc[TOK*KVLR];
__device__ __align__(16) hf g_kkT_h[2*KVLR*SQ],     g_kkT_l[2*KVLR*SQ];
__device__ __align__(16) float g_q[TOK*NH*QKD];
__device__ __align__(16) hf g_q_h[TOK*NH*QKD];
__device__ __align__(16) hf g_qq_h[TOK*QSTR];
__device__ __align__(16) float g_sc[33554432];
__device__ __align__(16) hf g_p_h[33554432];
__device__ __align__(16) hf g_ctx_h[TOK*CTXLD];
__device__ __align__(16) hf g_attn_h[TOK*HID];

__device__ __forceinline__ uint32_t smem_u32(const void* p) {
    uint32_t a;
    asm("{ .reg .u64 t; cvta.to.shared.u64 t, %1; cvt.u32.u64 %0, t; }" : "=r"(a) : "l"(p));
    return a;
}
// split: h = fp16(v), l = fp16((v - h) * 1024)   (scaled to dodge subnormal flush)
__device__ __forceinline__ void split_hl(float v, unsigned short& h, unsigned short& l) {
    hf hh = __float2half_rn(v);
    float r = (v - __half2float(hh)) * LSCALE;
    hf ll2 = __float2half_rn(r);
    h = __half_as_ushort(hh); l = __half_as_ushort(ll2);
}

#define LDMX4(r, a) \
    asm volatile("ldmatrix.sync.aligned.m8n8.x4.shared.b16 {%0,%1,%2,%3}, [%4];" \
        : "=r"((r)[0]), "=r"((r)[1]), "=r"((r)[2]), "=r"((r)[3]) : "r"(a))

__device__ __forceinline__ void mma_f16(float* d, const uint32_t* a, const uint32_t* b) {
    asm volatile("mma.sync.aligned.m16n8k16.row.col.f32.f16.f16.f32 "
        "{%0,%1,%2,%3}, {%4,%5,%6,%7}, {%8,%9}, {%0,%1,%2,%3};"
        : "+f"(d[0]), "+f"(d[1]), "+f"(d[2]), "+f"(d[3])
        : "r"(a[0]), "r"(a[1]), "r"(a[2]), "r"(a[3]), "r"(b[0]), "r"(b[1]));
}

// ---- fp16 2-MMA GEMM: C[m,n] = alpha * sum_k A[m,k]*B[n,k] ----
// A: single fp16. B: fp16 hi + scaled lo (x1024). Dual fp32 accumulators.
// mode 0 plain, 1 causal tile-skip, 2 causal K-limit.
// outmode 0: f32 C; 1: fp16 Ch.
#define BM 128
#define BN 64
#define BK 32
#define SKP 40
#define OFF_BH 10240
#define OFF_BL 15360
#define STAGE_B 20480
#define SMEM_T (3*STAGE_B)

__global__ __launch_bounds__(256) void gemm_tc(
    const hf* __restrict__ Ah, int lda, ll sAb, ll sAh,
    const hf* __restrict__ Bh, const hf* __restrict__ Bl, int ldb, ll sBb, ll sBh,
    float* __restrict__ C, hf* __restrict__ Ch,
    int ldc, ll sCb, ll sCh, int K, float alpha, int mode, int zdiv, int outmode)
{
    extern __shared__ char sm[];
    int z = blockIdx.z, zb = z / zdiv, zh = z - zb * zdiv;
    int m0 = blockIdx.y * BM, n0 = blockIdx.x * BN;
    if (mode == 1 && n0 > m0 + (BM - 1)) return;
    int Kend = (mode == 2) ? min(K, m0 + BM) : K;
    int NIT = Kend / BK;

    Ah += zb * sAb + zh * sAh;
    Bh += zb * sBb + zh * sBh;  Bl += zb * sBb + zh * sBh;

    int tid = threadIdx.x, lane = tid & 31, wid = tid >> 5;
    int wm = wid & 3, wn = wid >> 2;           // 4 x 2 warp grid, warp tile 32x32
    uint32_t sb = smem_u32(sm);

    auto load_stage = [&](int it, int s) {
        int k0 = it * BK;
        uint32_t st = sb + s * STAGE_B;
#pragma unroll
        for (int q = 0; q < 4; q++) {
            int g = q * 256 + tid;
            const hf* gp; uint32_t sa;
            if (g < 512) {                        // A: 128 rows x 4 chunks
                int row = g >> 2, kc = g & 3;
                gp = Ah + (ll)(m0 + row) * lda + k0 + kc * 8;
                sa = st + (row * SKP + kc * 8) * 2;
            } else if (g < 768) {                 // B hi: 64 rows x 4 chunks
                int idx = g - 512;
                int row = idx >> 2, kc = idx & 3;
                gp = Bh + (ll)(n0 + row) * ldb + k0 + kc * 8;
                sa = st + OFF_BH + (row * SKP + kc * 8) * 2;
            } else {                              // B lo
                int idx = g - 768;
                int row = idx >> 2, kc = idx & 3;
                gp = Bl + (ll)(n0 + row) * ldb + k0 + kc * 8;
                sa = st + OFF_BL + (row * SKP + kc * 8) * 2;
            }
            asm volatile("cp.async.cg.shared.global [%0], [%1], 16;" :: "r"(sa), "l"(gp));
        }
        asm volatile("cp.async.commit_group;" ::: "memory");
    };

    float acc1[2][4][4], acc2[2][4][4];
#pragma unroll
    for (int i = 0; i < 2; i++)
#pragma unroll
        for (int j = 0; j < 4; j++)
#pragma unroll
            for (int k = 0; k < 4; k++) { acc1[i][j][k] = 0.f; acc2[i][j][k] = 0.f; }

    load_stage(0, 0);
    if (NIT > 1) load_stage(1, 1);
    for (int it = 0; it < NIT; it++) {
        if (it + 2 < NIT) {
            load_stage(it + 2, (it + 2) % 3);
            asm volatile("cp.async.wait_group 2;" ::: "memory");
        } else if (it + 1 < NIT) {
            asm volatile("cp.async.wait_group 1;" ::: "memory");
        } else {
            asm volatile("cp.async.wait_group 0;" ::: "memory");
        }
        __syncthreads();

        uint32_t st = sb + (it % 3) * STAGE_B;
#pragma unroll
        for (int ks = 0; ks < 2; ks++) {
            uint32_t Af[2][4];
#pragma unroll
            for (int mt = 0; mt < 2; mt++) {
                int row = wm * 32 + mt * 16 + (lane & 15);
                uint32_t col = ks * 16 + (lane >> 4) * 8;
                LDMX4(Af[mt], st + (row * SKP + col) * 2);
            }
            uint32_t Bhf[4][2], Blf[4][2];
#pragma unroll
            for (int g2 = 0; g2 < 2; g2++) {
                int grp = lane >> 3;
                int nrow = wn * 32 + g2 * 16 + (grp >> 1) * 8 + (lane & 7);
                uint32_t col = ks * 16 + (grp & 1) * 8;
                uint32_t a = st + OFF_BH + (nrow * SKP + col) * 2;
                LDMX4(&Bhf[g2 * 2][0], a);
                LDMX4(&Blf[g2 * 2][0], a + (OFF_BL - OFF_BH));
            }
#pragma unroll
            for (int mt = 0; mt < 2; mt++)
#pragma unroll
                for (int nt = 0; nt < 4; nt++) {
                    mma_f16(acc1[mt][nt], Af[mt], Bhf[nt]);
                    mma_f16(acc2[mt][nt], Af[mt], Blf[nt]);
                }
        }
        __syncthreads();
    }

    // epilogue: v = (acc1 + acc2/1024) * alpha
    int rbase = m0 + wm * 32 + (lane >> 2);
    int cbase = n0 + wn * 32 + (lane & 3) * 2;
    if (outmode == 0) {
        float* Cz = C + zb * sCb + zh * sCh;
#pragma unroll
        for (int mt = 0; mt < 2; mt++)
#pragma unroll
            for (int nt = 0; nt < 4; nt++) {
                int r = rbase + mt * 16, c = cbase + nt * 8;
#pragma unroll
                for (int h2 = 0; h2 < 2; h2++) {
                    int rr = r + h2 * 8;
                    float v0 = fmaf(acc2[mt][nt][h2*2+0], LINV, acc1[mt][nt][h2*2+0]) * alpha;
                    float v1 = fmaf(acc2[mt][nt][h2*2+1], LINV, acc1[mt][nt][h2*2+1]) * alpha;
                    *reinterpret_cast<float2*>(&Cz[(ll)rr * ldc + c]) = make_float2(v0, v1);
                }
            }
    } else {
        hf* Chz = Ch + zb * sCb + zh * sCh;
#pragma unroll
        for (int mt = 0; mt < 2; mt++)
#pragma unroll
            for (int nt = 0; nt < 4; nt++) {
                int r = rbase + mt * 16, c = cbase + nt * 8;
#pragma unroll
                for (int h2 = 0; h2 < 2; h2++) {
                    int rr = r + h2 * 8;
                    float v0 = fmaf(acc2[mt][nt][h2*2+0], LINV, acc1[mt][nt][h2*2+0]) * alpha;
                    float v1 = fmaf(acc2[mt][nt][h2*2+1], LINV, acc1[mt][nt][h2*2+1]) * alpha;
                    uint32_t pk = (uint32_t)__half_as_ushort(__float2half_rn(v0))
                                | ((uint32_t)__half_as_ushort(__float2half_rn(v1)) << 16);
                    *reinterpret_cast<uint32_t*>(&Chz[(ll)rr * ldc + c]) = pk;
                }
            }
    }
}

// ---- f32 -> fp16 (hi only) ----
__global__ __launch_bounds__(256) void cvt_h(const float* __restrict__ s, hf* __restrict__ h) {
    ll i = ((ll)blockIdx.x * 256 + threadIdx.x) * 8;
    float4 a = *reinterpret_cast<const float4*>(s + i);
    float4 b = *reinterpret_cast<const float4*>(s + i + 4);
    float v[8] = {a.x, a.y, a.z, a.w, b.x, b.y, b.z, b.w};
    unsigned short hs[8];
#pragma unroll
    for (int j = 0; j < 8; j++) hs[j] = __half_as_ushort(__float2half_rn(v[j]));
    uint4 hv;
    hv.x = hs[0] | ((uint32_t)hs[1] << 16); hv.y = hs[2] | ((uint32_t)hs[3] << 16);
    hv.z = hs[4] | ((uint32_t)hs[5] << 16); hv.w = hs[6] | ((uint32_t)hs[7] << 16);
    *reinterpret_cast<uint4*>(h + i) = hv;
}

// ---- f32 -> fp16 hi + scaled lo ----
__global__ __launch_bounds__(256) void cvt_hl(const float* __restrict__ s,
                                              hf* __restrict__ h, hf* __restrict__ l) {
    ll i = ((ll)blockIdx.x * 256 + threadIdx.x) * 8;
    float4 a = *reinterpret_cast<const float4*>(s + i);
    float4 b = *reinterpret_cast<const float4*>(s + i + 4);
    float v[8] = {a.x, a.y, a.z, a.w, b.x, b.y, b.z, b.w};
    unsigned short hs[8], ls[8];
#pragma unroll
    for (int j = 0; j < 8; j++) split_hl(v[j], hs[j], ls[j]);
    uint4 hv, lv;
    hv.x = hs[0] | ((uint32_t)hs[1] << 16); hv.y = hs[2] | ((uint32_t)hs[3] << 16);
    hv.z = hs[4] | ((uint32_t)hs[5] << 16); hv.w = hs[6] | ((uint32_t)hs[7] << 16);
    lv.x = ls[0] | ((uint32_t)ls[1] << 16); lv.y = ls[2] | ((uint32_t)ls[3] << 16);
    lv.z = ls[4] | ((uint32_t)ls[5] << 16); lv.w = ls[6] | ((uint32_t)ls[7] << 16);
    *reinterpret_cast<uint4*>(h + i) = hv;
    *reinterpret_cast<uint4*>(l + i) = lv;
}

// ---- transpose + convert: src (RxC) -> dst (CxR) hi + scaled lo ----
__global__ __launch_bounds__(256) void tcvt(const float* __restrict__ s, int lds, ll sz,
                                            hf* __restrict__ dh, hf* __restrict__ dl,
                                            int ldd, ll dz) {
    __shared__ float t[32][33];
    s += (ll)blockIdx.z * sz;  dh += (ll)blockIdx.z * dz;  dl += (ll)blockIdx.z * dz;
    int r0 = blockIdx.y * 32, c0 = blockIdx.x * 32;
    int tx = threadIdx.x & 31, ty = threadIdx.x >> 5;
#pragma unroll
    for (int i = 0; i < 32; i += 8)
        t[ty + i][tx] = s[(ll)(r0 + ty + i) * lds + c0 + tx];
    __syncthreads();
#pragma unroll
    for (int i = 0; i < 32; i += 8) {
        unsigned short hh, ll2;
        split_hl(t[tx][ty + i], hh, ll2);
        ll o = (ll)(c0 + ty + i) * ldd + r0 + tx;
        dh[o] = __ushort_as_half(hh);
        dl[o] = __ushort_as_half(ll2);
    }
}

// ---- dual LN + k_pe rope ----
__global__ __launch_bounds__(256) void ln_rope_k(
    const float* __restrict__ qa_raw, const float* __restrict__ kva_raw,
    const float* __restrict__ qw, const float* __restrict__ kw,
    const float* __restrict__ cosb, const float* __restrict__ sinb,
    hf* __restrict__ qh, hf* __restrict__ kh, hf* __restrict__ kl,
    float* __restrict__ kvc)
{
    int t = blockIdx.x, tid = threadIdx.x;
    __shared__ float r1[256], r2[256];
    const float* row = qa_raw + (ll)t * QLR;
    float s = 0.f, s2 = 0.f;
    for (int i = tid; i < QLR; i += 256) { float v = row[i]; s += v; s2 += v * v; }
    r1[tid] = s; r2[tid] = s2; __syncthreads();
    for (int o = 128; o > 0; o >>= 1) { if (tid < o) { r1[tid] += r1[tid+o]; r2[tid] += r2[tid+o]; } __syncthreads(); }
    float mean = r1[0] * (1.f / QLR);
    float rs = rsqrtf(r2[0] * (1.f / QLR) - mean * mean + 1e-5f);
    for (int i = tid; i < QLR; i += 256)
        qh[(ll)t * QLR + i] = __float2half_rn((row[i] - mean) * rs * qw[i]);
    __syncthreads();
    const float* krow = kva_raw + (ll)t * EFFD;
    s = 0.f; s2 = 0.f;
    for (int i = tid; i < KVLR; i += 256) { float v = krow[i]; s += v; s2 += v * v; }
    r1[tid] = s; r2[tid] = s2; __syncthreads();
    for (int o = 128; o > 0; o >>= 1) { if (tid < o) { r1[tid] += r1[tid+o]; r2[tid] += r2[tid+o]; } __syncthreads(); }
    mean = r1[0] * (1.f / KVLR);
    rs = rsqrtf(r2[0] * (1.f / KVLR) - mean * mean + 1e-5f);
    for (int i = tid; i < KVLR; i += 256) {
        float v = (krow[i] - mean) * rs * kw[i];
        unsigned short hh, ll2; split_hl(v, hh, ll2);
        kh[(ll)t * EFFD + i] = __ushort_as_half(hh);
        kl[(ll)t * EFFD + i] = __ushort_as_half(ll2);
        kvc[(ll)t * KVLR + i] = v;
    }
    if (tid < ROPE) {
        int i = tid;
        float x = krow[KVLR + i];
        float rot = (i < 32) ? -krow[KVLR + i + 32] : krow[KVLR + i - 32];
        float v = x * cosb[(ll)t * ROPE + i] + rot * sinb[(ll)t * ROPE + i];
        unsigned short hh, ll2; split_hl(v, hh, ll2);
        kh[(ll)t * EFFD + KVLR + i] = __ushort_as_half(hh);
        kl[(ll)t * EFFD + KVLR + i] = __ushort_as_half(ll2);
    }
}

// ---- q_pe rope -> qq[...,512:576] ----
__global__ __launch_bounds__(256) void qrope_k(
    const float* __restrict__ q, const float* __restrict__ cosb,
    const float* __restrict__ sinb, hf* __restrict__ qqh)
{
    int t = blockIdx.x, tid = threadIdx.x;
    for (int idx = tid; idx < NH * ROPE; idx += 256) {
        int h = idx >> 6, i = idx & 63;
        const float* qp = q + (ll)t * (NH * QKD) + h * QKD + NOPE;
        float x = qp[i];
        float rot = (i < 32) ? -qp[i + 32] : qp[i - 32];
        float v = x * cosb[(ll)t * ROPE + i] + rot * sinb[(ll)t * ROPE + i];
        qqh[(ll)t * QSTR + h * EFFD + KVLR + i] = __float2half_rn(v);
    }
}

// ---- causal softmax -> fp16 p, zero-filled to 128-tile boundary ----
__global__ __launch_bounds__(128) void softmax_k(
    const float* __restrict__ sc, hf* __restrict__ ph)
{
    int q = blockIdx.x, bh = blockIdx.y;
    ll ob = ((ll)bh * SQ + q) * SQ;
    const float* row = sc + ob;
    int n = q + 1, tid = threadIdx.x;
    float v[8]; int cnt = 0; float mx = -3.4e38f;
    for (int k = tid; k < n; k += 128) { float x = row[k]; v[cnt++] = x; mx = fmaxf(mx, x); }
    __shared__ float red[128];
    red[tid] = mx; __syncthreads();
    for (int o = 64; o > 0; o >>= 1) { if (tid < o) red[tid] = fmaxf(red[tid], red[tid+o]); __syncthreads(); }
    mx = red[0]; __syncthreads();
    float sum = 0.f;
    for (int c = 0; c < cnt; c++) { float e = __expf(v[c] - mx); v[c] = e; sum += e; }
    red[tid] = sum; __syncthreads();
    for (int o = 64; o > 0; o >>= 1) { if (tid < o) red[tid] += red[tid+o]; __syncthreads(); }
    float inv = 1.f / red[0];
    cnt = 0;
    for (int k = tid; k < n; k += 128) ph[ob + k] = __float2half_rn(v[cnt++] * inv);
    int zend = ((q >> 7) + 1) << 7;
    hf z0 = __float2half_rn(0.f);
    for (int k = n + tid; k < zend; k += 128) ph[ob + k] = z0;
}

extern "C" void kernel_launch(void* const* d_in, const int* in_sizes, int n_in,
                              void* d_out, int out_size)
{
    const float* hidden = (const float*)d_in[0];
    const float* cosb   = (const float*)d_in[1];
    const float* sinb   = (const float*)d_in[2];
    const float* w_qa   = (const float*)d_in[3];
    const float* qln    = (const float*)d_in[4];
    const float* w_qb   = (const float*)d_in[5];
    const float* w_kva  = (const float*)d_in[6];
    const float* kln    = (const float*)d_in[7];
    const float* w_uk   = (const float*)d_in[8];
    const float* w_uv   = (const float*)d_in[9];
    const float* w_o    = (const float*)d_in[10];
    float* out = (float*)d_out;

    hf *hid_h,*wqa_h,*wqa_l,*wkva_h,*wkva_l,*wqb_h,*wqb_l,*wo_h,*wo_l;
    hf *wukT_h,*wukT_l,*wuvT_h,*wuvT_l,*qaln_h,*kk_h,*kk_l,*kkT_h,*kkT_l;
    hf *q_h,*qq_h,*p_h,*ctx_h,*attn_h;
    float *qa_raw,*kva_raw,*kvc,*qf,*sc;
    cudaGetSymbolAddress((void**)&hid_h,g_hid_h);
    cudaGetSymbolAddress((void**)&wqa_h,g_wqa_h);   cudaGetSymbolAddress((void**)&wqa_l,g_wqa_l);
    cudaGetSymbolAddress((void**)&wkva_h,g_wkva_h); cudaGetSymbolAddress((void**)&wkva_l,g_wkva_l);
    cudaGetSymbolAddress((void**)&wqb_h,g_wqb_h);   cudaGetSymbolAddress((void**)&wqb_l,g_wqb_l);
    cudaGetSymbolAddress((void**)&wo_h,g_wo_h);     cudaGetSymbolAddress((void**)&wo_l,g_wo_l);
    cudaGetSymbolAddress((void**)&wukT_h,g_wukT_h); cudaGetSymbolAddress((void**)&wukT_l,g_wukT_l);
    cudaGetSymbolAddress((void**)&wuvT_h,g_wuvT_h); cudaGetSymbolAddress((void**)&wuvT_l,g_wuvT_l);
    cudaGetSymbolAddress((void**)&qa_raw,g_qa_raw); cudaGetSymbolAddress((void**)&kva_raw,g_kva_raw);
    cudaGetSymbolAddress((void**)&qaln_h,g_qaln_h);
    cudaGetSymbolAddress((void**)&kk_h,g_kk_h);     cudaGetSymbolAddress((void**)&kk_l,g_kk_l);
    cudaGetSymbolAddress((void**)&kvc,g_kvc);
    cudaGetSymbolAddress((void**)&kkT_h,g_kkT_h);   cudaGetSymbolAddress((void**)&kkT_l,g_kkT_l);
    cudaGetSymbolAddress((void**)&qf,g_q);
    cudaGetSymbolAddress((void**)&q_h,g_q_h);
    cudaGetSymbolAddress((void**)&qq_h,g_qq_h);
    cudaGetSymbolAddress((void**)&sc,g_sc);
    cudaGetSymbolAddress((void**)&p_h,g_p_h);
    cudaGetSymbolAddress((void**)&ctx_h,g_ctx_h);
    cudaGetSymbolAddress((void**)&attn_h,g_attn_h);

    cudaFuncSetAttribute(gemm_tc, cudaFuncAttributeMaxDynamicSharedMemorySize, SMEM_T);
    const float scale = 1.0f / sqrtf((float)QKD);

    // conversions
    cvt_h<<<TOK*HID/2048, 256>>>(hidden, hid_h);
    cvt_hl<<<QLR*HID/2048, 256>>>(w_qa, wqa_h, wqa_l);
    cvt_hl<<<EFFD*HID/2048, 256>>>(w_kva, wkva_h, wkva_l);
    cvt_hl<<<NH*QKD*QLR/2048, 256>>>(w_qb, wqb_h, wqb_l);
    cvt_hl<<<HID*HID/2048, 256>>>(w_o, wo_h, wo_l);
    tcvt<<<dim3(KVLR/32, NOPE/32, NH), 256>>>(w_uk, KVLR, (ll)NOPE*KVLR, wukT_h, wukT_l, NOPE, (ll)KVLR*NOPE);
    tcvt<<<dim3(VD/32, KVLR/32, NH), 256>>>(w_uv, VD, (ll)KVLR*VD, wuvT_h, wuvT_l, KVLR, (ll)VD*KVLR);

    // 1) qa_raw = hidden @ w_qa^T  (f32)
    gemm_tc<<<dim3(QLR/BN, TOK/BM, 1), 256, SMEM_T>>>(
        hid_h, HID, 0, 0,  wqa_h, wqa_l, HID, 0, 0,
        qa_raw, 0, QLR, 0, 0,  HID, 1.f, 0, 1, 0);
    // 2) kva_raw = hidden @ w_kva^T  (f32)
    gemm_tc<<<dim3(EFFD/BN, TOK/BM, 1), 256, SMEM_T>>>(
        hid_h, HID, 0, 0,  wkva_h, wkva_l, HID, 0, 0,
        kva_raw, 0, EFFD, 0, 0,  HID, 1.f, 0, 1, 0);
    // 3) LN + k_pe rope
    ln_rope_k<<<TOK, 256>>>(qa_raw, kva_raw, qln, kln, cosb, sinb,
                            qaln_h, kk_h, kk_l, kvc);
    // kv_c^T per batch for ctx GEMM
    tcvt<<<dim3(KVLR/32, SQ/32, 2), 256>>>(kvc, KVLR, (ll)SQ*KVLR, kkT_h, kkT_l, SQ, (ll)KVLR*SQ);
    // 4) q = qa_ln @ w_qb^T  (f32)
    gemm_tc<<<dim3(NH*QKD/BN, TOK/BM, 1), 256, SMEM_T>>>(
        qaln_h, QLR, 0, 0,  wqb_h, wqb_l, QLR, 0, 0,
        qf, 0, NH*QKD, 0, 0,  QLR, 1.f, 0, 1, 0);
    cvt_h<<<TOK*NH*QKD/2048, 256>>>(qf, q_h);
    qrope_k<<<TOK, 256>>>(qf, cosb, sinb, qq_h);
    // 6) q_lat[h] = q_nope[h] @ wukT[h]^T -> qq[...,0:512]
    gemm_tc<<<dim3(KVLR/BN, TOK/BM, NH), 256, SMEM_T>>>(
        q_h, NH*QKD, 0, QKD,  wukT_h, wukT_l, NOPE, 0, (ll)KVLR*NOPE,
        0, qq_h, QSTR, 0, EFFD,  NOPE, 1.f, 0, NH, 1);
    // 7) scores = qq @ kk^T * scale, causal skip  (f32)
    gemm_tc<<<dim3(SQ/BN, SQ/BM, 2*NH), 256, SMEM_T>>>(
        qq_h, QSTR, (ll)SQ*QSTR, EFFD,
        kk_h, kk_l, EFFD, (ll)SQ*EFFD, 0,
        sc, 0, SQ, (ll)NH*SQ*SQ, (ll)SQ*SQ,  EFFD, scale, 1, NH, 0);
    // 8) softmax -> p fp16
    softmax_k<<<dim3(SQ, 2*NH), 128>>>(sc, p_h);
    // 9) ctx = p @ kv_c  (causal K-limit), fp16 out
    gemm_tc<<<dim3(KVLR/BN, SQ/BM, 2*NH), 256, SMEM_T>>>(
        p_h, SQ, (ll)NH*SQ*SQ, (ll)SQ*SQ,
        kkT_h, kkT_l, SQ, (ll)KVLR*SQ, 0,
        0, ctx_h, CTXLD, (ll)SQ*CTXLD, KVLR,  SQ, 1.f, 2, NH, 1);
    // 10) attn[h] = ctx[h] @ wuvT[h]^T, fp16 out
    gemm_tc<<<dim3(VD/BN, TOK/BM, NH), 256, SMEM_T>>>(
        ctx_h, CTXLD, 0, KVLR,  wuvT_h, wuvT_l, KVLR, 0, (ll)VD*KVLR,
        0, attn_h, HID, 0, VD,  KVLR, 1.f, 0, NH, 1);
    // 11) out = attn @ w_o^T  (f32)
    gemm_tc<<<dim3(HID/BN, TOK/BM, 1), 256, SMEM_T>>>(
        attn_h, HID, 0, 0,  wo_h, wo_l, HID, 0, 0,
        out, 0, HID, 0, 0,  HID, 1.f, 0, 1, 0);
}

// round 9
// speedup vs baseline: 3.9001x; 1.1031x over previous
#include <cuda_runtime.h>
#include <cuda_fp16.h>
#include <math.h>
#include <stdint.h>

#define TOK   2048
#define HID   2048
#define QLR   1536
#define KVLR  512
#define ROPE  64
#define NH    16
#define QKD   192
#define NOPE  128
#define VD    128
#define SQ    1024
#define EFFD  576
#define QSTR  9216
#define CTXLD 8192

#define LSCALE 1024.0f
#define LINV   0.0009765625f

typedef __half hf;
typedef long long ll;

// ---------------- scratch ----------------
__device__ __align__(16) hf g_hid_h[TOK*HID];
__device__ __align__(16) hf g_wqa_h[QLR*HID],       g_wqa_l[QLR*HID];
__device__ __align__(16) hf g_wkva_h[EFFD*HID],     g_wkva_l[EFFD*HID];
__device__ __align__(16) hf g_wqb_h[NH*QKD*QLR],    g_wqb_l[NH*QKD*QLR];
__device__ __align__(16) hf g_wo_h[HID*HID],        g_wo_l[HID*HID];
__device__ __align__(16) hf g_wukT_h[NH*KVLR*NOPE], g_wukT_l[NH*KVLR*NOPE];
__device__ __align__(16) hf g_wuvT_h[NH*VD*KVLR],   g_wuvT_l[NH*VD*KVLR];
__device__ __align__(16) float g_qa_raw[TOK*QLR];
__device__ __align__(16) float g_kva_raw[TOK*EFFD];
__device__ __align__(16) hf g_qaln_h[TOK*QLR];
__device__ __align__(16) hf g_kk_h[TOK*EFFD],       g_kk_l[TOK*EFFD];
__device__ __align__(16) float g_kvc[TOK*KVLR];
__device__ __align__(16) hf g_kkT_h[2*KVLR*SQ],     g_kkT_l[2*KVLR*SQ];
__device__ __align__(16) float g_q[TOK*NH*QKD];
__device__ __align__(16) hf g_q_h[TOK*NH*QKD];
__device__ __align__(16) hf g_qq_h[TOK*QSTR];
__device__ __align__(16) float g_sc[33554432];
__device__ __align__(16) hf g_p_h[33554432];
__device__ __align__(16) hf g_ctx_h[TOK*CTXLD];
__device__ __align__(16) hf g_attn_h[TOK*HID];

__device__ __forceinline__ uint32_t smem_u32(const void* p) {
    uint32_t a;
    asm("{ .reg .u64 t; cvta.to.shared.u64 t, %1; cvt.u32.u64 %0, t; }" : "=r"(a) : "l"(p));
    return a;
}
// split: h = fp16(v), l = fp16((v - h) * 1024)   (scaled to dodge subnormal flush)
__device__ __forceinline__ void split_hl(float v, unsigned short& h, unsigned short& l) {
    hf hh = __float2half_rn(v);
    float r = (v - __half2float(hh)) * LSCALE;
    hf ll2 = __float2half_rn(r);
    h = __half_as_ushort(hh); l = __half_as_ushort(ll2);
}

#define LDMX4(r, a) \
    asm volatile("ldmatrix.sync.aligned.m8n8.x4.shared.b16 {%0,%1,%2,%3}, [%4];" \
        : "=r"((r)[0]), "=r"((r)[1]), "=r"((r)[2]), "=r"((r)[3]) : "r"(a))

__device__ __forceinline__ void mma_f16(float* d, const uint32_t* a, const uint32_t* b) {
    asm volatile("mma.sync.aligned.m16n8k16.row.col.f32.f16.f16.f32 "
        "{%0,%1,%2,%3}, {%4,%5,%6,%7}, {%8,%9}, {%0,%1,%2,%3};"
        : "+f"(d[0]), "+f"(d[1]), "+f"(d[2]), "+f"(d[3])
        : "r"(a[0]), "r"(a[1]), "r"(a[2]), "r"(a[3]), "r"(b[0]), "r"(b[1]));
}

// ---- fp16 2-MMA GEMM: C[m,n] = alpha * sum_k A[m,k]*B[n,k] ----
// A: single fp16. B: fp16 hi + scaled lo (x1024). Dual fp32 accumulators.
// mode 0 plain, 1 causal tile-skip, 2 causal K-limit.
// outmode 0: f32 C; 1: fp16 Ch.
#define BM 128
#define BN 64
#define BK 64
#define SKP 72
#define OFF_BH 18432
#define OFF_BL 27648
#define STAGE_B 36864
#define SMEM_T (3*STAGE_B)

__global__ __launch_bounds__(256) void gemm_tc(
    const hf* __restrict__ Ah, int lda, ll sAb, ll sAh,
    const hf* __restrict__ Bh, const hf* __restrict__ Bl, int ldb, ll sBb, ll sBh,
    float* __restrict__ C, hf* __restrict__ Ch,
    int ldc, ll sCb, ll sCh, int K, float alpha, int mode, int zdiv, int outmode)
{
    extern __shared__ char sm[];
    int z = blockIdx.z, zb = z / zdiv, zh = z - zb * zdiv;
    int m0 = blockIdx.y * BM, n0 = blockIdx.x * BN;
    if (mode == 1 && n0 > m0 + (BM - 1)) return;
    int Kend = (mode == 2) ? min(K, m0 + BM) : K;
    int NIT = Kend / BK;

    Ah += zb * sAb + zh * sAh;
    Bh += zb * sBb + zh * sBh;  Bl += zb * sBb + zh * sBh;

    int tid = threadIdx.x, lane = tid & 31, wid = tid >> 5;
    int wm = wid & 3, wn = wid >> 2;           // 4 x 2 warp grid, warp tile 32x32
    uint32_t sb = smem_u32(sm);

    auto load_stage = [&](int it, int s) {
        int k0 = it * BK;
        uint32_t st = sb + s * STAGE_B;
#pragma unroll
        for (int q = 0; q < 8; q++) {
            int g = q * 256 + tid;
            const hf* gp; uint32_t sa;
            if (g < 1024) {                       // A: 128 rows x 8 chunks of 16B
                int row = g >> 3, kc = g & 7;
                gp = Ah + (ll)(m0 + row) * lda + k0 + kc * 8;
                sa = st + (row * SKP + kc * 8) * 2;
            } else if (g < 1536) {                // B hi: 64 rows x 8 chunks
                int idx = g - 1024;
                int row = idx >> 3, kc = idx & 7;
                gp = Bh + (ll)(n0 + row) * ldb + k0 + kc * 8;
                sa = st + OFF_BH + (row * SKP + kc * 8) * 2;
            } else {                              // B lo: 64 rows x 8 chunks
                int idx = g - 1536;
                int row = idx >> 3, kc = idx & 7;
                gp = Bl + (ll)(n0 + row) * ldb + k0 + kc * 8;
                sa = st + OFF_BL + (row * SKP + kc * 8) * 2;
            }
            asm volatile("cp.async.cg.shared.global [%0], [%1], 16;" :: "r"(sa), "l"(gp));
        }
        asm volatile("cp.async.commit_group;" ::: "memory");
    };

    float acc1[2][4][4], acc2[2][4][4];
#pragma unroll
    for (int i = 0; i < 2; i++)
#pragma unroll
        for (int j = 0; j < 4; j++)
#pragma unroll
            for (int k = 0; k < 4; k++) { acc1[i][j][k] = 0.f; acc2[i][j][k] = 0.f; }

    load_stage(0, 0);
    if (NIT > 1) load_stage(1, 1);
    for (int it = 0; it < NIT; it++) {
        if (it + 2 < NIT) {
            load_stage(it + 2, (it + 2) % 3);
            asm volatile("cp.async.wait_group 2;" ::: "memory");
        } else if (it + 1 < NIT) {
            asm volatile("cp.async.wait_group 1;" ::: "memory");
        } else {
            asm volatile("cp.async.wait_group 0;" ::: "memory");
        }
        __syncthreads();

        uint32_t st = sb + (it % 3) * STAGE_B;
#pragma unroll
        for (int ks = 0; ks < 4; ks++) {
            uint32_t Af[2][4];
#pragma unroll
            for (int mt = 0; mt < 2; mt++) {
                int row = wm * 32 + mt * 16 + (lane & 15);
                uint32_t col = ks * 16 + (lane >> 4) * 8;
                LDMX4(Af[mt], st + (row * SKP + col) * 2);
            }
            uint32_t Bhf[4][2], Blf[4][2];
#pragma unroll
            for (int g2 = 0; g2 < 2; g2++) {
                int grp = lane >> 3;
                int nrow = wn * 32 + g2 * 16 + (grp >> 1) * 8 + (lane & 7);
                uint32_t col = ks * 16 + (grp & 1) * 8;
                uint32_t a = st + OFF_BH + (nrow * SKP + col) * 2;
                LDMX4(&Bhf[g2 * 2][0], a);
                LDMX4(&Blf[g2 * 2][0], a + (OFF_BL - OFF_BH));
            }
#pragma unroll
            for (int mt = 0; mt < 2; mt++)
#pragma unroll
                for (int nt = 0; nt < 4; nt++) {
                    mma_f16(acc1[mt][nt], Af[mt], Bhf[nt]);
                    mma_f16(acc2[mt][nt], Af[mt], Blf[nt]);
                }
        }
        __syncthreads();
    }

    // epilogue: v = (acc1 + acc2/1024) * alpha
    int rbase = m0 + wm * 32 + (lane >> 2);
    int cbase = n0 + wn * 32 + (lane & 3) * 2;
    if (outmode == 0) {
        float* Cz = C + zb * sCb + zh * sCh;
#pragma unroll
        for (int mt = 0; mt < 2; mt++)
#pragma unroll
            for (int nt = 0; nt < 4; nt++) {
                int r = rbase + mt * 16, c = cbase + nt * 8;
#pragma unroll
                for (int h2 = 0; h2 < 2; h2++) {
                    int rr = r + h2 * 8;
                    float v0 = fmaf(acc2[mt][nt][h2*2+0], LINV, acc1[mt][nt][h2*2+0]) * alpha;
                    float v1 = fmaf(acc2[mt][nt][h2*2+1], LINV, acc1[mt][nt][h2*2+1]) * alpha;
                    *reinterpret_cast<float2*>(&Cz[(ll)rr * ldc + c]) = make_float2(v0, v1);
                }
            }
    } else {
        hf* Chz = Ch + zb * sCb + zh * sCh;
#pragma unroll
        for (int mt = 0; mt < 2; mt++)
#pragma unroll
            for (int nt = 0; nt < 4; nt++) {
                int r = rbase + mt * 16, c = cbase + nt * 8;
#pragma unroll
                for (int h2 = 0; h2 < 2; h2++) {
                    int rr = r + h2 * 8;
                    float v0 = fmaf(acc2[mt][nt][h2*2+0], LINV, acc1[mt][nt][h2*2+0]) * alpha;
                    float v1 = fmaf(acc2[mt][nt][h2*2+1], LINV, acc1[mt][nt][h2*2+1]) * alpha;
                    uint32_t pk = (uint32_t)__half_as_ushort(__float2half_rn(v0))
                                | ((uint32_t)__half_as_ushort(__float2half_rn(v1)) << 16);
                    *reinterpret_cast<uint32_t*>(&Chz[(ll)rr * ldc + c]) = pk;
                }
            }
    }
}

// ---- f32 -> fp16 (hi only) ----
__global__ __launch_bounds__(256) void cvt_h(const float* __restrict__ s, hf* __restrict__ h) {
    ll i = ((ll)blockIdx.x * 256 + threadIdx.x) * 8;
    float4 a = *reinterpret_cast<const float4*>(s + i);
    float4 b = *reinterpret_cast<const float4*>(s + i + 4);
    float v[8] = {a.x, a.y, a.z, a.w, b.x, b.y, b.z, b.w};
    unsigned short hs[8];
#pragma unroll
    for (int j = 0; j < 8; j++) hs[j] = __half_as_ushort(__float2half_rn(v[j]));
    uint4 hv;
    hv.x = hs[0] | ((uint32_t)hs[1] << 16); hv.y = hs[2] | ((uint32_t)hs[3] << 16);
    hv.z = hs[4] | ((uint32_t)hs[5] << 16); hv.w = hs[6] | ((uint32_t)hs[7] << 16);
    *reinterpret_cast<uint4*>(h + i) = hv;
}

// ---- f32 -> fp16 hi + scaled lo ----
__global__ __launch_bounds__(256) void cvt_hl(const float* __restrict__ s,
                                              hf* __restrict__ h, hf* __restrict__ l) {
    ll i = ((ll)blockIdx.x * 256 + threadIdx.x) * 8;
    float4 a = *reinterpret_cast<const float4*>(s + i);
    float4 b = *reinterpret_cast<const float4*>(s + i + 4);
    float v[8] = {a.x, a.y, a.z, a.w, b.x, b.y, b.z, b.w};
    unsigned short hs[8], ls[8];
#pragma unroll
    for (int j = 0; j < 8; j++) split_hl(v[j], hs[j], ls[j]);
    uint4 hv, lv;
    hv.x = hs[0] | ((uint32_t)hs[1] << 16); hv.y = hs[2] | ((uint32_t)hs[3] << 16);
    hv.z = hs[4] | ((uint32_t)hs[5] << 16); hv.w = hs[6] | ((uint32_t)hs[7] << 16);
    lv.x = ls[0] | ((uint32_t)ls[1] << 16); lv.y = ls[2] | ((uint32_t)ls[3] << 16);
    lv.z = ls[4] | ((uint32_t)ls[5] << 16); lv.w = ls[6] | ((uint32_t)ls[7] << 16);
    *reinterpret_cast<uint4*>(h + i) = hv;
    *reinterpret_cast<uint4*>(l + i) = lv;
}

// ---- transpose + convert: src (RxC) -> dst (CxR) hi + scaled lo ----
__global__ __launch_bounds__(256) void tcvt(const float* __restrict__ s, int lds, ll sz,
                                            hf* __restrict__ dh, hf* __restrict__ dl,
                                            int ldd, ll dz) {
    __shared__ float t[32][33];
    s += (ll)blockIdx.z * sz;  dh += (ll)blockIdx.z * dz;  dl += (ll)blockIdx.z * dz;
    int r0 = blockIdx.y * 32, c0 = blockIdx.x * 32;
    int tx = threadIdx.x & 31, ty = threadIdx.x >> 5;
#pragma unroll
    for (int i = 0; i < 32; i += 8)
        t[ty + i][tx] = s[(ll)(r0 + ty + i) * lds + c0 + tx];
    __syncthreads();
#pragma unroll
    for (int i = 0; i < 32; i += 8) {
        unsigned short hh, ll2;
        split_hl(t[tx][ty + i], hh, ll2);
        ll o = (ll)(c0 + ty + i) * ldd + r0 + tx;
        dh[o] = __ushort_as_half(hh);
        dl[o] = __ushort_as_half(ll2);
    }
}

// ---- dual LN + k_pe rope ----
__global__ __launch_bounds__(256) void ln_rope_k(
    const float* __restrict__ qa_raw, const float* __restrict__ kva_raw,
    const float* __restrict__ qw, const float* __restrict__ kw,
    const float* __restrict__ cosb, const float* __restrict__ sinb,
    hf* __restrict__ qh, hf* __restrict__ kh, hf* __restrict__ kl,
    float* __restrict__ kvc)
{
    int t = blockIdx.x, tid = threadIdx.x;
    __shared__ float r1[256], r2[256];
    const float* row = qa_raw + (ll)t * QLR;
    float s = 0.f, s2 = 0.f;
    for (int i = tid; i < QLR; i += 256) { float v = row[i]; s += v; s2 += v * v; }
    r1[tid] = s; r2[tid] = s2; __syncthreads();
    for (int o = 128; o > 0; o >>= 1) { if (tid < o) { r1[tid] += r1[tid+o]; r2[tid] += r2[tid+o]; } __syncthreads(); }
    float mean = r1[0] * (1.f / QLR);
    float rs = rsqrtf(r2[0] * (1.f / QLR) - mean * mean + 1e-5f);
    for (int i = tid; i < QLR; i += 256)
        qh[(ll)t * QLR + i] = __float2half_rn((row[i] - mean) * rs * qw[i]);
    __syncthreads();
    const float* krow = kva_raw + (ll)t * EFFD;
    s = 0.f; s2 = 0.f;
    for (int i = tid; i < KVLR; i += 256) { float v = krow[i]; s += v; s2 += v * v; }
    r1[tid] = s; r2[tid] = s2; __syncthreads();
    for (int o = 128; o > 0; o >>= 1) { if (tid < o) { r1[tid] += r1[tid+o]; r2[tid] += r2[tid+o]; } __syncthreads(); }
    mean = r1[0] * (1.f / KVLR);
    rs = rsqrtf(r2[0] * (1.f / KVLR) - mean * mean + 1e-5f);
    for (int i = tid; i < KVLR; i += 256) {
        float v = (krow[i] - mean) * rs * kw[i];
        unsigned short hh, ll2; split_hl(v, hh, ll2);
        kh[(ll)t * EFFD + i] = __ushort_as_half(hh);
        kl[(ll)t * EFFD + i] = __ushort_as_half(ll2);
        kvc[(ll)t * KVLR + i] = v;
    }
    if (tid < ROPE) {
        int i = tid;
        float x = krow[KVLR + i];
        float rot = (i < 32) ? -krow[KVLR + i + 32] : krow[KVLR + i - 32];
        float v = x * cosb[(ll)t * ROPE + i] + rot * sinb[(ll)t * ROPE + i];
        unsigned short hh, ll2; split_hl(v, hh, ll2);
        kh[(ll)t * EFFD + KVLR + i] = __ushort_as_half(hh);
        kl[(ll)t * EFFD + KVLR + i] = __ushort_as_half(ll2);
    }
}

// ---- q_pe rope -> qq[...,512:576] ----
__global__ __launch_bounds__(256) void qrope_k(
    const float* __restrict__ q, const float* __restrict__ cosb,
    const float* __restrict__ sinb, hf* __restrict__ qqh)
{
    int t = blockIdx.x, tid = threadIdx.x;
    for (int idx = tid; idx < NH * ROPE; idx += 256) {
        int h = idx >> 6, i = idx & 63;
        const float* qp = q + (ll)t * (NH * QKD) + h * QKD + NOPE;
        float x = qp[i];
        float rot = (i < 32) ? -qp[i + 32] : qp[i - 32];
        float v = x * cosb[(ll)t * ROPE + i] + rot * sinb[(ll)t * ROPE + i];
        qqh[(ll)t * QSTR + h * EFFD + KVLR + i] = __float2half_rn(v);
    }
}

// ---- causal softmax -> fp16 p, zero-filled to 128-tile boundary ----
__global__ __launch_bounds__(128) void softmax_k(
    const float* __restrict__ sc, hf* __restrict__ ph)
{
    int q = blockIdx.x, bh = blockIdx.y;
    ll ob = ((ll)bh * SQ + q) * SQ;
    const float* row = sc + ob;
    int n = q + 1, tid = threadIdx.x;
    float v[8]; int cnt = 0; float mx = -3.4e38f;
    for (int k = tid; k < n; k += 128) { float x = row[k]; v[cnt++] = x; mx = fmaxf(mx, x); }
    __shared__ float red[128];
    red[tid] = mx; __syncthreads();
    for (int o = 64; o > 0; o >>= 1) { if (tid < o) red[tid] = fmaxf(red[tid], red[tid+o]); __syncthreads(); }
    mx = red[0]; __syncthreads();
    float sum = 0.f;
    for (int c = 0; c < cnt; c++) { float e = __expf(v[c] - mx); v[c] = e; sum += e; }
    red[tid] = sum; __syncthreads();
    for (int o = 64; o > 0; o >>= 1) { if (tid < o) red[tid] += red[tid+o]; __syncthreads(); }
    float inv = 1.f / red[0];
    cnt = 0;
    for (int k = tid; k < n; k += 128) ph[ob + k] = __float2half_rn(v[cnt++] * inv);
    int zend = ((q >> 7) + 1) << 7;
    hf z0 = __float2half_rn(0.f);
    for (int k = n + tid; k < zend; k += 128) ph[ob + k] = z0;
}

extern "C" void kernel_launch(void* const* d_in, const int* in_sizes, int n_in,
                              void* d_out, int out_size)
{
    const float* hidden = (const float*)d_in[0];
    const float* cosb   = (const float*)d_in[1];
    const float* sinb   = (const float*)d_in[2];
    const float* w_qa   = (const float*)d_in[3];
    const float* qln    = (const float*)d_in[4];
    const float* w_qb   = (const float*)d_in[5];
    const float* w_kva  = (const float*)d_in[6];
    const float* kln    = (const float*)d_in[7];
    const float* w_uk   = (const float*)d_in[8];
    const float* w_uv   = (const float*)d_in[9];
    const float* w_o    = (const float*)d_in[10];
    float* out = (float*)d_out;

    hf *hid_h,*wqa_h,*wqa_l,*wkva_h,*wkva_l,*wqb_h,*wqb_l,*wo_h,*wo_l;
    hf *wukT_h,*wukT_l,*wuvT_h,*wuvT_l,*qaln_h,*kk_h,*kk_l,*kkT_h,*kkT_l;
    hf *q_h,*qq_h,*p_h,*ctx_h,*attn_h;
    float *qa_raw,*kva_raw,*kvc,*qf,*sc;
    cudaGetSymbolAddress((void**)&hid_h,g_hid_h);
    cudaGetSymbolAddress((void**)&wqa_h,g_wqa_h);   cudaGetSymbolAddress((void**)&wqa_l,g_wqa_l);
    cudaGetSymbolAddress((void**)&wkva_h,g_wkva_h); cudaGetSymbolAddress((void**)&wkva_l,g_wkva_l);
    cudaGetSymbolAddress((void**)&wqb_h,g_wqb_h);   cudaGetSymbolAddress((void**)&wqb_l,g_wqb_l);
    cudaGetSymbolAddress((void**)&wo_h,g_wo_h);     cudaGetSymbolAddress((void**)&wo_l,g_wo_l);
    cudaGetSymbolAddress((void**)&wukT_h,g_wukT_h); cudaGetSymbolAddress((void**)&wukT_l,g_wukT_l);
    cudaGetSymbolAddress((void**)&wuvT_h,g_wuvT_h); cudaGetSymbolAddress((void**)&wuvT_l,g_wuvT_l);
    cudaGetSymbolAddress((void**)&qa_raw,g_qa_raw); cudaGetSymbolAddress((void**)&kva_raw,g_kva_raw);
    cudaGetSymbolAddress((void**)&qaln_h,g_qaln_h);
    cudaGetSymbolAddress((void**)&kk_h,g_kk_h);     cudaGetSymbolAddress((void**)&kk_l,g_kk_l);
    cudaGetSymbolAddress((void**)&kvc,g_kvc);
    cudaGetSymbolAddress((void**)&kkT_h,g_kkT_h);   cudaGetSymbolAddress((void**)&kkT_l,g_kkT_l);
    cudaGetSymbolAddress((void**)&qf,g_q);
    cudaGetSymbolAddress((void**)&q_h,g_q_h);
    cudaGetSymbolAddress((void**)&qq_h,g_qq_h);
    cudaGetSymbolAddress((void**)&sc,g_sc);
    cudaGetSymbolAddress((void**)&p_h,g_p_h);
    cudaGetSymbolAddress((void**)&ctx_h,g_ctx_h);
    cudaGetSymbolAddress((void**)&attn_h,g_attn_h);

    cudaFuncSetAttribute(gemm_tc, cudaFuncAttributeMaxDynamicSharedMemorySize, SMEM_T);
    const float scale = 1.0f / sqrtf((float)QKD);

    // conversions
    cvt_h<<<TOK*HID/2048, 256>>>(hidden, hid_h);
    cvt_hl<<<QLR*HID/2048, 256>>>(w_qa, wqa_h, wqa_l);
    cvt_hl<<<EFFD*HID/2048, 256>>>(w_kva, wkva_h, wkva_l);
    cvt_hl<<<NH*QKD*QLR/2048, 256>>>(w_qb, wqb_h, wqb_l);
    cvt_hl<<<HID*HID/2048, 256>>>(w_o, wo_h, wo_l);
    tcvt<<<dim3(KVLR/32, NOPE/32, NH), 256>>>(w_uk, KVLR, (ll)NOPE*KVLR, wukT_h, wukT_l, NOPE, (ll)KVLR*NOPE);
    tcvt<<<dim3(VD/32, KVLR/32, NH), 256>>>(w_uv, VD, (ll)KVLR*VD, wuvT_h, wuvT_l, KVLR, (ll)VD*KVLR);

    // 1) qa_raw = hidden @ w_qa^T  (f32)
    gemm_tc<<<dim3(QLR/BN, TOK/BM, 1), 256, SMEM_T>>>(
        hid_h, HID, 0, 0,  wqa_h, wqa_l, HID, 0, 0,
        qa_raw, 0, QLR, 0, 0,  HID, 1.f, 0, 1, 0);
    // 2) kva_raw = hidden @ w_kva^T  (f32)
    gemm_tc<<<dim3(EFFD/BN, TOK/BM, 1), 256, SMEM_T>>>(
        hid_h, HID, 0, 0,  wkva_h, wkva_l, HID, 0, 0,
        kva_raw, 0, EFFD, 0, 0,  HID, 1.f, 0, 1, 0);
    // 3) LN + k_pe rope
    ln_rope_k<<<TOK, 256>>>(qa_raw, kva_raw, qln, kln, cosb, sinb,
                            qaln_h, kk_h, kk_l, kvc);
    // kv_c^T per batch for ctx GEMM
    tcvt<<<dim3(KVLR/32, SQ/32, 2), 256>>>(kvc, KVLR, (ll)SQ*KVLR, kkT_h, kkT_l, SQ, (ll)KVLR*SQ);
    // 4) q = qa_ln @ w_qb^T  (f32)
    gemm_tc<<<dim3(NH*QKD/BN, TOK/BM, 1), 256, SMEM_T>>>(
        qaln_h, QLR, 0, 0,  wqb_h, wqb_l, QLR, 0, 0,
        qf, 0, NH*QKD, 0, 0,  QLR, 1.f, 0, 1, 0);
    cvt_h<<<TOK*NH*QKD/2048, 256>>>(qf, q_h);
    qrope_k<<<TOK, 256>>>(qf, cosb, sinb, qq_h);
    // 6) q_lat[h] = q_nope[h] @ wukT[h]^T -> qq[...,0:512]
    gemm_tc<<<dim3(KVLR/BN, TOK/BM, NH), 256, SMEM_T>>>(
        q_h, NH*QKD, 0, QKD,  wukT_h, wukT_l, NOPE, 0, (ll)KVLR*NOPE,
        0, qq_h, QSTR, 0, EFFD,  NOPE, 1.f, 0, NH, 1);
    // 7) scores = qq @ kk^T * scale, causal skip  (f32)
    gemm_tc<<<dim3(SQ/BN, SQ/BM, 2*NH), 256, SMEM_T>>>(
        qq_h, QSTR, (ll)SQ*QSTR, EFFD,
        kk_h, kk_l, EFFD, (ll)SQ*EFFD, 0,
        sc, 0, SQ, (ll)NH*SQ*SQ, (ll)SQ*SQ,  EFFD, scale, 1, NH, 0);
    // 8) softmax -> p fp16
    softmax_k<<<dim3(SQ, 2*NH), 128>>>(sc, p_h);
    // 9) ctx = p @ kv_c  (causal K-limit), fp16 out
    gemm_tc<<<dim3(KVLR/BN, SQ/BM, 2*NH), 256, SMEM_T>>>(
        p_h, SQ, (ll)NH*SQ*SQ, (ll)SQ*SQ,
        kkT_h, kkT_l, SQ, (ll)KVLR*SQ, 0,
        0, ctx_h, CTXLD, (ll)SQ*CTXLD, KVLR,  SQ, 1.f, 2, NH, 1);
    // 10) attn[h] = ctx[h] @ wuvT[h]^T, fp16 out
    gemm_tc<<<dim3(VD/BN, TOK/BM, NH), 256, SMEM_T>>>(
        ctx_h, CTXLD, 0, KVLR,  wuvT_h, wuvT_l, KVLR, 0, (ll)VD*KVLR,
        0, attn_h, HID, 0, VD,  KVLR, 1.f, 0, NH, 1);
    // 11) out = attn @ w_o^T  (f32)
    gemm_tc<<<dim3(HID/BN, TOK/BM, 1), 256, SMEM_T>>>(
        attn_h, HID, 0, 0,  wo_h, wo_l, HID, 0, 0,
        out, 0, HID, 0, 0,  HID, 1.f, 0, 1, 0);
}

// round 10
// speedup vs baseline: 4.8207x; 1.2361x over previous
#include <cuda_runtime.h>
#include <cuda_fp16.h>
#include <math.h>
#include <stdint.h>

#define TOK   2048
#define HID   2048
#define QLR   1536
#define KVLR  512
#define ROPE  64
#define NH    16
#define QKD   192
#define NOPE  128
#define VD    128
#define SQ    1024
#define EFFD  576
#define KD2   3072   // NH*QKD

#define LSCALE 1024.0f
#define LINV   0.0009765625f

typedef __half hf;
typedef long long ll;

// ---------------- scratch ----------------
__device__ __align__(16) hf g_hid_h[TOK*HID];
__device__ __align__(16) hf g_wqa_h[QLR*HID],       g_wqa_l[QLR*HID];
__device__ __align__(16) hf g_wkva_h[EFFD*HID],     g_wkva_l[EFFD*HID];
__device__ __align__(16) hf g_wqb_h[NH*QKD*QLR],    g_wqb_l[NH*QKD*QLR];
__device__ __align__(16) hf g_wo_h[HID*HID],        g_wo_l[HID*HID];
__device__ __align__(16) hf g_wuk_h[NH*NOPE*KVLR],  g_wuk_l[NH*NOPE*KVLR];
__device__ __align__(16) hf g_wuvT_h[NH*VD*KVLR],   g_wuvT_l[NH*VD*KVLR];
__device__ __align__(16) float g_qa_raw[TOK*QLR];
__device__ __align__(16) float g_kva_raw[TOK*EFFD];
__device__ __align__(16) hf g_qaln_h[TOK*QLR];
__device__ __align__(16) hf g_kk_h[TOK*EFFD],       g_kk_l[TOK*EFFD];
__device__ __align__(16) float g_q[TOK*KD2];
__device__ __align__(16) hf g_q_h[TOK*KD2];
__device__ __align__(16) hf g_kk2_h[TOK*KD2],       g_kk2_l[TOK*KD2];
__device__ __align__(16) hf g_vT_h[2*NH*VD*SQ],     g_vT_l[2*NH*VD*SQ];
__device__ __align__(16) float g_sc[33554432];
__device__ __align__(16) hf g_p_h[33554432];
__device__ __align__(16) hf g_attn_h[TOK*HID];

__device__ __forceinline__ uint32_t smem_u32(const void* p) {
    uint32_t a;
    asm("{ .reg .u64 t; cvta.to.shared.u64 t, %1; cvt.u32.u64 %0, t; }" : "=r"(a) : "l"(p));
    return a;
}
// split: h = fp16(v), l = fp16((v - h) * 1024)   (scaled to dodge subnormal flush)
__device__ __forceinline__ void split_hl(float v, unsigned short& h, unsigned short& l) {
    hf hh = __float2half_rn(v);
    float r = (v - __half2float(hh)) * LSCALE;
    hf ll2 = __float2half_rn(r);
    h = __half_as_ushort(hh); l = __half_as_ushort(ll2);
}

#define LDMX4(r, a) \
    asm volatile("ldmatrix.sync.aligned.m8n8.x4.shared.b16 {%0,%1,%2,%3}, [%4];" \
        : "=r"((r)[0]), "=r"((r)[1]), "=r"((r)[2]), "=r"((r)[3]) : "r"(a))

__device__ __forceinline__ void mma_f16(float* d, const uint32_t* a, const uint32_t* b) {
    asm volatile("mma.sync.aligned.m16n8k16.row.col.f32.f16.f16.f32 "
        "{%0,%1,%2,%3}, {%4,%5,%6,%7}, {%8,%9}, {%0,%1,%2,%3};"
        : "+f"(d[0]), "+f"(d[1]), "+f"(d[2]), "+f"(d[3])
        : "r"(a[0]), "r"(a[1]), "r"(a[2]), "r"(a[3]), "r"(b[0]), "r"(b[1]));
}

// ---- fp16 2-MMA GEMM: C[m,n] = alpha * sum_k A[m,k]*B[n,k] ----
// A: single fp16. B: fp16 hi + scaled lo (x1024). Dual fp32 accumulators.
// mode 0 plain, 1 causal tile-skip, 2 causal K-limit.
// outmode 0: f32 C; 1: fp16 Ch; 2: fp16 hi/lo (Ch, Cl).
#define BM 128
#define BN 64
#define BK 64
#define SKP 72
#define OFF_BH 18432
#define OFF_BL 27648
#define STAGE_B 36864
#define SMEM_T (3*STAGE_B)

__global__ __launch_bounds__(256) void gemm_tc(
    const hf* __restrict__ Ah, int lda, ll sAb, ll sAh,
    const hf* __restrict__ Bh, const hf* __restrict__ Bl, int ldb, ll sBb, ll sBh,
    float* __restrict__ C, hf* __restrict__ Ch, hf* __restrict__ Cl,
    int ldc, ll sCb, ll sCh, int K, float alpha, int mode, int zdiv, int outmode)
{
    extern __shared__ char sm[];
    int z = blockIdx.z, zb = z / zdiv, zh = z - zb * zdiv;
    int m0 = blockIdx.y * BM, n0 = blockIdx.x * BN;
    if (mode == 1 && n0 > m0 + (BM - 1)) return;
    int Kend = (mode == 2) ? min(K, m0 + BM) : K;
    int NIT = Kend / BK;

    Ah += zb * sAb + zh * sAh;
    Bh += zb * sBb + zh * sBh;  Bl += zb * sBb + zh * sBh;

    int tid = threadIdx.x, lane = tid & 31, wid = tid >> 5;
    int wm = wid & 3, wn = wid >> 2;           // 4 x 2 warp grid, warp tile 32x32
    uint32_t sb = smem_u32(sm);

    auto load_stage = [&](int it, int s) {
        int k0 = it * BK;
        uint32_t st = sb + s * STAGE_B;
#pragma unroll
        for (int q = 0; q < 8; q++) {
            int g = q * 256 + tid;
            const hf* gp; uint32_t sa;
            if (g < 1024) {                       // A: 128 rows x 8 chunks of 16B
                int row = g >> 3, kc = g & 7;
                gp = Ah + (ll)(m0 + row) * lda + k0 + kc * 8;
                sa = st + (row * SKP + kc * 8) * 2;
            } else if (g < 1536) {                // B hi: 64 rows x 8 chunks
                int idx = g - 1024;
                int row = idx >> 3, kc = idx & 7;
                gp = Bh + (ll)(n0 + row) * ldb + k0 + kc * 8;
                sa = st + OFF_BH + (row * SKP + kc * 8) * 2;
            } else {                              // B lo: 64 rows x 8 chunks
                int idx = g - 1536;
                int row = idx >> 3, kc = idx & 7;
                gp = Bl + (ll)(n0 + row) * ldb + k0 + kc * 8;
                sa = st + OFF_BL + (row * SKP + kc * 8) * 2;
            }
            asm volatile("cp.async.cg.shared.global [%0], [%1], 16;" :: "r"(sa), "l"(gp));
        }
        asm volatile("cp.async.commit_group;" ::: "memory");
    };

    float acc1[2][4][4], acc2[2][4][4];
#pragma unroll
    for (int i = 0; i < 2; i++)
#pragma unroll
        for (int j = 0; j < 4; j++)
#pragma unroll
            for (int k = 0; k < 4; k++) { acc1[i][j][k] = 0.f; acc2[i][j][k] = 0.f; }

    load_stage(0, 0);
    if (NIT > 1) load_stage(1, 1);
    for (int it = 0; it < NIT; it++) {
        if (it + 2 < NIT) {
            load_stage(it + 2, (it + 2) % 3);
            asm volatile("cp.async.wait_group 2;" ::: "memory");
        } else if (it + 1 < NIT) {
            asm volatile("cp.async.wait_group 1;" ::: "memory");
        } else {
            asm volatile("cp.async.wait_group 0;" ::: "memory");
        }
        __syncthreads();

        uint32_t st = sb + (it % 3) * STAGE_B;
#pragma unroll
        for (int ks = 0; ks < 4; ks++) {
            uint32_t Af[2][4];
#pragma unroll
            for (int mt = 0; mt < 2; mt++) {
                int row = wm * 32 + mt * 16 + (lane & 15);
                uint32_t col = ks * 16 + (lane >> 4) * 8;
                LDMX4(Af[mt], st + (row * SKP + col) * 2);
            }
            uint32_t Bhf[4][2], Blf[4][2];
#pragma unroll
            for (int g2 = 0; g2 < 2; g2++) {
                int grp = lane >> 3;
                int nrow = wn * 32 + g2 * 16 + (grp >> 1) * 8 + (lane & 7);
                uint32_t col = ks * 16 + (grp & 1) * 8;
                uint32_t a = st + OFF_BH + (nrow * SKP + col) * 2;
                LDMX4(&Bhf[g2 * 2][0], a);
                LDMX4(&Blf[g2 * 2][0], a + (OFF_BL - OFF_BH));
            }
#pragma unroll
            for (int mt = 0; mt < 2; mt++)
#pragma unroll
                for (int nt = 0; nt < 4; nt++) {
                    mma_f16(acc1[mt][nt], Af[mt], Bhf[nt]);
                    mma_f16(acc2[mt][nt], Af[mt], Blf[nt]);
                }
        }
        __syncthreads();
    }

    // epilogue: v = (acc1 + acc2/1024) * alpha
    int rbase = m0 + wm * 32 + (lane >> 2);
    int cbase = n0 + wn * 32 + (lane & 3) * 2;
    if (outmode == 0) {
        float* Cz = C + zb * sCb + zh * sCh;
#pragma unroll
        for (int mt = 0; mt < 2; mt++)
#pragma unroll
            for (int nt = 0; nt < 4; nt++) {
                int r = rbase + mt * 16, c = cbase + nt * 8;
#pragma unroll
                for (int h2 = 0; h2 < 2; h2++) {
                    int rr = r + h2 * 8;
                    float v0 = fmaf(acc2[mt][nt][h2*2+0], LINV, acc1[mt][nt][h2*2+0]) * alpha;
                    float v1 = fmaf(acc2[mt][nt][h2*2+1], LINV, acc1[mt][nt][h2*2+1]) * alpha;
                    *reinterpret_cast<float2*>(&Cz[(ll)rr * ldc + c]) = make_float2(v0, v1);
                }
            }
    } else if (outmode == 1) {
        hf* Chz = Ch + zb * sCb + zh * sCh;
#pragma unroll
        for (int mt = 0; mt < 2; mt++)
#pragma unroll
            for (int nt = 0; nt < 4; nt++) {
                int r = rbase + mt * 16, c = cbase + nt * 8;
#pragma unroll
                for (int h2 = 0; h2 < 2; h2++) {
                    int rr = r + h2 * 8;
                    float v0 = fmaf(acc2[mt][nt][h2*2+0], LINV, acc1[mt][nt][h2*2+0]) * alpha;
                    float v1 = fmaf(acc2[mt][nt][h2*2+1], LINV, acc1[mt][nt][h2*2+1]) * alpha;
                    uint32_t pk = (uint32_t)__half_as_ushort(__float2half_rn(v0))
                                | ((uint32_t)__half_as_ushort(__float2half_rn(v1)) << 16);
                    *reinterpret_cast<uint32_t*>(&Chz[(ll)rr * ldc + c]) = pk;
                }
            }
    } else {
        hf* Chz = Ch + zb * sCb + zh * sCh;
        hf* Clz = Cl + zb * sCb + zh * sCh;
#pragma unroll
        for (int mt = 0; mt < 2; mt++)
#pragma unroll
            for (int nt = 0; nt < 4; nt++) {
                int r = rbase + mt * 16, c = cbase + nt * 8;
#pragma unroll
                for (int h2 = 0; h2 < 2; h2++) {
                    int rr = r + h2 * 8;
                    float v0 = fmaf(acc2[mt][nt][h2*2+0], LINV, acc1[mt][nt][h2*2+0]) * alpha;
                    float v1 = fmaf(acc2[mt][nt][h2*2+1], LINV, acc1[mt][nt][h2*2+1]) * alpha;
                    unsigned short h0, l0, h1, l1;
                    split_hl(v0, h0, l0);
                    split_hl(v1, h1, l1);
                    *reinterpret_cast<uint32_t*>(&Chz[(ll)rr * ldc + c]) =
                        (uint32_t)h0 | ((uint32_t)h1 << 16);
                    *reinterpret_cast<uint32_t*>(&Clz[(ll)rr * ldc + c]) =
                        (uint32_t)l0 | ((uint32_t)l1 << 16);
                }
            }
    }
}

// ---- f32 -> fp16 (hi only) ----
__global__ __launch_bounds__(256) void cvt_h(const float* __restrict__ s, hf* __restrict__ h) {
    ll i = ((ll)blockIdx.x * 256 + threadIdx.x) * 8;
    float4 a = *reinterpret_cast<const float4*>(s + i);
    float4 b = *reinterpret_cast<const float4*>(s + i + 4);
    float v[8] = {a.x, a.y, a.z, a.w, b.x, b.y, b.z, b.w};
    unsigned short hs[8];
#pragma unroll
    for (int j = 0; j < 8; j++) hs[j] = __half_as_ushort(__float2half_rn(v[j]));
    uint4 hv;
    hv.x = hs[0] | ((uint32_t)hs[1] << 16); hv.y = hs[2] | ((uint32_t)hs[3] << 16);
    hv.z = hs[4] | ((uint32_t)hs[5] << 16); hv.w = hs[6] | ((uint32_t)hs[7] << 16);
    *reinterpret_cast<uint4*>(h + i) = hv;
}

// ---- f32 -> fp16 hi + scaled lo ----
__global__ __launch_bounds__(256) void cvt_hl(const float* __restrict__ s,
                                              hf* __restrict__ h, hf* __restrict__ l) {
    ll i = ((ll)blockIdx.x * 256 + threadIdx.x) * 8;
    float4 a = *reinterpret_cast<const float4*>(s + i);
    float4 b = *reinterpret_cast<const float4*>(s + i + 4);
    float v[8] = {a.x, a.y, a.z, a.w, b.x, b.y, b.z, b.w};
    unsigned short hs[8], ls[8];
#pragma unroll
    for (int j = 0; j < 8; j++) split_hl(v[j], hs[j], ls[j]);
    uint4 hv, lv;
    hv.x = hs[0] | ((uint32_t)hs[1] << 16); hv.y = hs[2] | ((uint32_t)hs[3] << 16);
    hv.z = hs[4] | ((uint32_t)hs[5] << 16); hv.w = hs[6] | ((uint32_t)hs[7] << 16);
    lv.x = ls[0] | ((uint32_t)ls[1] << 16); lv.y = ls[2] | ((uint32_t)ls[3] << 16);
    lv.z = ls[4] | ((uint32_t)ls[5] << 16); lv.w = ls[6] | ((uint32_t)ls[7] << 16);
    *reinterpret_cast<uint4*>(h + i) = hv;
    *reinterpret_cast<uint4*>(l + i) = lv;
}

// ---- transpose + convert: src (RxC) -> dst (CxR) hi + scaled lo ----
__global__ __launch_bounds__(256) void tcvt(const float* __restrict__ s, int lds, ll sz,
                                            hf* __restrict__ dh, hf* __restrict__ dl,
                                            int ldd, ll dz) {
    __shared__ float t[32][33];
    s += (ll)blockIdx.z * sz;  dh += (ll)blockIdx.z * dz;  dl += (ll)blockIdx.z * dz;
    int r0 = blockIdx.y * 32, c0 = blockIdx.x * 32;
    int tx = threadIdx.x & 31, ty = threadIdx.x >> 5;
#pragma unroll
    for (int i = 0; i < 32; i += 8)
        t[ty + i][tx] = s[(ll)(r0 + ty + i) * lds + c0 + tx];
    __syncthreads();
#pragma unroll
    for (int i = 0; i < 32; i += 8) {
        unsigned short hh, ll2;
        split_hl(t[tx][ty + i], hh, ll2);
        ll o = (ll)(c0 + ty + i) * ldd + r0 + tx;
        dh[o] = __ushort_as_half(hh);
        dl[o] = __ushort_as_half(ll2);
    }
}

// ---- dual LN + k_pe rope ----
__global__ __launch_bounds__(256) void ln_rope_k(
    const float* __restrict__ qa_raw, const float* __restrict__ kva_raw,
    const float* __restrict__ qw, const float* __restrict__ kw,
    const float* __restrict__ cosb, const float* __restrict__ sinb,
    hf* __restrict__ qh, hf* __restrict__ kh, hf* __restrict__ kl)
{
    int t = blockIdx.x, tid = threadIdx.x;
    __shared__ float r1[256], r2[256];
    const float* row = qa_raw + (ll)t * QLR;
    float s = 0.f, s2 = 0.f;
    for (int i = tid; i < QLR; i += 256) { float v = row[i]; s += v; s2 += v * v; }
    r1[tid] = s; r2[tid] = s2; __syncthreads();
    for (int o = 128; o > 0; o >>= 1) { if (tid < o) { r1[tid] += r1[tid+o]; r2[tid] += r2[tid+o]; } __syncthreads(); }
    float mean = r1[0] * (1.f / QLR);
    float rs = rsqrtf(r2[0] * (1.f / QLR) - mean * mean + 1e-5f);
    for (int i = tid; i < QLR; i += 256)
        qh[(ll)t * QLR + i] = __float2half_rn((row[i] - mean) * rs * qw[i]);
    __syncthreads();
    const float* krow = kva_raw + (ll)t * EFFD;
    s = 0.f; s2 = 0.f;
    for (int i = tid; i < KVLR; i += 256) { float v = krow[i]; s += v; s2 += v * v; }
    r1[tid] = s; r2[tid] = s2; __syncthreads();
    for (int o = 128; o > 0; o >>= 1) { if (tid < o) { r1[tid] += r1[tid+o]; r2[tid] += r2[tid+o]; } __syncthreads(); }
    mean = r1[0] * (1.f / KVLR);
    rs = rsqrtf(r2[0] * (1.f / KVLR) - mean * mean + 1e-5f);
    for (int i = tid; i < KVLR; i += 256) {
        float v = (krow[i] - mean) * rs * kw[i];
        unsigned short hh, ll2; split_hl(v, hh, ll2);
        kh[(ll)t * EFFD + i] = __ushort_as_half(hh);
        kl[(ll)t * EFFD + i] = __ushort_as_half(ll2);
    }
    if (tid < ROPE) {
        int i = tid;
        float x = krow[KVLR + i];
        float rot = (i < 32) ? -krow[KVLR + i + 32] : krow[KVLR + i - 32];
        float v = x * cosb[(ll)t * ROPE + i] + rot * sinb[(ll)t * ROPE + i];
        unsigned short hh, ll2; split_hl(v, hh, ll2);
        kh[(ll)t * EFFD + KVLR + i] = __ushort_as_half(hh);
        kl[(ll)t * EFFD + KVLR + i] = __ushort_as_half(ll2);
    }
}

// ---- q_pe rope, written in-place into q_h[..., h*QKD+NOPE..] ----
__global__ __launch_bounds__(256) void qrope_k(
    const float* __restrict__ q, const float* __restrict__ cosb,
    const float* __restrict__ sinb, hf* __restrict__ qh)
{
    int t = blockIdx.x, tid = threadIdx.x;
    for (int idx = tid; idx < NH * ROPE; idx += 256) {
        int h = idx >> 6, i = idx & 63;
        const float* qp = q + (ll)t * KD2 + h * QKD + NOPE;
        float x = qp[i];
        float rot = (i < 32) ? -qp[i + 32] : qp[i - 32];
        float v = x * cosb[(ll)t * ROPE + i] + rot * sinb[(ll)t * ROPE + i];
        qh[(ll)t * KD2 + h * QKD + NOPE + i] = __float2half_rn(v);
    }
}

// ---- replicate k_pe hi/lo into kk2[t, h*QKD+NOPE..] for all heads ----
__global__ __launch_bounds__(256) void kpe_rep(
    const hf* __restrict__ kh, const hf* __restrict__ kl,
    hf* __restrict__ k2h, hf* __restrict__ k2l)
{
    int t = blockIdx.x, tid = threadIdx.x;
    for (int idx = tid; idx < NH * ROPE; idx += 256) {
        int h = idx >> 6, i = idx & 63;
        ll src = (ll)t * EFFD + KVLR + i;
        ll dst = (ll)t * KD2 + h * QKD + NOPE + i;
        k2h[dst] = kh[src];
        k2l[dst] = kl[src];
    }
}

// ---- causal softmax -> fp16 p, zero-filled to 128-tile boundary ----
__global__ __launch_bounds__(128) void softmax_k(
    const float* __restrict__ sc, hf* __restrict__ ph)
{
    int q = blockIdx.x, bh = blockIdx.y;
    ll ob = ((ll)bh * SQ + q) * SQ;
    const float* row = sc + ob;
    int n = q + 1, tid = threadIdx.x;
    float v[8]; int cnt = 0; float mx = -3.4e38f;
    for (int k = tid; k < n; k += 128) { float x = row[k]; v[cnt++] = x; mx = fmaxf(mx, x); }
    __shared__ float red[128];
    red[tid] = mx; __syncthreads();
    for (int o = 64; o > 0; o >>= 1) { if (tid < o) red[tid] = fmaxf(red[tid], red[tid+o]); __syncthreads(); }
    mx = red[0]; __syncthreads();
    float sum = 0.f;
    for (int c = 0; c < cnt; c++) { float e = __expf(v[c] - mx); v[c] = e; sum += e; }
    red[tid] = sum; __syncthreads();
    for (int o = 64; o > 0; o >>= 1) { if (tid < o) red[tid] += red[tid+o]; __syncthreads(); }
    float inv = 1.f / red[0];
    cnt = 0;
    for (int k = tid; k < n; k += 128) ph[ob + k] = __float2half_rn(v[cnt++] * inv);
    int zend = ((q >> 7) + 1) << 7;
    hf z0 = __float2half_rn(0.f);
    for (int k = n + tid; k < zend; k += 128) ph[ob + k] = z0;
}

extern "C" void kernel_launch(void* const* d_in, const int* in_sizes, int n_in,
                              void* d_out, int out_size)
{
    const float* hidden = (const float*)d_in[0];
    const float* cosb   = (const float*)d_in[1];
    const float* sinb   = (const float*)d_in[2];
    const float* w_qa   = (const float*)d_in[3];
    const float* qln    = (const float*)d_in[4];
    const float* w_qb   = (const float*)d_in[5];
    const float* w_kva  = (const float*)d_in[6];
    const float* kln    = (const float*)d_in[7];
    const float* w_uk   = (const float*)d_in[8];
    const float* w_uv   = (const float*)d_in[9];
    const float* w_o    = (const float*)d_in[10];
    float* out = (float*)d_out;

    hf *hid_h,*wqa_h,*wqa_l,*wkva_h,*wkva_l,*wqb_h,*wqb_l,*wo_h,*wo_l;
    hf *wuk_h,*wuk_l,*wuvT_h,*wuvT_l,*qaln_h,*kk_h,*kk_l;
    hf *q_h,*kk2_h,*kk2_l,*vT_h,*vT_l,*p_h,*attn_h;
    float *qa_raw,*kva_raw,*qf,*sc;
    cudaGetSymbolAddress((void**)&hid_h,g_hid_h);
    cudaGetSymbolAddress((void**)&wqa_h,g_wqa_h);   cudaGetSymbolAddress((void**)&wqa_l,g_wqa_l);
    cudaGetSymbolAddress((void**)&wkva_h,g_wkva_h); cudaGetSymbolAddress((void**)&wkva_l,g_wkva_l);
    cudaGetSymbolAddress((void**)&wqb_h,g_wqb_h);   cudaGetSymbolAddress((void**)&wqb_l,g_wqb_l);
    cudaGetSymbolAddress((void**)&wo_h,g_wo_h);     cudaGetSymbolAddress((void**)&wo_l,g_wo_l);
    cudaGetSymbolAddress((void**)&wuk_h,g_wuk_h);   cudaGetSymbolAddress((void**)&wuk_l,g_wuk_l);
    cudaGetSymbolAddress((void**)&wuvT_h,g_wuvT_h); cudaGetSymbolAddress((void**)&wuvT_l,g_wuvT_l);
    cudaGetSymbolAddress((void**)&qa_raw,g_qa_raw); cudaGetSymbolAddress((void**)&kva_raw,g_kva_raw);
    cudaGetSymbolAddress((void**)&qaln_h,g_qaln_h);
    cudaGetSymbolAddress((void**)&kk_h,g_kk_h);     cudaGetSymbolAddress((void**)&kk_l,g_kk_l);
    cudaGetSymbolAddress((void**)&qf,g_q);
    cudaGetSymbolAddress((void**)&q_h,g_q_h);
    cudaGetSymbolAddress((void**)&kk2_h,g_kk2_h);   cudaGetSymbolAddress((void**)&kk2_l,g_kk2_l);
    cudaGetSymbolAddress((void**)&vT_h,g_vT_h);     cudaGetSymbolAddress((void**)&vT_l,g_vT_l);
    cudaGetSymbolAddress((void**)&sc,g_sc);
    cudaGetSymbolAddress((void**)&p_h,g_p_h);
    cudaGetSymbolAddress((void**)&attn_h,g_attn_h);

    cudaFuncSetAttribute(gemm_tc, cudaFuncAttributeMaxDynamicSharedMemorySize, SMEM_T);
    const float scale = 1.0f / sqrtf((float)QKD);

    // conversions
    cvt_h<<<TOK*HID/2048, 256>>>(hidden, hid_h);
    cvt_hl<<<QLR*HID/2048, 256>>>(w_qa, wqa_h, wqa_l);
    cvt_hl<<<EFFD*HID/2048, 256>>>(w_kva, wkva_h, wkva_l);
    cvt_hl<<<NH*QKD*QLR/2048, 256>>>(w_qb, wqb_h, wqb_l);
    cvt_hl<<<HID*HID/2048, 256>>>(w_o, wo_h, wo_l);
    cvt_hl<<<NH*NOPE*KVLR/2048, 256>>>(w_uk, wuk_h, wuk_l);   // W_UK_T is k-contiguous already
    tcvt<<<dim3(VD/32, KVLR/32, NH), 256>>>(w_uv, VD, (ll)KVLR*VD, wuvT_h, wuvT_l, KVLR, (ll)VD*KVLR);

    // 1) qa_raw = hidden @ w_qa^T  (f32)
    gemm_tc<<<dim3(QLR/BN, TOK/BM, 1), 256, SMEM_T>>>(
        hid_h, HID, 0, 0,  wqa_h, wqa_l, HID, 0, 0,
        qa_raw, 0, 0, QLR, 0, 0,  HID, 1.f, 0, 1, 0);
    // 2) kva_raw = hidden @ w_kva^T  (f32)
    gemm_tc<<<dim3(EFFD/BN, TOK/BM, 1), 256, SMEM_T>>>(
        hid_h, HID, 0, 0,  wkva_h, wkva_l, HID, 0, 0,
        kva_raw, 0, 0, EFFD, 0, 0,  HID, 1.f, 0, 1, 0);
    // 3) LN + k_pe rope -> qaln_h, kk_h/l (kv_c | roped k_pe)
    ln_rope_k<<<TOK, 256>>>(qa_raw, kva_raw, qln, kln, cosb, sinb,
                            qaln_h, kk_h, kk_l);
    // 4) q = qa_ln @ w_qb^T  (f32), then cvt + rope in place
    gemm_tc<<<dim3(KD2/BN, TOK/BM, 1), 256, SMEM_T>>>(
        qaln_h, QLR, 0, 0,  wqb_h, wqb_l, QLR, 0, 0,
        qf, 0, 0, KD2, 0, 0,  QLR, 1.f, 0, 1, 0);
    cvt_h<<<TOK*KD2/2048, 256>>>(qf, q_h);
    qrope_k<<<TOK, 256>>>(qf, cosb, sinb, q_h);
    // 5) k decompress: kk2[t, h*192+0:128] = kv_c[t] @ W_UK_T[h]^T  (hi/lo out)
    gemm_tc<<<dim3(NOPE/BN, TOK/BM, NH), 256, SMEM_T>>>(
        kk_h, EFFD, 0, 0,  wuk_h, wuk_l, KVLR, 0, (ll)NOPE*KVLR,
        0, kk2_h, kk2_l, KD2, 0, QKD,  KVLR, 1.f, 0, NH, 2);
    // 6) replicate roped k_pe into kk2[..., 128:192] per head
    kpe_rep<<<TOK, 256>>>(kk_h, kk_l, kk2_h, kk2_l);
    // 7) v decompress (transposed): vT[b,h][dv, s] = W_UV^T[h] @ kv_c[b]^T  (hi/lo out)
    gemm_tc<<<dim3(SQ/BN, VD/BM, 2*NH), 256, SMEM_T>>>(
        wuvT_h, KVLR, 0, (ll)VD*KVLR,
        kk_h, kk_l, EFFD, (ll)SQ*EFFD, 0,
        0, vT_h, vT_l, SQ, (ll)NH*VD*SQ, (ll)VD*SQ,  KVLR, 1.f, 0, NH, 2);
    // 8) scores = q @ k^T * scale over K=192, causal skip  (f32)
    gemm_tc<<<dim3(SQ/BN, SQ/BM, 2*NH), 256, SMEM_T>>>(
        q_h, KD2, (ll)SQ*KD2, QKD,
        kk2_h, kk2_l, KD2, (ll)SQ*KD2, QKD,
        sc, 0, 0, SQ, (ll)NH*SQ*SQ, (ll)SQ*SQ,  QKD, scale, 1, NH, 0);
    // 9) softmax -> p fp16
    softmax_k<<<dim3(SQ, 2*NH), 128>>>(sc, p_h);
    // 10) attn = p @ v  (causal K-limit), fp16 out -> attn_h[t, h*VD..]
    gemm_tc<<<dim3(VD/BN, SQ/BM, 2*NH), 256, SMEM_T>>>(
        p_h, SQ, (ll)NH*SQ*SQ, (ll)SQ*SQ,
        vT_h, vT_l, SQ, (ll)NH*VD*SQ, (ll)VD*SQ,
        0, attn_h, 0, HID, (ll)SQ*HID, VD,  SQ, 1.f, 2, NH, 1);
    // 11) out = attn @ w_o^T  (f32)
    gemm_tc<<<dim3(HID/BN, TOK/BM, 1), 256, SMEM_T>>>(
        attn_h, HID, 0, 0,  wo_h, wo_l, HID, 0, 0,
        out, 0, 0, HID, 0, 0,  HID, 1.f, 0, 1, 0);
}

// round 12
// speedup vs baseline: 6.5939x; 1.3678x over previous
#include <cuda_runtime.h>
#include <cuda_fp16.h>
#include <math.h>
#include <stdint.h>

#define TOK   2048
#define HID   2048
#define QLR   1536
#define KVLR  512
#define ROPE  64
#define NH    16
#define QKD   192
#define NOPE  128
#define VD    128
#define SQ    1024
#define EFFD  576
#define KD2   3072   // NH*QKD

typedef __half hf;
typedef long long ll;

// ---------------- scratch (fp16 hi only everywhere) ----------------
__device__ __align__(16) hf g_hid_h[TOK*HID];
__device__ __align__(16) hf g_wqa_h[QLR*HID];
__device__ __align__(16) hf g_wkva_h[EFFD*HID];
__device__ __align__(16) hf g_wqb_h[NH*QKD*QLR];
__device__ __align__(16) hf g_wo_h[HID*HID];
__device__ __align__(16) hf g_wuk_h[NH*NOPE*KVLR];
__device__ __align__(16) hf g_wuvT_h[NH*VD*KVLR];
__device__ __align__(16) float g_qa_raw[TOK*QLR];
__device__ __align__(16) float g_kva_raw[TOK*EFFD];
__device__ __align__(16) hf g_qaln_h[TOK*QLR];
__device__ __align__(16) hf g_kk_h[TOK*EFFD];
__device__ __align__(16) float g_q[TOK*KD2];
__device__ __align__(16) hf g_q_h[TOK*KD2];
__device__ __align__(16) hf g_kk2_h[TOK*KD2];
__device__ __align__(16) hf g_vT_h[2*NH*VD*SQ];
__device__ __align__(16) float g_sc[33554432];
__device__ __align__(16) hf g_p_h[33554432];
__device__ __align__(16) hf g_attn_h[TOK*HID];

__device__ __forceinline__ uint32_t smem_u32(const void* p) {
    uint32_t a;
    asm("{ .reg .u64 t; cvta.to.shared.u64 t, %1; cvt.u32.u64 %0, t; }" : "=r"(a) : "l"(p));
    return a;
}

#define LDMX4(r, a) \
    asm volatile("ldmatrix.sync.aligned.m8n8.x4.shared.b16 {%0,%1,%2,%3}, [%4];" \
        : "=r"((r)[0]), "=r"((r)[1]), "=r"((r)[2]), "=r"((r)[3]) : "r"(a))

__device__ __forceinline__ void mma_f16(float* d, const uint32_t* a, const uint32_t* b) {
    asm volatile("mma.sync.aligned.m16n8k16.row.col.f32.f16.f16.f32 "
        "{%0,%1,%2,%3}, {%4,%5,%6,%7}, {%8,%9}, {%0,%1,%2,%3};"
        : "+f"(d[0]), "+f"(d[1]), "+f"(d[2]), "+f"(d[3])
        : "r"(a[0]), "r"(a[1]), "r"(a[2]), "r"(a[3]), "r"(b[0]), "r"(b[1]));
}

// ---- fp16 single-MMA GEMM: C[m,n] = alpha * sum_k A[m,k]*B[n,k] ----
// mode 0 plain, 1 causal tile-skip, 2 causal K-limit.
// outmode 0: f32 C; 1: fp16 Ch.
#define BM 128
#define BN 64
#define BK 64
#define SKP 72
#define OFF_B 18432
#define STAGE_B 27648
#define SMEM_T (3*STAGE_B)

__global__ __launch_bounds__(256) void gemm_tc(
    const hf* __restrict__ Ah, int lda, ll sAb, ll sAh,
    const hf* __restrict__ Bh, int ldb, ll sBb, ll sBh,
    float* __restrict__ C, hf* __restrict__ Ch,
    int ldc, ll sCb, ll sCh, int K, float alpha, int mode, int zdiv, int outmode)
{
    extern __shared__ char sm[];
    int z = blockIdx.z, zb = z / zdiv, zh = z - zb * zdiv;
    int m0 = blockIdx.y * BM, n0 = blockIdx.x * BN;
    if (mode == 1 && n0 > m0 + (BM - 1)) return;
    int Kend = (mode == 2) ? min(K, m0 + BM) : K;
    int NIT = Kend / BK;

    Ah += zb * sAb + zh * sAh;
    Bh += zb * sBb + zh * sBh;

    int tid = threadIdx.x, lane = tid & 31, wid = tid >> 5;
    int wm = wid & 3, wn = wid >> 2;           // 4 x 2 warp grid, warp tile 32x32
    uint32_t sb = smem_u32(sm);

    auto load_stage = [&](int it, int s) {
        int k0 = it * BK;
        uint32_t st = sb + s * STAGE_B;
#pragma unroll
        for (int q = 0; q < 6; q++) {
            int g = q * 256 + tid;
            const hf* gp; uint32_t sa;
            if (g < 1024) {                       // A: 128 rows x 8 chunks of 16B
                int row = g >> 3, kc = g & 7;
                gp = Ah + (ll)(m0 + row) * lda + k0 + kc * 8;
                sa = st + (row * SKP + kc * 8) * 2;
            } else {                              // B: 64 rows x 8 chunks
                int idx = g - 1024;
                int row = idx >> 3, kc = idx & 7;
                gp = Bh + (ll)(n0 + row) * ldb + k0 + kc * 8;
                sa = st + OFF_B + (row * SKP + kc * 8) * 2;
            }
            asm volatile("cp.async.cg.shared.global [%0], [%1], 16;" :: "r"(sa), "l"(gp));
        }
        asm volatile("cp.async.commit_group;" ::: "memory");
    };

    float acc[2][4][4];
#pragma unroll
    for (int i = 0; i < 2; i++)
#pragma unroll
        for (int j = 0; j < 4; j++)
#pragma unroll
            for (int k = 0; k < 4; k++) acc[i][j][k] = 0.f;

    load_stage(0, 0);
    if (NIT > 1) load_stage(1, 1);
    for (int it = 0; it < NIT; it++) {
        if (it + 2 < NIT) {
            load_stage(it + 2, (it + 2) % 3);
            asm volatile("cp.async.wait_group 2;" ::: "memory");
        } else if (it + 1 < NIT) {
            asm volatile("cp.async.wait_group 1;" ::: "memory");
        } else {
            asm volatile("cp.async.wait_group 0;" ::: "memory");
        }
        __syncthreads();

        uint32_t st = sb + (it % 3) * STAGE_B;
#pragma unroll
        for (int ks = 0; ks < 4; ks++) {
            uint32_t Af[2][4];
#pragma unroll
            for (int mt = 0; mt < 2; mt++) {
                int row = wm * 32 + mt * 16 + (lane & 15);
                uint32_t col = ks * 16 + (lane >> 4) * 8;
                LDMX4(Af[mt], st + (row * SKP + col) * 2);
            }
            uint32_t Bf[4][2];
#pragma unroll
            for (int g2 = 0; g2 < 2; g2++) {
                int grp = lane >> 3;
                int nrow = wn * 32 + g2 * 16 + (grp >> 1) * 8 + (lane & 7);
                uint32_t col = ks * 16 + (grp & 1) * 8;
                LDMX4(&Bf[g2 * 2][0], st + OFF_B + (nrow * SKP + col) * 2);
            }
#pragma unroll
            for (int mt = 0; mt < 2; mt++)
#pragma unroll
                for (int nt = 0; nt < 4; nt++)
                    mma_f16(acc[mt][nt], Af[mt], Bf[nt]);
        }
        __syncthreads();
    }

    // epilogue
    int rbase = m0 + wm * 32 + (lane >> 2);
    int cbase = n0 + wn * 32 + (lane & 3) * 2;
    if (outmode == 0) {
        float* Cz = C + zb * sCb + zh * sCh;
#pragma unroll
        for (int mt = 0; mt < 2; mt++)
#pragma unroll
            for (int nt = 0; nt < 4; nt++) {
                int r = rbase + mt * 16, c = cbase + nt * 8;
#pragma unroll
                for (int h2 = 0; h2 < 2; h2++) {
                    int rr = r + h2 * 8;
                    float v0 = acc[mt][nt][h2*2+0] * alpha;
                    float v1 = acc[mt][nt][h2*2+1] * alpha;
                    *reinterpret_cast<float2*>(&Cz[(ll)rr * ldc + c]) = make_float2(v0, v1);
                }
            }
    } else {
        hf* Chz = Ch + zb * sCb + zh * sCh;
#pragma unroll
        for (int mt = 0; mt < 2; mt++)
#pragma unroll
            for (int nt = 0; nt < 4; nt++) {
                int r = rbase + mt * 16, c = cbase + nt * 8;
#pragma unroll
                for (int h2 = 0; h2 < 2; h2++) {
                    int rr = r + h2 * 8;
                    float v0 = acc[mt][nt][h2*2+0] * alpha;
                    float v1 = acc[mt][nt][h2*2+1] * alpha;
                    uint32_t pk = (uint32_t)__half_as_ushort(__float2half_rn(v0))
                                | ((uint32_t)__half_as_ushort(__float2half_rn(v1)) << 16);
                    *reinterpret_cast<uint32_t*>(&Chz[(ll)rr * ldc + c]) = pk;
                }
            }
    }
}

// ---- f32 -> fp16 ----
__global__ __launch_bounds__(256) void cvt_h(const float* __restrict__ s, hf* __restrict__ h) {
    ll i = ((ll)blockIdx.x * 256 + threadIdx.x) * 8;
    float4 a = *reinterpret_cast<const float4*>(s + i);
    float4 b = *reinterpret_cast<const float4*>(s + i + 4);
    float v[8] = {a.x, a.y, a.z, a.w, b.x, b.y, b.z, b.w};
    unsigned short hs[8];
#pragma unroll
    for (int j = 0; j < 8; j++) hs[j] = __half_as_ushort(__float2half_rn(v[j]));
    uint4 hv;
    hv.x = hs[0] | ((uint32_t)hs[1] << 16); hv.y = hs[2] | ((uint32_t)hs[3] << 16);
    hv.z = hs[4] | ((uint32_t)hs[5] << 16); hv.w = hs[6] | ((uint32_t)hs[7] << 16);
    *reinterpret_cast<uint4*>(h + i) = hv;
}

// ---- transpose + convert: src (RxC) -> dst (CxR) fp16 ----
__global__ __launch_bounds__(256) void tcvt(const float* __restrict__ s, int lds, ll sz,
                                            hf* __restrict__ dh, int ldd, ll dz) {
    __shared__ float t[32][33];
    s += (ll)blockIdx.z * sz;  dh += (ll)blockIdx.z * dz;
    int r0 = blockIdx.y * 32, c0 = blockIdx.x * 32;
    int tx = threadIdx.x & 31, ty = threadIdx.x >> 5;
#pragma unroll
    for (int i = 0; i < 32; i += 8)
        t[ty + i][tx] = s[(ll)(r0 + ty + i) * lds + c0 + tx];
    __syncthreads();
#pragma unroll
    for (int i = 0; i < 32; i += 8)
        dh[(ll)(c0 + ty + i) * ldd + r0 + tx] = __float2half_rn(t[tx][ty + i]);
}

// ---- dual LN + k_pe rope ----
__global__ __launch_bounds__(256) void ln_rope_k(
    const float* __restrict__ qa_raw, const float* __restrict__ kva_raw,
    const float* __restrict__ qw, const float* __restrict__ kw,
    const float* __restrict__ cosb, const float* __restrict__ sinb,
    hf* __restrict__ qh, hf* __restrict__ kh)
{
    int t = blockIdx.x, tid = threadIdx.x;
    __shared__ float r1[256], r2[256];
    const float* row = qa_raw + (ll)t * QLR;
    float s = 0.f, s2 = 0.f;
    for (int i = tid; i < QLR; i += 256) { float v = row[i]; s += v; s2 += v * v; }
    r1[tid] = s; r2[tid] = s2; __syncthreads();
    for (int o = 128; o > 0; o >>= 1) { if (tid < o) { r1[tid] += r1[tid+o]; r2[tid] += r2[tid+o]; } __syncthreads(); }
    float mean = r1[0] * (1.f / QLR);
    float rs = rsqrtf(r2[0] * (1.f / QLR) - mean * mean + 1e-5f);
    for (int i = tid; i < QLR; i += 256)
        qh[(ll)t * QLR + i] = __float2half_rn((row[i] - mean) * rs * qw[i]);
    __syncthreads();
    const float* krow = kva_raw + (ll)t * EFFD;
    s = 0.f; s2 = 0.f;
    for (int i = tid; i < KVLR; i += 256) { float v = krow[i]; s += v; s2 += v * v; }
    r1[tid] = s; r2[tid] = s2; __syncthreads();
    for (int o = 128; o > 0; o >>= 1) { if (tid < o) { r1[tid] += r1[tid+o]; r2[tid] += r2[tid+o]; } __syncthreads(); }
    mean = r1[0] * (1.f / KVLR);
    rs = rsqrtf(r2[0] * (1.f / KVLR) - mean * mean + 1e-5f);
    for (int i = tid; i < KVLR; i += 256)
        kh[(ll)t * EFFD + i] = __float2half_rn((krow[i] - mean) * rs * kw[i]);
    if (tid < ROPE) {
        int i = tid;
        float x = krow[KVLR + i];
        float rot = (i < 32) ? -krow[KVLR + i + 32] : krow[KVLR + i - 32];
        float v = x * cosb[(ll)t * ROPE + i] + rot * sinb[(ll)t * ROPE + i];
        kh[(ll)t * EFFD + KVLR + i] = __float2half_rn(v);
    }
}

// ---- q_pe rope, written in-place into q_h[..., h*QKD+NOPE..] ----
__global__ __launch_bounds__(256) void qrope_k(
    const float* __restrict__ q, const float* __restrict__ cosb,
    const float* __restrict__ sinb, hf* __restrict__ qh)
{
    int t = blockIdx.x, tid = threadIdx.x;
    for (int idx = tid; idx < NH * ROPE; idx += 256) {
        int h = idx >> 6, i = idx & 63;
        const float* qp = q + (ll)t * KD2 + h * QKD + NOPE;
        float x = qp[i];
        float rot = (i < 32) ? -qp[i + 32] : qp[i - 32];
        float v = x * cosb[(ll)t * ROPE + i] + rot * sinb[(ll)t * ROPE + i];
        qh[(ll)t * KD2 + h * QKD + NOPE + i] = __float2half_rn(v);
    }
}

// ---- replicate roped k_pe into kk2[t, h*QKD+NOPE..] for all heads ----
__global__ __launch_bounds__(256) void kpe_rep(
    const hf* __restrict__ kh, hf* __restrict__ k2h)
{
    int t = blockIdx.x, tid = threadIdx.x;
    for (int idx = tid; idx < NH * ROPE; idx += 256) {
        int h = idx >> 6, i = idx & 63;
        k2h[(ll)t * KD2 + h * QKD + NOPE + i] = kh[(ll)t * EFFD + KVLR + i];
    }
}

// ---- causal softmax -> fp16 p, zero-filled to 128-tile boundary ----
__global__ __launch_bounds__(128) void softmax_k(
    const float* __restrict__ sc, hf* __restrict__ ph)
{
    int q = blockIdx.x, bh = blockIdx.y;
    ll ob = ((ll)bh * SQ + q) * SQ;
    const float* row = sc + ob;
    int n = q + 1, tid = threadIdx.x;
    float v[8]; int cnt = 0; float mx = -3.4e38f;
    for (int k = tid; k < n; k += 128) { float x = row[k]; v[cnt++] = x; mx = fmaxf(mx, x); }
    __shared__ float red[128];
    red[tid] = mx; __syncthreads();
    for (int o = 64; o > 0; o >>= 1) { if (tid < o) red[tid] = fmaxf(red[tid], red[tid+o]); __syncthreads(); }
    mx = red[0]; __syncthreads();
    float sum = 0.f;
    for (int c = 0; c < cnt; c++) { float e = __expf(v[c] - mx); v[c] = e; sum += e; }
    red[tid] = sum; __syncthreads();
    for (int o = 64; o > 0; o >>= 1) { if (tid < o) red[tid] += red[tid+o]; __syncthreads(); }
    float inv = 1.f / red[0];
    cnt = 0;
    for (int k = tid; k < n; k += 128) ph[ob + k] = __float2half_rn(v[cnt++] * inv);
    int zend = ((q >> 7) + 1) << 7;
    hf z0 = __float2half_rn(0.f);
    for (int k = n + tid; k < zend; k += 128) ph[ob + k] = z0;
}

extern "C" void kernel_launch(void* const* d_in, const int* in_sizes, int n_in,
                              void* d_out, int out_size)
{
    const float* hidden = (const float*)d_in[0];
    const float* cosb   = (const float*)d_in[1];
    const float* sinb   = (const float*)d_in[2];
    const float* w_qa   = (const float*)d_in[3];
    const float* qln    = (const float*)d_in[4];
    const float* w_qb   = (const float*)d_in[5];
    const float* w_kva  = (const float*)d_in[6];
    const float* kln    = (const float*)d_in[7];
    const float* w_uk   = (const float*)d_in[8];
    const float* w_uv   = (const float*)d_in[9];
    const float* w_o    = (const float*)d_in[10];
    float* out = (float*)d_out;

    hf *hid_h,*wqa_h,*wkva_h,*wqb_h,*wo_h,*wuk_h,*wuvT_h,*qaln_h,*kk_h;
    hf *q_h,*kk2_h,*vT_h,*p_h,*attn_h;
    float *qa_raw,*kva_raw,*qf,*sc;
    cudaGetSymbolAddress((void**)&hid_h,g_hid_h);
    cudaGetSymbolAddress((void**)&wqa_h,g_wqa_h);
    cudaGetSymbolAddress((void**)&wkva_h,g_wkva_h);
    cudaGetSymbolAddress((void**)&wqb_h,g_wqb_h);
    cudaGetSymbolAddress((void**)&wo_h,g_wo_h);
    cudaGetSymbolAddress((void**)&wuk_h,g_wuk_h);
    cudaGetSymbolAddress((void**)&wuvT_h,g_wuvT_h);
    cudaGetSymbolAddress((void**)&qa_raw,g_qa_raw);
    cudaGetSymbolAddress((void**)&kva_raw,g_kva_raw);
    cudaGetSymbolAddress((void**)&qaln_h,g_qaln_h);
    cudaGetSymbolAddress((void**)&kk_h,g_kk_h);
    cudaGetSymbolAddress((void**)&qf,g_q);
    cudaGetSymbolAddress((void**)&q_h,g_q_h);
    cudaGetSymbolAddress((void**)&kk2_h,g_kk2_h);
    cudaGetSymbolAddress((void**)&vT_h,g_vT_h);
    cudaGetSymbolAddress((void**)&sc,g_sc);
    cudaGetSymbolAddress((void**)&p_h,g_p_h);
    cudaGetSymbolAddress((void**)&attn_h,g_attn_h);

    cudaFuncSetAttribute(gemm_tc, cudaFuncAttributeMaxDynamicSharedMemorySize, SMEM_T);
    const float scale = 1.0f / sqrtf((float)QKD);

    // conversions (all fp16 hi only)
    cvt_h<<<TOK*HID/2048, 256>>>(hidden, hid_h);
    cvt_h<<<QLR*HID/2048, 256>>>(w_qa, wqa_h);
    cvt_h<<<EFFD*HID/2048, 256>>>(w_kva, wkva_h);
    cvt_h<<<NH*QKD*QLR/2048, 256>>>(w_qb, wqb_h);
    cvt_h<<<HID*HID/2048, 256>>>(w_o, wo_h);
    cvt_h<<<NH*NOPE*KVLR/2048, 256>>>(w_uk, wuk_h);   // W_UK_T already k-contiguous
    tcvt<<<dim3(VD/32, KVLR/32, NH), 256>>>(w_uv, VD, (ll)KVLR*VD, wuvT_h, KVLR, (ll)VD*KVLR);

    // 1) qa_raw = hidden @ w_qa^T  (f32)
    gemm_tc<<<dim3(QLR/BN, TOK/BM, 1), 256, SMEM_T>>>(
        hid_h, HID, 0, 0,  wqa_h, HID, 0, 0,
        qa_raw, 0, QLR, 0, 0,  HID, 1.f, 0, 1, 0);
    // 2) kva_raw = hidden @ w_kva^T  (f32)
    gemm_tc<<<dim3(EFFD/BN, TOK/BM, 1), 256, SMEM_T>>>(
        hid_h, HID, 0, 0,  wkva_h, HID, 0, 0,
        kva_raw, 0, EFFD, 0, 0,  HID, 1.f, 0, 1, 0);
    // 3) LN + k_pe rope -> qaln_h, kk_h (kv_c | roped k_pe)
    ln_rope_k<<<TOK, 256>>>(qa_raw, kva_raw, qln, kln, cosb, sinb, qaln_h, kk_h);
    // 4) q = qa_ln @ w_qb^T  (f32), then cvt + rope in place
    gemm_tc<<<dim3(KD2/BN, TOK/BM, 1), 256, SMEM_T>>>(
        qaln_h, QLR, 0, 0,  wqb_h, QLR, 0, 0,
        qf, 0, KD2, 0, 0,  QLR, 1.f, 0, 1, 0);
    cvt_h<<<TOK*KD2/2048, 256>>>(qf, q_h);
    qrope_k<<<TOK, 256>>>(qf, cosb, sinb, q_h);
    // 5) k decompress: kk2[t, h*192+0:128] = kv_c[t] @ W_UK_T[h]^T
    gemm_tc<<<dim3(NOPE/BN, TOK/BM, NH), 256, SMEM_T>>>(
        kk_h, EFFD, 0, 0,  wuk_h, KVLR, 0, (ll)NOPE*KVLR,
        0, kk2_h, KD2, 0, QKD,  KVLR, 1.f, 0, NH, 1);
    // 6) replicate roped k_pe into kk2[..., 128:192] per head
    kpe_rep<<<TOK, 256>>>(kk_h, kk2_h);
    // 7) v decompress (transposed): vT[b,h][dv, s] = W_UV^T[h] @ kv_c[b]^T
    gemm_tc<<<dim3(SQ/BN, VD/BM, 2*NH), 256, SMEM_T>>>(
        wuvT_h, KVLR, 0, (ll)VD*KVLR,
        kk_h, EFFD, (ll)SQ*EFFD, 0,
        0, vT_h, SQ, (ll)NH*VD*SQ, (ll)VD*SQ,  KVLR, 1.f, 0, NH, 1);
    // 8) scores = q @ k^T * scale over K=192, causal skip  (f32)
    gemm_tc<<<dim3(SQ/BN, SQ/BM, 2*NH), 256, SMEM_T>>>(
        q_h, KD2, (ll)SQ*KD2, QKD,
        kk2_h, KD2, (ll)SQ*KD2, QKD,
        sc, 0, SQ, (ll)NH*SQ*SQ, (ll)SQ*SQ,  QKD, scale, 1, NH, 0);
    // 9) softmax -> p fp16
    softmax_k<<<dim3(SQ, 2*NH), 128>>>(sc, p_h);
    // 10) attn = p @ v  (causal K-limit), fp16 out -> attn_h[t, h*VD..]
    gemm_tc<<<dim3(VD/BN, SQ/BM, 2*NH), 256, SMEM_T>>>(
        p_h, SQ, (ll)NH*SQ*SQ, (ll)SQ*SQ,
        vT_h, SQ, (ll)NH*VD*SQ, (ll)VD*SQ,
        0, attn_h, HID, (ll)SQ*HID, VD,  SQ, 1.f, 2, NH, 1);
    // 11) out = attn @ w_o^T  (f32)
    gemm_tc<<<dim3(HID/BN, TOK/BM, 1), 256, SMEM_T>>>(
        attn_h, HID, 0, 0,  wo_h, HID, 0, 0,
        out, 0, HID, 0, 0,  HID, 1.f, 0, 1, 0);
}

// round 14
// speedup vs baseline: 6.7590x; 1.0250x over previous
#include <cuda_runtime.h>
#include <cuda_fp16.h>
#include <math.h>
#include <stdint.h>

#define TOK   2048
#define HID   2048
#define QLR   1536
#define KVLR  512
#define ROPE  64
#define NH    16
#define QKD   192
#define NOPE  128
#define VD    128
#define SQ    1024
#define EFFD  576
#define KD2   3072   // NH*QKD
#define QKVN  2112   // QLR + EFFD

typedef __half hf;
typedef long long ll;

// ---------------- scratch (fp16 hi only everywhere) ----------------
__device__ __align__(16) hf g_hid_h[TOK*HID];
__device__ __align__(16) hf g_wqakva_h[QKVN*HID];     // [w_qa ; w_kva]
__device__ __align__(16) hf g_wqb_h[NH*QKD*QLR];
__device__ __align__(16) hf g_wo_h[HID*HID];
__device__ __align__(16) hf g_wuk_h[NH*NOPE*KVLR];
__device__ __align__(16) hf g_wuvT_h[NH*VD*KVLR];
__device__ __align__(16) float g_qakva_raw[TOK*QKVN];
__device__ __align__(16) hf g_qaln_h[TOK*QLR];
__device__ __align__(16) hf g_kk_h[TOK*EFFD];
__device__ __align__(16) float g_q[TOK*KD2];
__device__ __align__(16) hf g_q_h[TOK*KD2];
__device__ __align__(16) hf g_kk2_h[TOK*KD2];
__device__ __align__(16) hf g_vT_h[2*NH*VD*SQ];
__device__ __align__(16) float g_sc[33554432];
__device__ __align__(16) hf g_p_h[33554432];
__device__ __align__(16) hf g_attn_h[TOK*HID];

__device__ __forceinline__ uint32_t smem_u32(const void* p) {
    uint32_t a;
    asm("{ .reg .u64 t; cvta.to.shared.u64 t, %1; cvt.u32.u64 %0, t; }" : "=r"(a) : "l"(p));
    return a;
}

#define LDMX4(r, a) \
    asm volatile("ldmatrix.sync.aligned.m8n8.x4.shared.b16 {%0,%1,%2,%3}, [%4];" \
        : "=r"((r)[0]), "=r"((r)[1]), "=r"((r)[2]), "=r"((r)[3]) : "r"(a))

__device__ __forceinline__ void mma_f16(float* d, const uint32_t* a, const uint32_t* b) {
    asm volatile("mma.sync.aligned.m16n8k16.row.col.f32.f16.f16.f32 "
        "{%0,%1,%2,%3}, {%4,%5,%6,%7}, {%8,%9}, {%0,%1,%2,%3};"
        : "+f"(d[0]), "+f"(d[1]), "+f"(d[2]), "+f"(d[3])
        : "r"(a[0]), "r"(a[1]), "r"(a[2]), "r"(a[3]), "r"(b[0]), "r"(b[1]));
}

// ---- persistent fp16 GEMM: C[m,n] = alpha * sum_k A[m,k]*B[n,k] ----
// Tile grid (nx, ny, nz) walked by gridDim.x persistent CTAs.
// mode 0 plain, 1 causal tile-skip, 2 causal K-limit.
// outmode 0: f32 C; 1: fp16 Ch; 3: both.
#define BM 128
#define BN 64
#define BK 64
#define SKP 72
#define OFF_B 18432
#define STAGE_B 27648
#define SMEM_T (3*STAGE_B)
#define NPERS 296

__global__ __launch_bounds__(256) void gemm_tc(
    const hf* __restrict__ A0, int lda, ll sAb, ll sAh,
    const hf* __restrict__ B0, int ldb, ll sBb, ll sBh,
    float* __restrict__ C, hf* __restrict__ Ch,
    int ldc, ll sCb, ll sCh, int K, float alpha, int mode, int zdiv, int outmode,
    int nx, int ny, int nz)
{
    extern __shared__ char sm[];
    int tid = threadIdx.x, lane = tid & 31, wid = tid >> 5;
    int wm = wid & 3, wn = wid >> 2;           // 4 x 2 warp grid, warp tile 32x32
    uint32_t sb = smem_u32(sm);
    int nT = nx * ny * nz;

    for (int t = blockIdx.x; t < nT; t += gridDim.x) {
        int gz = t / (nx * ny);
        int rem = t - gz * nx * ny;
        int gy = rem / nx;
        int gx = rem - gy * nx;
        int m0 = gy * BM, n0 = gx * BN;
        if (mode == 1 && n0 > m0 + (BM - 1)) continue;
        int Kend = (mode == 2) ? min(K, m0 + BM) : K;
        int NIT = Kend / BK;

        int zb = gz / zdiv, zh = gz - zb * zdiv;
        const hf* Ah = A0 + zb * sAb + zh * sAh;
        const hf* Bh = B0 + zb * sBb + zh * sBh;

        auto load_stage = [&](int it, int s) {
            int k0 = it * BK;
            uint32_t st = sb + s * STAGE_B;
#pragma unroll
            for (int q = 0; q < 6; q++) {
                int g = q * 256 + tid;
                const hf* gp; uint32_t sa;
                if (g < 1024) {                       // A: 128 rows x 8 chunks of 16B
                    int row = g >> 3, kc = g & 7;
                    gp = Ah + (ll)(m0 + row) * lda + k0 + kc * 8;
                    sa = st + (row * SKP + kc * 8) * 2;
                } else {                              // B: 64 rows x 8 chunks
                    int idx = g - 1024;
                    int row = idx >> 3, kc = idx & 7;
                    gp = Bh + (ll)(n0 + row) * ldb + k0 + kc * 8;
                    sa = st + OFF_B + (row * SKP + kc * 8) * 2;
                }
                asm volatile("cp.async.cg.shared.global [%0], [%1], 16;" :: "r"(sa), "l"(gp));
            }
            asm volatile("cp.async.commit_group;" ::: "memory");
        };

        float acc[2][4][4];
#pragma unroll
        for (int i = 0; i < 2; i++)
#pragma unroll
            for (int j = 0; j < 4; j++)
#pragma unroll
                for (int k = 0; k < 4; k++) acc[i][j][k] = 0.f;

        load_stage(0, 0);
        if (NIT > 1) load_stage(1, 1);
        for (int it = 0; it < NIT; it++) {
            if (it + 2 < NIT) {
                load_stage(it + 2, (it + 2) % 3);
                asm volatile("cp.async.wait_group 2;" ::: "memory");
            } else if (it + 1 < NIT) {
                asm volatile("cp.async.wait_group 1;" ::: "memory");
            } else {
                asm volatile("cp.async.wait_group 0;" ::: "memory");
            }
            __syncthreads();

            uint32_t st = sb + (it % 3) * STAGE_B;
#pragma unroll
            for (int ks = 0; ks < 4; ks++) {
                uint32_t Af[2][4];
#pragma unroll
                for (int mt = 0; mt < 2; mt++) {
                    int row = wm * 32 + mt * 16 + (lane & 15);
                    uint32_t col = ks * 16 + (lane >> 4) * 8;
                    LDMX4(Af[mt], st + (row * SKP + col) * 2);
                }
                uint32_t Bf[4][2];
#pragma unroll
                for (int g2 = 0; g2 < 2; g2++) {
                    int grp = lane >> 3;
                    int nrow = wn * 32 + g2 * 16 + (grp >> 1) * 8 + (lane & 7);
                    uint32_t col = ks * 16 + (grp & 1) * 8;
                    LDMX4(&Bf[g2 * 2][0], st + OFF_B + (nrow * SKP + col) * 2);
                }
#pragma unroll
                for (int mt = 0; mt < 2; mt++)
#pragma unroll
                    for (int nt = 0; nt < 4; nt++)
                        mma_f16(acc[mt][nt], Af[mt], Bf[nt]);
            }
            __syncthreads();
        }

        // epilogue
        int rbase = m0 + wm * 32 + (lane >> 2);
        int cbase = n0 + wn * 32 + (lane & 3) * 2;
        if (outmode != 1) {
            float* Cz = C + zb * sCb + zh * sCh;
#pragma unroll
            for (int mt = 0; mt < 2; mt++)
#pragma unroll
                for (int nt = 0; nt < 4; nt++) {
                    int r = rbase + mt * 16, c = cbase + nt * 8;
#pragma unroll
                    for (int h2 = 0; h2 < 2; h2++) {
                        int rr = r + h2 * 8;
                        float v0 = acc[mt][nt][h2*2+0] * alpha;
                        float v1 = acc[mt][nt][h2*2+1] * alpha;
                        *reinterpret_cast<float2*>(&Cz[(ll)rr * ldc + c]) = make_float2(v0, v1);
                    }
                }
        }
        if (outmode != 0) {
            hf* Chz = Ch + zb * sCb + zh * sCh;
#pragma unroll
            for (int mt = 0; mt < 2; mt++)
#pragma unroll
                for (int nt = 0; nt < 4; nt++) {
                    int r = rbase + mt * 16, c = cbase + nt * 8;
#pragma unroll
                    for (int h2 = 0; h2 < 2; h2++) {
                        int rr = r + h2 * 8;
                        float v0 = acc[mt][nt][h2*2+0] * alpha;
                        float v1 = acc[mt][nt][h2*2+1] * alpha;
                        uint32_t pk = (uint32_t)__half_as_ushort(__float2half_rn(v0))
                                    | ((uint32_t)__half_as_ushort(__float2half_rn(v1)) << 16);
                        *reinterpret_cast<uint32_t*>(&Chz[(ll)rr * ldc + c]) = pk;
                    }
                }
        }
    }
}

// ---- f32 -> fp16 ----
__global__ __launch_bounds__(256) void cvt_h(const float* __restrict__ s, hf* __restrict__ h) {
    ll i = ((ll)blockIdx.x * 256 + threadIdx.x) * 8;
    float4 a = *reinterpret_cast<const float4*>(s + i);
    float4 b = *reinterpret_cast<const float4*>(s + i + 4);
    float v[8] = {a.x, a.y, a.z, a.w, b.x, b.y, b.z, b.w};
    unsigned short hs[8];
#pragma unroll
    for (int j = 0; j < 8; j++) hs[j] = __half_as_ushort(__float2half_rn(v[j]));
    uint4 hv;
    hv.x = hs[0] | ((uint32_t)hs[1] << 16); hv.y = hs[2] | ((uint32_t)hs[3] << 16);
    hv.z = hs[4] | ((uint32_t)hs[5] << 16); hv.w = hs[6] | ((uint32_t)hs[7] << 16);
    *reinterpret_cast<uint4*>(h + i) = hv;
}

// ---- transpose + convert: src (RxC) -> dst (CxR) fp16 ----
__global__ __launch_bounds__(256) void tcvt(const float* __restrict__ s, int lds, ll sz,
                                            hf* __restrict__ dh, int ldd, ll dz) {
    __shared__ float t[32][33];
    s += (ll)blockIdx.z * sz;  dh += (ll)blockIdx.z * dz;
    int r0 = blockIdx.y * 32, c0 = blockIdx.x * 32;
    int tx = threadIdx.x & 31, ty = threadIdx.x >> 5;
#pragma unroll
    for (int i = 0; i < 32; i += 8)
        t[ty + i][tx] = s[(ll)(r0 + ty + i) * lds + c0 + tx];
    __syncthreads();
#pragma unroll
    for (int i = 0; i < 32; i += 8)
        dh[(ll)(c0 + ty + i) * ldd + r0 + tx] = __float2half_rn(t[tx][ty + i]);
}

// ---- dual LN + k_pe rope (reads fused qakva buffer, row stride QKVN) ----
__global__ __launch_bounds__(256) void ln_rope_k(
    const float* __restrict__ qakva,
    const float* __restrict__ qw, const float* __restrict__ kw,
    const float* __restrict__ cosb, const float* __restrict__ sinb,
    hf* __restrict__ qh, hf* __restrict__ kh)
{
    int t = blockIdx.x, tid = threadIdx.x;
    __shared__ float r1[256], r2[256];
    const float* row = qakva + (ll)t * QKVN;
    float s = 0.f, s2 = 0.f;
    for (int i = tid; i < QLR; i += 256) { float v = row[i]; s += v; s2 += v * v; }
    r1[tid] = s; r2[tid] = s2; __syncthreads();
    for (int o = 128; o > 0; o >>= 1) { if (tid < o) { r1[tid] += r1[tid+o]; r2[tid] += r2[tid+o]; } __syncthreads(); }
    float mean = r1[0] * (1.f / QLR);
    float rs = rsqrtf(r2[0] * (1.f / QLR) - mean * mean + 1e-5f);
    for (int i = tid; i < QLR; i += 256)
        qh[(ll)t * QLR + i] = __float2half_rn((row[i] - mean) * rs * qw[i]);
    __syncthreads();
    const float* krow = row + QLR;
    s = 0.f; s2 = 0.f;
    for (int i = tid; i < KVLR; i += 256) { float v = krow[i]; s += v; s2 += v * v; }
    r1[tid] = s; r2[tid] = s2; __syncthreads();
    for (int o = 128; o > 0; o >>= 1) { if (tid < o) { r1[tid] += r1[tid+o]; r2[tid] += r2[tid+o]; } __syncthreads(); }
    mean = r1[0] * (1.f / KVLR);
    rs = rsqrtf(r2[0] * (1.f / KVLR) - mean * mean + 1e-5f);
    for (int i = tid; i < KVLR; i += 256)
        kh[(ll)t * EFFD + i] = __float2half_rn((krow[i] - mean) * rs * kw[i]);
    if (tid < ROPE) {
        int i = tid;
        float x = krow[KVLR + i];
        float rot = (i < 32) ? -krow[KVLR + i + 32] : krow[KVLR + i - 32];
        float v = x * cosb[(ll)t * ROPE + i] + rot * sinb[(ll)t * ROPE + i];
        kh[(ll)t * EFFD + KVLR + i] = __float2half_rn(v);
    }
}

// ---- q_pe rope, written in-place into q_h[..., h*QKD+NOPE..] ----
__global__ __launch_bounds__(256) void qrope_k(
    const float* __restrict__ q, const float* __restrict__ cosb,
    const float* __restrict__ sinb, hf* __restrict__ qh)
{
    int t = blockIdx.x, tid = threadIdx.x;
    for (int idx = tid; idx < NH * ROPE; idx += 256) {
        int h = idx >> 6, i = idx & 63;
        const float* qp = q + (ll)t * KD2 + h * QKD + NOPE;
        float x = qp[i];
        float rot = (i < 32) ? -qp[i + 32] : qp[i - 32];
        float v = x * cosb[(ll)t * ROPE + i] + rot * sinb[(ll)t * ROPE + i];
        qh[(ll)t * KD2 + h * QKD + NOPE + i] = __float2half_rn(v);
    }
}

// ---- replicate roped k_pe into kk2[t, h*QKD+NOPE..] for all heads ----
__global__ __launch_bounds__(256) void kpe_rep(
    const hf* __restrict__ kh, hf* __restrict__ k2h)
{
    int t = blockIdx.x, tid = threadIdx.x;
    for (int idx = tid; idx < NH * ROPE; idx += 256) {
        int h = idx >> 6, i = idx & 63;
        k2h[(ll)t * KD2 + h * QKD + NOPE + i] = kh[(ll)t * EFFD + KVLR + i];
    }
}

// ---- causal softmax -> fp16 p, zero-filled to 128-tile boundary ----
__global__ __launch_bounds__(128) void softmax_k(
    const float* __restrict__ sc, hf* __restrict__ ph)
{
    int q = blockIdx.x, bh = blockIdx.y;
    ll ob = ((ll)bh * SQ + q) * SQ;
    const float* row = sc + ob;
    int n = q + 1, tid = threadIdx.x;
    float v[8]; int cnt = 0; float mx = -3.4e38f;
    for (int k = tid; k < n; k += 128) { float x = row[k]; v[cnt++] = x; mx = fmaxf(mx, x); }
    __shared__ float red[128];
    red[tid] = mx; __syncthreads();
    for (int o = 64; o > 0; o >>= 1) { if (tid < o) red[tid] = fmaxf(red[tid], red[tid+o]); __syncthreads(); }
    mx = red[0]; __syncthreads();
    float sum = 0.f;
    for (int c = 0; c < cnt; c++) { float e = __expf(v[c] - mx); v[c] = e; sum += e; }
    red[tid] = sum; __syncthreads();
    for (int o = 64; o > 0; o >>= 1) { if (tid < o) red[tid] += red[tid+o]; __syncthreads(); }
    float inv = 1.f / red[0];
    cnt = 0;
    for (int k = tid; k < n; k += 128) ph[ob + k] = __float2half_rn(v[cnt++] * inv);
    int zend = ((q >> 7) + 1) << 7;
    hf z0 = __float2half_rn(0.f);
    for (int k = n + tid; k < zend; k += 128) ph[ob + k] = z0;
}

static inline int pgrid(int nx, int ny, int nz) {
    int t = nx * ny * nz;
    return t < NPERS ? t : NPERS;
}

extern "C" void kernel_launch(void* const* d_in, const int* in_sizes, int n_in,
                              void* d_out, int out_size)
{
    const float* hidden = (const float*)d_in[0];
    const float* cosb   = (const float*)d_in[1];
    const float* sinb   = (const float*)d_in[2];
    const float* w_qa   = (const float*)d_in[3];
    const float* qln    = (const float*)d_in[4];
    const float* w_qb   = (const float*)d_in[5];
    const float* w_kva  = (const float*)d_in[6];
    const float* kln    = (const float*)d_in[7];
    const float* w_uk   = (const float*)d_in[8];
    const float* w_uv   = (const float*)d_in[9];
    const float* w_o    = (const float*)d_in[10];
    float* out = (float*)d_out;

    hf *hid_h,*wqakva_h,*wqb_h,*wo_h,*wuk_h,*wuvT_h,*qaln_h,*kk_h;
    hf *q_h,*kk2_h,*vT_h,*p_h,*attn_h;
    float *qakva_raw,*qf,*sc;
    cudaGetSymbolAddress((void**)&hid_h,g_hid_h);
    cudaGetSymbolAddress((void**)&wqakva_h,g_wqakva_h);
    cudaGetSymbolAddress((void**)&wqb_h,g_wqb_h);
    cudaGetSymbolAddress((void**)&wo_h,g_wo_h);
    cudaGetSymbolAddress((void**)&wuk_h,g_wuk_h);
    cudaGetSymbolAddress((void**)&wuvT_h,g_wuvT_h);
    cudaGetSymbolAddress((void**)&qakva_raw,g_qakva_raw);
    cudaGetSymbolAddress((void**)&qaln_h,g_qaln_h);
    cudaGetSymbolAddress((void**)&kk_h,g_kk_h);
    cudaGetSymbolAddress((void**)&qf,g_q);
    cudaGetSymbolAddress((void**)&q_h,g_q_h);
    cudaGetSymbolAddress((void**)&kk2_h,g_kk2_h);
    cudaGetSymbolAddress((void**)&vT_h,g_vT_h);
    cudaGetSymbolAddress((void**)&sc,g_sc);
    cudaGetSymbolAddress((void**)&p_h,g_p_h);
    cudaGetSymbolAddress((void**)&attn_h,g_attn_h);

    cudaFuncSetAttribute(gemm_tc, cudaFuncAttributeMaxDynamicSharedMemorySize, SMEM_T);
    const float scale = 1.0f / sqrtf((float)QKD);

    // conversions (all fp16 hi only)
    cvt_h<<<TOK*HID/2048, 256>>>(hidden, hid_h);
    cvt_h<<<QLR*HID/2048, 256>>>(w_qa, wqakva_h);                 // rows [0, QLR)
    cvt_h<<<EFFD*HID/2048, 256>>>(w_kva, wqakva_h + (ll)QLR*HID); // rows [QLR, QKVN)
    cvt_h<<<NH*QKD*QLR/2048, 256>>>(w_qb, wqb_h);
    cvt_h<<<HID*HID/2048, 256>>>(w_o, wo_h);
    cvt_h<<<NH*NOPE*KVLR/2048, 256>>>(w_uk, wuk_h);   // W_UK_T already k-contiguous
    tcvt<<<dim3(VD/32, KVLR/32, NH), 256>>>(w_uv, VD, (ll)KVLR*VD, wuvT_h, KVLR, (ll)VD*KVLR);

    // 1) qakva_raw = hidden @ [w_qa; w_kva]^T  (f32, fused)
    gemm_tc<<<pgrid(QKVN/BN, TOK/BM, 1), 256, SMEM_T>>>(
        hid_h, HID, 0, 0,  wqakva_h, HID, 0, 0,
        qakva_raw, 0, QKVN, 0, 0,  HID, 1.f, 0, 1, 0,
        QKVN/BN, TOK/BM, 1);
    // 2) LN + k_pe rope -> qaln_h, kk_h (kv_c | roped k_pe)
    ln_rope_k<<<TOK, 256>>>(qakva_raw, qln, kln, cosb, sinb, qaln_h, kk_h);
    // 3) q = qa_ln @ w_qb^T  (dual f32+fp16 out), then rope in place
    gemm_tc<<<pgrid(KD2/BN, TOK/BM, 1), 256, SMEM_T>>>(
        qaln_h, QLR, 0, 0,  wqb_h, QLR, 0, 0,
        qf, q_h, KD2, 0, 0,  QLR, 1.f, 0, 1, 3,
        KD2/BN, TOK/BM, 1);
    qrope_k<<<TOK, 256>>>(qf, cosb, sinb, q_h);
    // 4) k decompress: kk2[t, h*192+0:128] = kv_c[t] @ W_UK_T[h]^T
    gemm_tc<<<pgrid(NOPE/BN, TOK/BM, NH), 256, SMEM_T>>>(
        kk_h, EFFD, 0, 0,  wuk_h, KVLR, 0, (ll)NOPE*KVLR,
        0, kk2_h, KD2, 0, QKD,  KVLR, 1.f, 0, NH, 1,
        NOPE/BN, TOK/BM, NH);
    // 5) replicate roped k_pe into kk2[..., 128:192] per head
    kpe_rep<<<TOK, 256>>>(kk_h, kk2_h);
    // 6) v decompress (transposed): vT[b,h][dv, s] = W_UV^T[h] @ kv_c[b]^T
    gemm_tc<<<pgrid(SQ/BN, VD/BM, 2*NH), 256, SMEM_T>>>(
        wuvT_h, KVLR, 0, (ll)VD*KVLR,
        kk_h, EFFD, (ll)SQ*EFFD, 0,
        0, vT_h, SQ, (ll)NH*VD*SQ, (ll)VD*SQ,  KVLR, 1.f, 0, NH, 1,
        SQ/BN, VD/BM, 2*NH);
    // 7) scores = q @ k^T * scale over K=192, causal skip  (f32)
    gemm_tc<<<pgrid(SQ/BN, SQ/BM, 2*NH), 256, SMEM_T>>>(
        q_h, KD2, (ll)SQ*KD2, QKD,
        kk2_h, KD2, (ll)SQ*KD2, QKD,
        sc, 0, SQ, (ll)NH*SQ*SQ, (ll)SQ*SQ,  QKD, scale, 1, NH, 0,
        SQ/BN, SQ/BM, 2*NH);
    // 8) softmax -> p fp16
    softmax_k<<<dim3(SQ, 2*NH), 128>>>(sc, p_h);
    // 9) attn = p @ v  (causal K-limit), fp16 out -> attn_h[t, h*VD..]
    gemm_tc<<<pgrid(VD/BN, SQ/BM, 2*NH), 256, SMEM_T>>>(
        p_h, SQ, (ll)NH*SQ*SQ, (ll)SQ*SQ,
        vT_h, SQ, (ll)NH*VD*SQ, (ll)VD*SQ,
        0, attn_h, HID, (ll)SQ*HID, VD,  SQ, 1.f, 2, NH, 1,
        VD/BN, SQ/BM, 2*NH);
    // 10) out = attn @ w_o^T  (f32)
    gemm_tc<<<pgrid(HID/BN, TOK/BM, 1), 256, SMEM_T>>>(
        attn_h, HID, 0, 0,  wo_h, HID, 0, 0,
        out, 0, HID, 0, 0,  HID, 1.f, 0, 1, 0,
        HID/BN, TOK/BM, 1);
}

// round 15
// speedup vs baseline: 6.7623x; 1.0005x over previous
#include <cuda_runtime.h>
#include <cuda_fp16.h>
#include <math.h>
#include <stdint.h>

#define TOK   2048
#define HID   2048
#define QLR   1536
#define KVLR  512
#define ROPE  64
#define NH    16
#define QKD   192
#define NOPE  128
#define VD    128
#define SQ    1024
#define EFFD  576
#define KD2   3072   // NH*QKD
#define QKVN  2112   // QLR + EFFD

typedef __half hf;
typedef long long ll;

// ---------------- scratch (fp16 hi only everywhere) ----------------
__device__ __align__(16) hf g_hid_h[TOK*HID];
__device__ __align__(16) hf g_wqakva_h[QKVN*HID];     // [w_qa ; w_kva]
__device__ __align__(16) hf g_wqb_h[NH*QKD*QLR];
__device__ __align__(16) hf g_wo_h[HID*HID];
__device__ __align__(16) hf g_wuk_h[NH*NOPE*KVLR];
__device__ __align__(16) hf g_wuvT_h[NH*VD*KVLR];
__device__ __align__(16) float g_qakva_raw[TOK*QKVN];
__device__ __align__(16) hf g_qaln_h[TOK*QLR];
__device__ __align__(16) hf g_kk_h[TOK*EFFD];
__device__ __align__(16) float g_q[TOK*KD2];
__device__ __align__(16) hf g_q_h[TOK*KD2];
__device__ __align__(16) hf g_kk2_h[TOK*KD2];
__device__ __align__(16) hf g_vT_h[2*NH*VD*SQ];
__device__ __align__(16) hf g_sc_h[33554432];          // fp16 scores
__device__ __align__(16) hf g_p_h[33554432];
__device__ __align__(16) hf g_attn_h[TOK*HID];

__device__ __forceinline__ uint32_t smem_u32(const void* p) {
    uint32_t a;
    asm("{ .reg .u64 t; cvta.to.shared.u64 t, %1; cvt.u32.u64 %0, t; }" : "=r"(a) : "l"(p));
    return a;
}

#define LDMX4(r, a) \
    asm volatile("ldmatrix.sync.aligned.m8n8.x4.shared.b16 {%0,%1,%2,%3}, [%4];" \
        : "=r"((r)[0]), "=r"((r)[1]), "=r"((r)[2]), "=r"((r)[3]) : "r"(a))

__device__ __forceinline__ void mma_f16(float* d, const uint32_t* a, const uint32_t* b) {
    asm volatile("mma.sync.aligned.m16n8k16.row.col.f32.f16.f16.f32 "
        "{%0,%1,%2,%3}, {%4,%5,%6,%7}, {%8,%9}, {%0,%1,%2,%3};"
        : "+f"(d[0]), "+f"(d[1]), "+f"(d[2]), "+f"(d[3])
        : "r"(a[0]), "r"(a[1]), "r"(a[2]), "r"(a[3]), "r"(b[0]), "r"(b[1]));
}

// ---- persistent fp16 GEMM: C[m,n] = alpha * sum_k A[m,k]*B[n,k] ----
// Tile grid walked by gridDim.x persistent CTAs.
// mode 0 plain; mode 1 causal (compact triangular enumeration, nx = tiles/z);
// mode 2 causal K-limit (gy reversed: long tiles first).
// outmode 0: f32 C; 1: fp16 Ch; 3: both.
#define BM 128
#define BN 64
#define BK 64
#define SKP 72
#define OFF_B 18432
#define STAGE_B 27648
#define SMEM_T (3*STAGE_B)
#define NPERS 296

__global__ __launch_bounds__(256) void gemm_tc(
    const hf* __restrict__ A0, int lda, ll sAb, ll sAh,
    const hf* __restrict__ B0, int ldb, ll sBb, ll sBh,
    float* __restrict__ C, hf* __restrict__ Ch,
    int ldc, ll sCb, ll sCh, int K, float alpha, int mode, int zdiv, int outmode,
    int nx, int ny, int nz)
{
    extern __shared__ char sm[];
    int tid = threadIdx.x, lane = tid & 31, wid = tid >> 5;
    int wm = wid & 3, wn = wid >> 2;           // 4 x 2 warp grid, warp tile 32x32
    uint32_t sb = smem_u32(sm);
    int nT = nx * (mode == 1 ? 1 : ny) * nz;

    for (int t = blockIdx.x; t < nT; t += gridDim.x) {
        int gz, gy, gx;
        if (mode == 1) {
            gz = t / nx;
            int idx = t - gz * nx;
            gy = (int)((sqrtf(4.f * idx + 1.f) - 1.f) * 0.5f);
            while ((gy + 1) * (gy + 2) <= idx) gy++;
            while (gy * (gy + 1) > idx) gy--;
            gx = idx - gy * (gy + 1);
        } else {
            gz = t / (nx * ny);
            int rem = t - gz * nx * ny;
            gy = rem / nx;
            gx = rem - gy * nx;
            if (mode == 2) gy = ny - 1 - gy;   // long-K tiles first
        }
        int m0 = gy * BM, n0 = gx * BN;
        int Kend = (mode == 2) ? min(K, m0 + BM) : K;
        int NIT = Kend / BK;

        int zb = gz / zdiv, zh = gz - zb * zdiv;
        const hf* Ah = A0 + zb * sAb + zh * sAh;
        const hf* Bh = B0 + zb * sBb + zh * sBh;

        auto load_stage = [&](int it, int s) {
            int k0 = it * BK;
            uint32_t st = sb + s * STAGE_B;
#pragma unroll
            for (int q = 0; q < 6; q++) {
                int g = q * 256 + tid;
                const hf* gp; uint32_t sa;
                if (g < 1024) {                       // A: 128 rows x 8 chunks of 16B
                    int row = g >> 3, kc = g & 7;
                    gp = Ah + (ll)(m0 + row) * lda + k0 + kc * 8;
                    sa = st + (row * SKP + kc * 8) * 2;
                } else {                              // B: 64 rows x 8 chunks
                    int idx2 = g - 1024;
                    int row = idx2 >> 3, kc = idx2 & 7;
                    gp = Bh + (ll)(n0 + row) * ldb + k0 + kc * 8;
                    sa = st + OFF_B + (row * SKP + kc * 8) * 2;
                }
                asm volatile("cp.async.cg.shared.global [%0], [%1], 16;" :: "r"(sa), "l"(gp));
            }
            asm volatile("cp.async.commit_group;" ::: "memory");
        };

        float acc[2][4][4];
#pragma unroll
        for (int i = 0; i < 2; i++)
#pragma unroll
            for (int j = 0; j < 4; j++)
#pragma unroll
                for (int k = 0; k < 4; k++) acc[i][j][k] = 0.f;

        load_stage(0, 0);
        if (NIT > 1) load_stage(1, 1);
        for (int it = 0; it < NIT; it++) {
            if (it + 2 < NIT) {
                load_stage(it + 2, (it + 2) % 3);
                asm volatile("cp.async.wait_group 2;" ::: "memory");
            } else if (it + 1 < NIT) {
                asm volatile("cp.async.wait_group 1;" ::: "memory");
            } else {
                asm volatile("cp.async.wait_group 0;" ::: "memory");
            }
            __syncthreads();

            uint32_t st = sb + (it % 3) * STAGE_B;
#pragma unroll
            for (int ks = 0; ks < 4; ks++) {
                uint32_t Af[2][4];
#pragma unroll
                for (int mt = 0; mt < 2; mt++) {
                    int row = wm * 32 + mt * 16 + (lane & 15);
                    uint32_t col = ks * 16 + (lane >> 4) * 8;
                    LDMX4(Af[mt], st + (row * SKP + col) * 2);
                }
                uint32_t Bf[4][2];
#pragma unroll
                for (int g2 = 0; g2 < 2; g2++) {
                    int grp = lane >> 3;
                    int nrow = wn * 32 + g2 * 16 + (grp >> 1) * 8 + (lane & 7);
                    uint32_t col = ks * 16 + (grp & 1) * 8;
                    LDMX4(&Bf[g2 * 2][0], st + OFF_B + (nrow * SKP + col) * 2);
                }
#pragma unroll
                for (int mt = 0; mt < 2; mt++)
#pragma unroll
                    for (int nt = 0; nt < 4; nt++)
                        mma_f16(acc[mt][nt], Af[mt], Bf[nt]);
            }
            __syncthreads();
        }

        // epilogue
        int rbase = m0 + wm * 32 + (lane >> 2);
        int cbase = n0 + wn * 32 + (lane & 3) * 2;
        if (outmode != 1) {
            float* Cz = C + zb * sCb + zh * sCh;
#pragma unroll
            for (int mt = 0; mt < 2; mt++)
#pragma unroll
                for (int nt = 0; nt < 4; nt++) {
                    int r = rbase + mt * 16, c = cbase + nt * 8;
#pragma unroll
                    for (int h2 = 0; h2 < 2; h2++) {
                        int rr = r + h2 * 8;
                        float v0 = acc[mt][nt][h2*2+0] * alpha;
                        float v1 = acc[mt][nt][h2*2+1] * alpha;
                        *reinterpret_cast<float2*>(&Cz[(ll)rr * ldc + c]) = make_float2(v0, v1);
                    }
                }
        }
        if (outmode != 0) {
            hf* Chz = Ch + zb * sCb + zh * sCh;
#pragma unroll
            for (int mt = 0; mt < 2; mt++)
#pragma unroll
                for (int nt = 0; nt < 4; nt++) {
                    int r = rbase + mt * 16, c = cbase + nt * 8;
#pragma unroll
                    for (int h2 = 0; h2 < 2; h2++) {
                        int rr = r + h2 * 8;
                        float v0 = acc[mt][nt][h2*2+0] * alpha;
                        float v1 = acc[mt][nt][h2*2+1] * alpha;
                        uint32_t pk = (uint32_t)__half_as_ushort(__float2half_rn(v0))
                                    | ((uint32_t)__half_as_ushort(__float2half_rn(v1)) << 16);
                        *reinterpret_cast<uint32_t*>(&Chz[(ll)rr * ldc + c]) = pk;
                    }
                }
        }
    }
}

// ---- f32 -> fp16 ----
__global__ __launch_bounds__(256) void cvt_h(const float* __restrict__ s, hf* __restrict__ h) {
    ll i = ((ll)blockIdx.x * 256 + threadIdx.x) * 8;
    float4 a = *reinterpret_cast<const float4*>(s + i);
    float4 b = *reinterpret_cast<const float4*>(s + i + 4);
    float v[8] = {a.x, a.y, a.z, a.w, b.x, b.y, b.z, b.w};
    unsigned short hs[8];
#pragma unroll
    for (int j = 0; j < 8; j++) hs[j] = __half_as_ushort(__float2half_rn(v[j]));
    uint4 hv;
    hv.x = hs[0] | ((uint32_t)hs[1] << 16); hv.y = hs[2] | ((uint32_t)hs[3] << 16);
    hv.z = hs[4] | ((uint32_t)hs[5] << 16); hv.w = hs[6] | ((uint32_t)hs[7] << 16);
    *reinterpret_cast<uint4*>(h + i) = hv;
}

// ---- transpose + convert: src (RxC) -> dst (CxR) fp16 ----
__global__ __launch_bounds__(256) void tcvt(const float* __restrict__ s, int lds, ll sz,
                                            hf* __restrict__ dh, int ldd, ll dz) {
    __shared__ float t[32][33];
    s += (ll)blockIdx.z * sz;  dh += (ll)blockIdx.z * dz;
    int r0 = blockIdx.y * 32, c0 = blockIdx.x * 32;
    int tx = threadIdx.x & 31, ty = threadIdx.x >> 5;
#pragma unroll
    for (int i = 0; i < 32; i += 8)
        t[ty + i][tx] = s[(ll)(r0 + ty + i) * lds + c0 + tx];
    __syncthreads();
#pragma unroll
    for (int i = 0; i < 32; i += 8)
        dh[(ll)(c0 + ty + i) * ldd + r0 + tx] = __float2half_rn(t[tx][ty + i]);
}

// ---- dual LN + k_pe rope (reads fused qakva buffer, row stride QKVN) ----
__global__ __launch_bounds__(256) void ln_rope_k(
    const float* __restrict__ qakva,
    const float* __restrict__ qw, const float* __restrict__ kw,
    const float* __restrict__ cosb, const float* __restrict__ sinb,
    hf* __restrict__ qh, hf* __restrict__ kh)
{
    int t = blockIdx.x, tid = threadIdx.x;
    __shared__ float r1[256], r2[256];
    const float* row = qakva + (ll)t * QKVN;
    float s = 0.f, s2 = 0.f;
    for (int i = tid; i < QLR; i += 256) { float v = row[i]; s += v; s2 += v * v; }
    r1[tid] = s; r2[tid] = s2; __syncthreads();
    for (int o = 128; o > 0; o >>= 1) { if (tid < o) { r1[tid] += r1[tid+o]; r2[tid] += r2[tid+o]; } __syncthreads(); }
    float mean = r1[0] * (1.f / QLR);
    float rs = rsqrtf(r2[0] * (1.f / QLR) - mean * mean + 1e-5f);
    for (int i = tid; i < QLR; i += 256)
        qh[(ll)t * QLR + i] = __float2half_rn((row[i] - mean) * rs * qw[i]);
    __syncthreads();
    const float* krow = row + QLR;
    s = 0.f; s2 = 0.f;
    for (int i = tid; i < KVLR; i += 256) { float v = krow[i]; s += v; s2 += v * v; }
    r1[tid] = s; r2[tid] = s2; __syncthreads();
    for (int o = 128; o > 0; o >>= 1) { if (tid < o) { r1[tid] += r1[tid+o]; r2[tid] += r2[tid+o]; } __syncthreads(); }
    mean = r1[0] * (1.f / KVLR);
    rs = rsqrtf(r2[0] * (1.f / KVLR) - mean * mean + 1e-5f);
    for (int i = tid; i < KVLR; i += 256)
        kh[(ll)t * EFFD + i] = __float2half_rn((krow[i] - mean) * rs * kw[i]);
    if (tid < ROPE) {
        int i = tid;
        float x = krow[KVLR + i];
        float rot = (i < 32) ? -krow[KVLR + i + 32] : krow[KVLR + i - 32];
        float v = x * cosb[(ll)t * ROPE + i] + rot * sinb[(ll)t * ROPE + i];
        kh[(ll)t * EFFD + KVLR + i] = __float2half_rn(v);
    }
}

// ---- q_pe rope, written in-place into q_h[..., h*QKD+NOPE..] ----
__global__ __launch_bounds__(256) void qrope_k(
    const float* __restrict__ q, const float* __restrict__ cosb,
    const float* __restrict__ sinb, hf* __restrict__ qh)
{
    int t = blockIdx.x, tid = threadIdx.x;
    for (int idx = tid; idx < NH * ROPE; idx += 256) {
        int h = idx >> 6, i = idx & 63;
        const float* qp = q + (ll)t * KD2 + h * QKD + NOPE;
        float x = qp[i];
        float rot = (i < 32) ? -qp[i + 32] : qp[i - 32];
        float v = x * cosb[(ll)t * ROPE + i] + rot * sinb[(ll)t * ROPE + i];
        qh[(ll)t * KD2 + h * QKD + NOPE + i] = __float2half_rn(v);
    }
}

// ---- replicate roped k_pe into kk2[t, h*QKD+NOPE..] for all heads ----
__global__ __launch_bounds__(256) void kpe_rep(
    const hf* __restrict__ kh, hf* __restrict__ k2h)
{
    int t = blockIdx.x, tid = threadIdx.x;
    for (int idx = tid; idx < NH * ROPE; idx += 256) {
        int h = idx >> 6, i = idx & 63;
        k2h[(ll)t * KD2 + h * QKD + NOPE + i] = kh[(ll)t * EFFD + KVLR + i];
    }
}

// ---- causal softmax (fp16 in) -> fp16 p, zero-filled to 128-tile boundary ----
__global__ __launch_bounds__(128) void softmax_k(
    const hf* __restrict__ sc, hf* __restrict__ ph)
{
    int q = blockIdx.x, bh = blockIdx.y;
    ll ob = ((ll)bh * SQ + q) * SQ;
    const hf* row = sc + ob;
    int n = q + 1, tid = threadIdx.x;
    float v[8]; int cnt = 0; float mx = -3.4e38f;
    for (int k = tid; k < n; k += 128) { float x = __half2float(row[k]); v[cnt++] = x; mx = fmaxf(mx, x); }
    __shared__ float red[128];
    red[tid] = mx; __syncthreads();
    for (int o = 64; o > 0; o >>= 1) { if (tid < o) red[tid] = fmaxf(red[tid], red[tid+o]); __syncthreads(); }
    mx = red[0]; __syncthreads();
    float sum = 0.f;
    for (int c = 0; c < cnt; c++) { float e = __expf(v[c] - mx); v[c] = e; sum += e; }
    red[tid] = sum; __syncthreads();
    for (int o = 64; o > 0; o >>= 1) { if (tid < o) red[tid] += red[tid+o]; __syncthreads(); }
    float inv = 1.f / red[0];
    cnt = 0;
    for (int k = tid; k < n; k += 128) ph[ob + k] = __float2half_rn(v[cnt++] * inv);
    int zend = ((q >> 7) + 1) << 7;
    hf z0 = __float2half_rn(0.f);
    for (int k = n + tid; k < zend; k += 128) ph[ob + k] = z0;
}

static inline int pgrid_n(int t) { return t < NPERS ? t : NPERS; }

extern "C" void kernel_launch(void* const* d_in, const int* in_sizes, int n_in,
                              void* d_out, int out_size)
{
    const float* hidden = (const float*)d_in[0];
    const float* cosb   = (const float*)d_in[1];
    const float* sinb   = (const float*)d_in[2];
    const float* w_qa   = (const float*)d_in[3];
    const float* qln    = (const float*)d_in[4];
    const float* w_qb   = (const float*)d_in[5];
    const float* w_kva  = (const float*)d_in[6];
    const float* kln    = (const float*)d_in[7];
    const float* w_uk   = (const float*)d_in[8];
    const float* w_uv   = (const float*)d_in[9];
    const float* w_o    = (const float*)d_in[10];
    float* out = (float*)d_out;

    hf *hid_h,*wqakva_h,*wqb_h,*wo_h,*wuk_h,*wuvT_h,*qaln_h,*kk_h;
    hf *q_h,*kk2_h,*vT_h,*sc_h,*p_h,*attn_h;
    float *qakva_raw,*qf;
    cudaGetSymbolAddress((void**)&hid_h,g_hid_h);
    cudaGetSymbolAddress((void**)&wqakva_h,g_wqakva_h);
    cudaGetSymbolAddress((void**)&wqb_h,g_wqb_h);
    cudaGetSymbolAddress((void**)&wo_h,g_wo_h);
    cudaGetSymbolAddress((void**)&wuk_h,g_wuk_h);
    cudaGetSymbolAddress((void**)&wuvT_h,g_wuvT_h);
    cudaGetSymbolAddress((void**)&qakva_raw,g_qakva_raw);
    cudaGetSymbolAddress((void**)&qaln_h,g_qaln_h);
    cudaGetSymbolAddress((void**)&kk_h,g_kk_h);
    cudaGetSymbolAddress((void**)&qf,g_q);
    cudaGetSymbolAddress((void**)&q_h,g_q_h);
    cudaGetSymbolAddress((void**)&kk2_h,g_kk2_h);
    cudaGetSymbolAddress((void**)&vT_h,g_vT_h);
    cudaGetSymbolAddress((void**)&sc_h,g_sc_h);
    cudaGetSymbolAddress((void**)&p_h,g_p_h);
    cudaGetSymbolAddress((void**)&attn_h,g_attn_h);

    cudaFuncSetAttribute(gemm_tc, cudaFuncAttributeMaxDynamicSharedMemorySize, SMEM_T);
    const float scale = 1.0f / sqrtf((float)QKD);

    // conversions (all fp16 hi only)
    cvt_h<<<TOK*HID/2048, 256>>>(hidden, hid_h);
    cvt_h<<<QLR*HID/2048, 256>>>(w_qa, wqakva_h);                 // rows [0, QLR)
    cvt_h<<<EFFD*HID/2048, 256>>>(w_kva, wqakva_h + (ll)QLR*HID); // rows [QLR, QKVN)
    cvt_h<<<NH*QKD*QLR/2048, 256>>>(w_qb, wqb_h);
    cvt_h<<<HID*HID/2048, 256>>>(w_o, wo_h);
    cvt_h<<<NH*NOPE*KVLR/2048, 256>>>(w_uk, wuk_h);   // W_UK_T already k-contiguous
    tcvt<<<dim3(VD/32, KVLR/32, NH), 256>>>(w_uv, VD, (ll)KVLR*VD, wuvT_h, KVLR, (ll)VD*KVLR);

    // 1) qakva_raw = hidden @ [w_qa; w_kva]^T  (f32, fused)
    gemm_tc<<<pgrid_n(QKVN/BN * TOK/BM), 256, SMEM_T>>>(
        hid_h, HID, 0, 0,  wqakva_h, HID, 0, 0,
        qakva_raw, 0, QKVN, 0, 0,  HID, 1.f, 0, 1, 0,
        QKVN/BN, TOK/BM, 1);
    // 2) LN + k_pe rope -> qaln_h, kk_h (kv_c | roped k_pe)
    ln_rope_k<<<TOK, 256>>>(qakva_raw, qln, kln, cosb, sinb, qaln_h, kk_h);
    // 3) q = qa_ln @ w_qb^T  (dual f32+fp16 out), then rope in place
    gemm_tc<<<pgrid_n(KD2/BN * TOK/BM), 256, SMEM_T>>>(
        qaln_h, QLR, 0, 0,  wqb_h, QLR, 0, 0,
        qf, q_h, KD2, 0, 0,  QLR, 1.f, 0, 1, 3,
        KD2/BN, TOK/BM, 1);
    qrope_k<<<TOK, 256>>>(qf, cosb, sinb, q_h);
    // 4) k decompress: kk2[t, h*192+0:128] = kv_c[t] @ W_UK_T[h]^T
    gemm_tc<<<pgrid_n(NOPE/BN * TOK/BM * NH), 256, SMEM_T>>>(
        kk_h, EFFD, 0, 0,  wuk_h, KVLR, 0, (ll)NOPE*KVLR,
        0, kk2_h, KD2, 0, QKD,  KVLR, 1.f, 0, NH, 1,
        NOPE/BN, TOK/BM, NH);
    // 5) replicate roped k_pe into kk2[..., 128:192] per head
    kpe_rep<<<TOK, 256>>>(kk_h, kk2_h);
    // 6) v decompress (transposed): vT[b,h][dv, s] = W_UV^T[h] @ kv_c[b]^T
    gemm_tc<<<pgrid_n(SQ/BN * VD/BM * 2*NH), 256, SMEM_T>>>(
        wuvT_h, KVLR, 0, (ll)VD*KVLR,
        kk_h, EFFD, (ll)SQ*EFFD, 0,
        0, vT_h, SQ, (ll)NH*VD*SQ, (ll)VD*SQ,  KVLR, 1.f, 0, NH, 1,
        SQ/BN, VD/BM, 2*NH);
    // 7) scores = q @ k^T * scale over K=192, compact causal tiles, fp16 out
    //    tiles/z = sum over 8 m-rows of (2gy+2) = 72
    gemm_tc<<<pgrid_n(72 * 2*NH), 256, SMEM_T>>>(
        q_h, KD2, (ll)SQ*KD2, QKD,
        kk2_h, KD2, (ll)SQ*KD2, QKD,
        0, sc_h, SQ, (ll)NH*SQ*SQ, (ll)SQ*SQ,  QKD, scale, 1, NH, 1,
        72, SQ/BM, 2*NH);
    // 8) softmax (fp16 in) -> p fp16
    softmax_k<<<dim3(SQ, 2*NH), 128>>>(sc_h, p_h);
    // 9) attn = p @ v  (causal K-limit, long tiles first), fp16 out
    gemm_tc<<<pgrid_n(VD/BN * SQ/BM * 2*NH), 256, SMEM_T>>>(
        p_h, SQ, (ll)NH*SQ*SQ, (ll)SQ*SQ,
        vT_h, SQ, (ll)NH*VD*SQ, (ll)VD*SQ,
        0, attn_h, HID, (ll)SQ*HID, VD,  SQ, 1.f, 2, NH, 1,
        VD/BN, SQ/BM, 2*NH);
    // 10) out = attn @ w_o^T  (f32)
    gemm_tc<<<pgrid_n(HID/BN * TOK/BM), 256, SMEM_T>>>(
        attn_h, HID, 0, 0,  wo_h, HID, 0, 0,
        out, 0, HID, 0, 0,  HID, 1.f, 0, 1, 0,
        HID/BN, TOK/BM, 1);
}

// round 16
// speedup vs baseline: 8.0466x; 1.1899x over previous
#include <cuda_runtime.h>
#include <cuda_fp16.h>
#include <math.h>
#include <stdint.h>

#define TOK   2048
#define HID   2048
#define QLR   1536
#define KVLR  512
#define ROPE  64
#define NH    16
#define QKD   192
#define NOPE  128
#define VD    128
#define SQ    1024
#define EFFD  576
#define KD2   3072   // NH*QKD
#define QKVN  2112   // QLR + EFFD

typedef __half hf;
typedef long long ll;

// ---------------- scratch (fp16 hi only everywhere) ----------------
__device__ __align__(16) hf g_hid_h[TOK*HID];
__device__ __align__(16) hf g_wqakva_h[QKVN*HID];     // [w_qa ; w_kva]
__device__ __align__(16) hf g_wqb_h[NH*QKD*QLR];
__device__ __align__(16) hf g_wo_h[HID*HID];
__device__ __align__(16) hf g_wuk_h[NH*NOPE*KVLR];
__device__ __align__(16) hf g_wuvT_h[NH*VD*KVLR];
__device__ __align__(16) float g_qakva_raw[TOK*QKVN];
__device__ __align__(16) hf g_qaln_h[TOK*QLR];
__device__ __align__(16) hf g_kk_h[TOK*EFFD];
__device__ __align__(16) float g_q[TOK*KD2];
__device__ __align__(16) hf g_q_h[TOK*KD2];
__device__ __align__(16) hf g_kk2_h[TOK*KD2];
__device__ __align__(16) hf g_vT_h[2*NH*VD*SQ];
__device__ __align__(16) hf g_attn_h[TOK*HID];

__device__ __forceinline__ uint32_t smem_u32(const void* p) {
    uint32_t a;
    asm("{ .reg .u64 t; cvta.to.shared.u64 t, %1; cvt.u32.u64 %0, t; }" : "=r"(a) : "l"(p));
    return a;
}

#define LDMX4(r, a) \
    asm volatile("ldmatrix.sync.aligned.m8n8.x4.shared.b16 {%0,%1,%2,%3}, [%4];" \
        : "=r"((r)[0]), "=r"((r)[1]), "=r"((r)[2]), "=r"((r)[3]) : "r"(a))

__device__ __forceinline__ void mma_f16(float* d, const uint32_t* a, const uint32_t* b) {
    asm volatile("mma.sync.aligned.m16n8k16.row.col.f32.f16.f16.f32 "
        "{%0,%1,%2,%3}, {%4,%5,%6,%7}, {%8,%9}, {%0,%1,%2,%3};"
        : "+f"(d[0]), "+f"(d[1]), "+f"(d[2]), "+f"(d[3])
        : "r"(a[0]), "r"(a[1]), "r"(a[2]), "r"(a[3]), "r"(b[0]), "r"(b[1]));
}
#define CPA16(sa, gp) \
    asm volatile("cp.async.cg.shared.global [%0], [%1], 16;" :: "r"(sa), "l"(gp))
#define CPCOMMIT() asm volatile("cp.async.commit_group;" ::: "memory")

// ---- persistent fp16 GEMM (unchanged from round 15, modes 0/2, out 0/1/3) ----
#define BM 128
#define BN 64
#define BK 64
#define SKP 72
#define OFF_B 18432
#define STAGE_B 27648
#define SMEM_T (3*STAGE_B)
#define NPERS 296

__global__ __launch_bounds__(256) void gemm_tc(
    const hf* __restrict__ A0, int lda, ll sAb, ll sAh,
    const hf* __restrict__ B0, int ldb, ll sBb, ll sBh,
    float* __restrict__ C, hf* __restrict__ Ch,
    int ldc, ll sCb, ll sCh, int K, float alpha, int mode, int zdiv, int outmode,
    int nx, int ny, int nz)
{
    extern __shared__ char sm[];
    int tid = threadIdx.x, lane = tid & 31, wid = tid >> 5;
    int wm = wid & 3, wn = wid >> 2;
    uint32_t sb = smem_u32(sm);
    int nT = nx * ny * nz;

    for (int t = blockIdx.x; t < nT; t += gridDim.x) {
        int gz = t / (nx * ny);
        int rem = t - gz * nx * ny;
        int gy = rem / nx;
        int gx = rem - gy * nx;
        if (mode == 2) gy = ny - 1 - gy;   // long-K tiles first
        int m0 = gy * BM, n0 = gx * BN;
        int Kend = (mode == 2) ? min(K, m0 + BM) : K;
        int NIT = Kend / BK;

        int zb = gz / zdiv, zh = gz - zb * zdiv;
        const hf* Ah = A0 + zb * sAb + zh * sAh;
        const hf* Bh = B0 + zb * sBb + zh * sBh;

        auto load_stage = [&](int it, int s) {
            int k0 = it * BK;
            uint32_t st = sb + s * STAGE_B;
#pragma unroll
            for (int q = 0; q < 6; q++) {
                int g = q * 256 + tid;
                const hf* gp; uint32_t sa;
                if (g < 1024) {
                    int row = g >> 3, kc = g & 7;
                    gp = Ah + (ll)(m0 + row) * lda + k0 + kc * 8;
                    sa = st + (row * SKP + kc * 8) * 2;
                } else {
                    int idx2 = g - 1024;
                    int row = idx2 >> 3, kc = idx2 & 7;
                    gp = Bh + (ll)(n0 + row) * ldb + k0 + kc * 8;
                    sa = st + OFF_B + (row * SKP + kc * 8) * 2;
                }
                CPA16(sa, gp);
            }
            CPCOMMIT();
        };

        float acc[2][4][4];
#pragma unroll
        for (int i = 0; i < 2; i++)
#pragma unroll
            for (int j = 0; j < 4; j++)
#pragma unroll
                for (int k = 0; k < 4; k++) acc[i][j][k] = 0.f;

        load_stage(0, 0);
        if (NIT > 1) load_stage(1, 1);
        for (int it = 0; it < NIT; it++) {
            if (it + 2 < NIT) {
                load_stage(it + 2, (it + 2) % 3);
                asm volatile("cp.async.wait_group 2;" ::: "memory");
            } else if (it + 1 < NIT) {
                asm volatile("cp.async.wait_group 1;" ::: "memory");
            } else {
                asm volatile("cp.async.wait_group 0;" ::: "memory");
            }
            __syncthreads();

            uint32_t st = sb + (it % 3) * STAGE_B;
#pragma unroll
            for (int ks = 0; ks < 4; ks++) {
                uint32_t Af[2][4];
#pragma unroll
                for (int mt = 0; mt < 2; mt++) {
                    int row = wm * 32 + mt * 16 + (lane & 15);
                    uint32_t col = ks * 16 + (lane >> 4) * 8;
                    LDMX4(Af[mt], st + (row * SKP + col) * 2);
                }
                uint32_t Bf[4][2];
#pragma unroll
                for (int g2 = 0; g2 < 2; g2++) {
                    int grp = lane >> 3;
                    int nrow = wn * 32 + g2 * 16 + (grp >> 1) * 8 + (lane & 7);
                    uint32_t col = ks * 16 + (grp & 1) * 8;
                    LDMX4(&Bf[g2 * 2][0], st + OFF_B + (nrow * SKP + col) * 2);
                }
#pragma unroll
                for (int mt = 0; mt < 2; mt++)
#pragma unroll
                    for (int nt = 0; nt < 4; nt++)
                        mma_f16(acc[mt][nt], Af[mt], Bf[nt]);
            }
            __syncthreads();
        }

        int rbase = m0 + wm * 32 + (lane >> 2);
        int cbase = n0 + wn * 32 + (lane & 3) * 2;
        if (outmode != 1) {
            float* Cz = C + zb * sCb + zh * sCh;
#pragma unroll
            for (int mt = 0; mt < 2; mt++)
#pragma unroll
                for (int nt = 0; nt < 4; nt++) {
                    int r = rbase + mt * 16, c = cbase + nt * 8;
#pragma unroll
                    for (int h2 = 0; h2 < 2; h2++) {
                        int rr = r + h2 * 8;
                        float v0 = acc[mt][nt][h2*2+0] * alpha;
                        float v1 = acc[mt][nt][h2*2+1] * alpha;
                        *reinterpret_cast<float2*>(&Cz[(ll)rr * ldc + c]) = make_float2(v0, v1);
                    }
                }
        }
        if (outmode != 0) {
            hf* Chz = Ch + zb * sCb + zh * sCh;
#pragma unroll
            for (int mt = 0; mt < 2; mt++)
#pragma unroll
                for (int nt = 0; nt < 4; nt++) {
                    int r = rbase + mt * 16, c = cbase + nt * 8;
#pragma unroll
                    for (int h2 = 0; h2 < 2; h2++) {
                        int rr = r + h2 * 8;
                        float v0 = acc[mt][nt][h2*2+0] * alpha;
                        float v1 = acc[mt][nt][h2*2+1] * alpha;
                        uint32_t pk = (uint32_t)__half_as_ushort(__float2half_rn(v0))
                                    | ((uint32_t)__half_as_ushort(__float2half_rn(v1)) << 16);
                        *reinterpret_cast<uint32_t*>(&Chz[(ll)rr * ldc + c]) = pk;
                    }
                }
        }
    }
}

// ---- fused flash attention: scores + online softmax + P@V ----
// One CTA per (bh, 128-query tile). 8 warps x 16 q-rows.
// q: [tok][KD2] per-head 192 slice (roped). k: same layout. vT: [bh][dv][s].
#define KPAD 200
#define VPAD 72
#define SQM  0
#define QBYTES 51200            // 128*KPAD*2
#define KBYTES 25600            // 64*KPAD*2
#define VBYTES 18432            // 128*VPAD*2
#define KVSTG (KBYTES+VBYTES)   // 44032
#define FA_SMEM (QBYTES + 2*KVSTG)

__global__ __launch_bounds__(256, 1) void fattn(
    const hf* __restrict__ qg, const hf* __restrict__ kg,
    const hf* __restrict__ vg, hf* __restrict__ og, float scale)
{
    extern __shared__ char sm[];
    int tid = threadIdx.x, lane = tid & 31, wid = tid >> 5;
    int job = blockIdx.x;
    int qi = 7 - (job >> 5);          // longest jobs first
    int gz = job & 31;
    int zb = gz >> 4, zh = gz & 15;
    int m0 = qi * 128;
    const hf* qp = qg + (ll)(zb * SQ) * KD2 + zh * QKD;
    const hf* kp = kg + (ll)(zb * SQ) * KD2 + zh * QKD;
    const hf* vp = vg + (ll)gz * VD * SQ;
    hf* op = og + (ll)(zb * SQ) * HID + zh * VD;
    uint32_t sb = smem_u32(sm);

    // group 0: q tile 128x192
#pragma unroll
    for (int g = tid; g < 3072; g += 256) {
        int row = g / 24, kc = g % 24;
        CPA16(sb + SQM + (row * KPAD + kc * 8) * 2,
              qp + (ll)(m0 + row) * KD2 + kc * 8);
    }
    CPCOMMIT();

    int nkv = 2 * qi + 2;
    auto loadkv = [&](int j, int s) {
        uint32_t base = sb + QBYTES + s * KVSTG;
#pragma unroll
        for (int g = tid; g < 1536; g += 256) {            // k 64x192
            int row = g / 24, kc = g % 24;
            CPA16(base + (row * KPAD + kc * 8) * 2,
                  kp + (ll)(j * 64 + row) * KD2 + kc * 8);
        }
#pragma unroll
        for (int g = tid; g < 1024; g += 256) {            // vT 128x64
            int row = g >> 3, kc = g & 7;
            CPA16(base + KBYTES + (row * VPAD + kc * 8) * 2,
                  vp + (ll)row * SQ + j * 64 + kc * 8);
        }
        CPCOMMIT();
    };
    loadkv(0, 0);
    loadkv(1, 1);
    asm volatile("cp.async.wait_group 1;" ::: "memory");   // q + kv0 ready
    __syncthreads();

    // resident q A-fragments (16 rows x 192)
    uint32_t Aq[12][4];
    {
        int row = wid * 16 + (lane & 15);
#pragma unroll
        for (int ks = 0; ks < 12; ks++) {
            uint32_t col = ks * 16 + (lane >> 4) * 8;
            LDMX4(Aq[ks], sb + SQM + (row * KPAD + col) * 2);
        }
    }

    float O[16][4];
#pragma unroll
    for (int n = 0; n < 16; n++)
#pragma unroll
        for (int e = 0; e < 4; e++) O[n][e] = 0.f;
    float mrow[2] = {-1e30f, -1e30f};
    float lrow[2] = {0.f, 0.f};
    int r0 = m0 + wid * 16 + (lane >> 2);

    for (int j = 0; j < nkv; j++) {
        if (j > 0) {
            if (j + 1 < nkv) asm volatile("cp.async.wait_group 1;" ::: "memory");
            else             asm volatile("cp.async.wait_group 0;" ::: "memory");
            __syncthreads();
        }
        uint32_t kb = sb + QBYTES + (j & 1) * KVSTG;
        uint32_t vb = kb + KBYTES;

        // S = q @ k^T
        float Sa[8][4];
#pragma unroll
        for (int f = 0; f < 8; f++)
#pragma unroll
            for (int e = 0; e < 4; e++) Sa[f][e] = 0.f;
#pragma unroll
        for (int ks = 0; ks < 12; ks++) {
            int grp = lane >> 3;
#pragma unroll
            for (int g2 = 0; g2 < 4; g2++) {
                int nrow = g2 * 16 + (grp >> 1) * 8 + (lane & 7);
                uint32_t col = ks * 16 + (grp & 1) * 8;
                uint32_t Bf[4];
                LDMX4(Bf, kb + (nrow * KPAD + col) * 2);
                mma_f16(Sa[g2 * 2],     Aq[ks], Bf);
                mma_f16(Sa[g2 * 2 + 1], Aq[ks], Bf + 2);
            }
        }

        // scale + causal mask
        int n0g = j * 64;
        bool domask = (n0g + 63) > m0;
#pragma unroll
        for (int f = 0; f < 8; f++)
#pragma unroll
            for (int e = 0; e < 4; e++) {
                float v = Sa[f][e] * scale;
                if (domask) {
                    int colg = n0g + f * 8 + 2 * (lane & 3) + (e & 1);
                    int rr = r0 + ((e >= 2) ? 8 : 0);
                    if (colg > rr) v = -1e30f;
                }
                Sa[f][e] = v;
            }

        // row max (4 lanes share a row)
        float mt0 = -1e30f, mt1 = -1e30f;
#pragma unroll
        for (int f = 0; f < 8; f++) {
            mt0 = fmaxf(mt0, fmaxf(Sa[f][0], Sa[f][1]));
            mt1 = fmaxf(mt1, fmaxf(Sa[f][2], Sa[f][3]));
        }
        mt0 = fmaxf(mt0, __shfl_xor_sync(0xFFFFFFFF, mt0, 1));
        mt0 = fmaxf(mt0, __shfl_xor_sync(0xFFFFFFFF, mt0, 2));
        mt1 = fmaxf(mt1, __shfl_xor_sync(0xFFFFFFFF, mt1, 1));
        mt1 = fmaxf(mt1, __shfl_xor_sync(0xFFFFFFFF, mt1, 2));
        float mn0 = fmaxf(mrow[0], mt0), mn1 = fmaxf(mrow[1], mt1);
        float sc0 = __expf(mrow[0] - mn0), sc1 = __expf(mrow[1] - mn1);
        mrow[0] = mn0; mrow[1] = mn1;
#pragma unroll
        for (int n = 0; n < 16; n++) {
            O[n][0] *= sc0; O[n][1] *= sc0;
            O[n][2] *= sc1; O[n][3] *= sc1;
        }

        // P = exp(S - m), pack into A-frags; row sums
        uint32_t Pf[4][4];
        float s0 = 0.f, s1 = 0.f;
#pragma unroll
        for (int f = 0; f < 8; f++) {
            float p0 = __expf(Sa[f][0] - mn0);
            float p1 = __expf(Sa[f][1] - mn0);
            float p2 = __expf(Sa[f][2] - mn1);
            float p3 = __expf(Sa[f][3] - mn1);
            s0 += p0 + p1; s1 += p2 + p3;
            __half2 h01 = __floats2half2_rn(p0, p1);
            __half2 h23 = __floats2half2_rn(p2, p3);
            int ks2 = f >> 1, hi = (f & 1) * 2;
            Pf[ks2][hi]     = *reinterpret_cast<uint32_t*>(&h01);
            Pf[ks2][hi + 1] = *reinterpret_cast<uint32_t*>(&h23);
        }
        s0 += __shfl_xor_sync(0xFFFFFFFF, s0, 1);
        s0 += __shfl_xor_sync(0xFFFFFFFF, s0, 2);
        s1 += __shfl_xor_sync(0xFFFFFFFF, s1, 1);
        s1 += __shfl_xor_sync(0xFFFFFFFF, s1, 2);
        lrow[0] = lrow[0] * sc0 + s0;
        lrow[1] = lrow[1] * sc1 + s1;

        // O += P @ V
#pragma unroll
        for (int ks = 0; ks < 4; ks++) {
            int grp = lane >> 3;
#pragma unroll
            for (int g2 = 0; g2 < 8; g2++) {
                int nrow = g2 * 16 + (grp >> 1) * 8 + (lane & 7);
                uint32_t col = ks * 16 + (grp & 1) * 8;
                uint32_t Bf[4];
                LDMX4(Bf, vb + (nrow * VPAD + col) * 2);
                mma_f16(O[g2 * 2],     Pf[ks], Bf);
                mma_f16(O[g2 * 2 + 1], Pf[ks], Bf + 2);
            }
        }
        __syncthreads();
        if (j + 2 < nkv) loadkv(j + 2, j & 1);
    }

    // normalize + store fp16
    float inv0 = 1.f / lrow[0], inv1 = 1.f / lrow[1];
    int rt = m0 + wid * 16 + (lane >> 2);
#pragma unroll
    for (int n = 0; n < 16; n++) {
        int c = n * 8 + 2 * (lane & 3);
        __half2 a = __floats2half2_rn(O[n][0] * inv0, O[n][1] * inv0);
        __half2 b = __floats2half2_rn(O[n][2] * inv1, O[n][3] * inv1);
        *reinterpret_cast<uint32_t*>(&op[(ll)rt * HID + c]) = *reinterpret_cast<uint32_t*>(&a);
        *reinterpret_cast<uint32_t*>(&op[(ll)(rt + 8) * HID + c]) = *reinterpret_cast<uint32_t*>(&b);
    }
}

// ---- f32 -> fp16 ----
__global__ __launch_bounds__(256) void cvt_h(const float* __restrict__ s, hf* __restrict__ h) {
    ll i = ((ll)blockIdx.x * 256 + threadIdx.x) * 8;
    float4 a = *reinterpret_cast<const float4*>(s + i);
    float4 b = *reinterpret_cast<const float4*>(s + i + 4);
    float v[8] = {a.x, a.y, a.z, a.w, b.x, b.y, b.z, b.w};
    unsigned short hs[8];
#pragma unroll
    for (int j = 0; j < 8; j++) hs[j] = __half_as_ushort(__float2half_rn(v[j]));
    uint4 hv;
    hv.x = hs[0] | ((uint32_t)hs[1] << 16); hv.y = hs[2] | ((uint32_t)hs[3] << 16);
    hv.z = hs[4] | ((uint32_t)hs[5] << 16); hv.w = hs[6] | ((uint32_t)hs[7] << 16);
    *reinterpret_cast<uint4*>(h + i) = hv;
}

// ---- transpose + convert: src (RxC) -> dst (CxR) fp16 ----
__global__ __launch_bounds__(256) void tcvt(const float* __restrict__ s, int lds, ll sz,
                                            hf* __restrict__ dh, int ldd, ll dz) {
    __shared__ float t[32][33];
    s += (ll)blockIdx.z * sz;  dh += (ll)blockIdx.z * dz;
    int r0 = blockIdx.y * 32, c0 = blockIdx.x * 32;
    int tx = threadIdx.x & 31, ty = threadIdx.x >> 5;
#pragma unroll
    for (int i = 0; i < 32; i += 8)
        t[ty + i][tx] = s[(ll)(r0 + ty + i) * lds + c0 + tx];
    __syncthreads();
#pragma unroll
    for (int i = 0; i < 32; i += 8)
        dh[(ll)(c0 + ty + i) * ldd + r0 + tx] = __float2half_rn(t[tx][ty + i]);
}

// ---- dual LN + k_pe rope ----
__global__ __launch_bounds__(256) void ln_rope_k(
    const float* __restrict__ qakva,
    const float* __restrict__ qw, const float* __restrict__ kw,
    const float* __restrict__ cosb, const float* __restrict__ sinb,
    hf* __restrict__ qh, hf* __restrict__ kh)
{
    int t = blockIdx.x, tid = threadIdx.x;
    __shared__ float r1[256], r2[256];
    const float* row = qakva + (ll)t * QKVN;
    float s = 0.f, s2 = 0.f;
    for (int i = tid; i < QLR; i += 256) { float v = row[i]; s += v; s2 += v * v; }
    r1[tid] = s; r2[tid] = s2; __syncthreads();
    for (int o = 128; o > 0; o >>= 1) { if (tid < o) { r1[tid] += r1[tid+o]; r2[tid] += r2[tid+o]; } __syncthreads(); }
    float mean = r1[0] * (1.f / QLR);
    float rs = rsqrtf(r2[0] * (1.f / QLR) - mean * mean + 1e-5f);
    for (int i = tid; i < QLR; i += 256)
        qh[(ll)t * QLR + i] = __float2half_rn((row[i] - mean) * rs * qw[i]);
    __syncthreads();
    const float* krow = row + QLR;
    s = 0.f; s2 = 0.f;
    for (int i = tid; i < KVLR; i += 256) { float v = krow[i]; s += v; s2 += v * v; }
    r1[tid] = s; r2[tid] = s2; __syncthreads();
    for (int o = 128; o > 0; o >>= 1) { if (tid < o) { r1[tid] += r1[tid+o]; r2[tid] += r2[tid+o]; } __syncthreads(); }
    mean = r1[0] * (1.f / KVLR);
    rs = rsqrtf(r2[0] * (1.f / KVLR) - mean * mean + 1e-5f);
    for (int i = tid; i < KVLR; i += 256)
        kh[(ll)t * EFFD + i] = __float2half_rn((krow[i] - mean) * rs * kw[i]);
    if (tid < ROPE) {
        int i = tid;
        float x = krow[KVLR + i];
        float rot = (i < 32) ? -krow[KVLR + i + 32] : krow[KVLR + i - 32];
        float v = x * cosb[(ll)t * ROPE + i] + rot * sinb[(ll)t * ROPE + i];
        kh[(ll)t * EFFD + KVLR + i] = __float2half_rn(v);
    }
}

// ---- q_pe rope ----
__global__ __launch_bounds__(256) void qrope_k(
    const float* __restrict__ q, const float* __restrict__ cosb,
    const float* __restrict__ sinb, hf* __restrict__ qh)
{
    int t = blockIdx.x, tid = threadIdx.x;
    for (int idx = tid; idx < NH * ROPE; idx += 256) {
        int h = idx >> 6, i = idx & 63;
        const float* qp = q + (ll)t * KD2 + h * QKD + NOPE;
        float x = qp[i];
        float rot = (i < 32) ? -qp[i + 32] : qp[i - 32];
        float v = x * cosb[(ll)t * ROPE + i] + rot * sinb[(ll)t * ROPE + i];
        qh[(ll)t * KD2 + h * QKD + NOPE + i] = __float2half_rn(v);
    }
}

// ---- replicate roped k_pe into kk2 ----
__global__ __launch_bounds__(256) void kpe_rep(
    const hf* __restrict__ kh, hf* __restrict__ k2h)
{
    int t = blockIdx.x, tid = threadIdx.x;
    for (int idx = tid; idx < NH * ROPE; idx += 256) {
        int h = idx >> 6, i = idx & 63;
        k2h[(ll)t * KD2 + h * QKD + NOPE + i] = kh[(ll)t * EFFD + KVLR + i];
    }
}

static inline int pgrid_n(int t) { return t < NPERS ? t : NPERS; }

extern "C" void kernel_launch(void* const* d_in, const int* in_sizes, int n_in,
                              void* d_out, int out_size)
{
    const float* hidden = (const float*)d_in[0];
    const float* cosb   = (const float*)d_in[1];
    const float* sinb   = (const float*)d_in[2];
    const float* w_qa   = (const float*)d_in[3];
    const float* qln    = (const float*)d_in[4];
    const float* w_qb   = (const float*)d_in[5];
    const float* w_kva  = (const float*)d_in[6];
    const float* kln    = (const float*)d_in[7];
    const float* w_uk   = (const float*)d_in[8];
    const float* w_uv   = (const float*)d_in[9];
    const float* w_o    = (const float*)d_in[10];
    float* out = (float*)d_out;

    hf *hid_h,*wqakva_h,*wqb_h,*wo_h,*wuk_h,*wuvT_h,*qaln_h,*kk_h;
    hf *q_h,*kk2_h,*vT_h,*attn_h;
    float *qakva_raw,*qf;
    cudaGetSymbolAddress((void**)&hid_h,g_hid_h);
    cudaGetSymbolAddress((void**)&wqakva_h,g_wqakva_h);
    cudaGetSymbolAddress((void**)&wqb_h,g_wqb_h);
    cudaGetSymbolAddress((void**)&wo_h,g_wo_h);
    cudaGetSymbolAddress((void**)&wuk_h,g_wuk_h);
    cudaGetSymbolAddress((void**)&wuvT_h,g_wuvT_h);
    cudaGetSymbolAddress((void**)&qakva_raw,g_qakva_raw);
    cudaGetSymbolAddress((void**)&qaln_h,g_qaln_h);
    cudaGetSymbolAddress((void**)&kk_h,g_kk_h);
    cudaGetSymbolAddress((void**)&qf,g_q);
    cudaGetSymbolAddress((void**)&q_h,g_q_h);
    cudaGetSymbolAddress((void**)&kk2_h,g_kk2_h);
    cudaGetSymbolAddress((void**)&vT_h,g_vT_h);
    cudaGetSymbolAddress((void**)&attn_h,g_attn_h);

    cudaFuncSetAttribute(gemm_tc, cudaFuncAttributeMaxDynamicSharedMemorySize, SMEM_T);
    cudaFuncSetAttribute(fattn,  cudaFuncAttributeMaxDynamicSharedMemorySize, FA_SMEM);
    const float scale = 1.0f / sqrtf((float)QKD);

    // conversions
    cvt_h<<<TOK*HID/2048, 256>>>(hidden, hid_h);
    cvt_h<<<QLR*HID/2048, 256>>>(w_qa, wqakva_h);
    cvt_h<<<EFFD*HID/2048, 256>>>(w_kva, wqakva_h + (ll)QLR*HID);
    cvt_h<<<NH*QKD*QLR/2048, 256>>>(w_qb, wqb_h);
    cvt_h<<<HID*HID/2048, 256>>>(w_o, wo_h);
    cvt_h<<<NH*NOPE*KVLR/2048, 256>>>(w_uk, wuk_h);
    tcvt<<<dim3(VD/32, KVLR/32, NH), 256>>>(w_uv, VD, (ll)KVLR*VD, wuvT_h, KVLR, (ll)VD*KVLR);

    // 1) qakva_raw = hidden @ [w_qa; w_kva]^T
    gemm_tc<<<pgrid_n(QKVN/BN * TOK/BM), 256, SMEM_T>>>(
        hid_h, HID, 0, 0,  wqakva_h, HID, 0, 0,
        qakva_raw, 0, QKVN, 0, 0,  HID, 1.f, 0, 1, 0,
        QKVN/BN, TOK/BM, 1);
    // 2) LN + k_pe rope
    ln_rope_k<<<TOK, 256>>>(qakva_raw, qln, kln, cosb, sinb, qaln_h, kk_h);
    // 3) q = qa_ln @ w_qb^T (dual out) + rope
    gemm_tc<<<pgrid_n(KD2/BN * TOK/BM), 256, SMEM_T>>>(
        qaln_h, QLR, 0, 0,  wqb_h, QLR, 0, 0,
        qf, q_h, KD2, 0, 0,  QLR, 1.f, 0, 1, 3,
        KD2/BN, TOK/BM, 1);
    qrope_k<<<TOK, 256>>>(qf, cosb, sinb, q_h);
    // 4) k decompress
    gemm_tc<<<pgrid_n(NOPE/BN * TOK/BM * NH), 256, SMEM_T>>>(
        kk_h, EFFD, 0, 0,  wuk_h, KVLR, 0, (ll)NOPE*KVLR,
        0, kk2_h, KD2, 0, QKD,  KVLR, 1.f, 0, NH, 1,
        NOPE/BN, TOK/BM, NH);
    // 5) k_pe replicate
    kpe_rep<<<TOK, 256>>>(kk_h, kk2_h);
    // 6) v decompress (transposed)
    gemm_tc<<<pgrid_n(SQ/BN * VD/BM * 2*NH), 256, SMEM_T>>>(
        wuvT_h, KVLR, 0, (ll)VD*KVLR,
        kk_h, EFFD, (ll)SQ*EFFD, 0,
        0, vT_h, SQ, (ll)NH*VD*SQ, (ll)VD*SQ,  KVLR, 1.f, 0, NH, 1,
        SQ/BN, VD/BM, 2*NH);
    // 7) fused attention (scores + softmax + P@V)
    fattn<<<256, 256, FA_SMEM>>>(q_h, kk2_h, vT_h, attn_h, scale);
    // 8) out = attn @ w_o^T
    gemm_tc<<<pgrid_n(HID/BN * TOK/BM), 256, SMEM_T>>>(
        attn_h, HID, 0, 0,  wo_h, HID, 0, 0,
        out, 0, HID, 0, 0,  HID, 1.f, 0, 1, 0,
        HID/BN, TOK/BM, 1);
}